// round 1
// baseline (speedup 1.0000x reference)
#include <cuda_runtime.h>
#include <cuda_bf16.h>
#include <math.h>

// ---------------- problem constants ----------------
#define BS   4
#define NQ   300
#define D    256
#define NH   8
#define DH   32
#define NL   4
#define NP   4
#define DFF  1024
#define LTOT 17821
#define BNQ  (BS*NQ)          // 1200
#define MVAL (BS*LTOT)        // 71284

// ---------------- scratch (device globals; no allocation allowed) ----------------
__device__ float g_q   [BNQ*D];
__device__ float g_qh  [BNQ*D];
__device__ float g_kh  [BNQ*D];
__device__ float g_vh  [BNQ*D];
__device__ float g_attn[BNQ*D];
__device__ float g_sa  [BNQ*D];
__device__ float g_tgt2[2][BNQ*D];
__device__ float g_off [BNQ*D];
__device__ float g_aw  [BNQ*(NH*NL*NP)];
__device__ float g_samp[BNQ*D];
__device__ float g_ffn [BNQ*DFF];
__device__ float g_y   [BNQ*D];
__device__ float g_x   [2][BNQ*D];
__device__ float g_value[MVAL*D];

// ---------------- elementwise add ----------------
__global__ void add2_kernel(const float* __restrict__ a, const float* __restrict__ b,
                            float* __restrict__ c, int n) {
    int i = blockIdx.x * blockDim.x + threadIdx.x;
    if (i < n) c[i] = a[i] + b[i];
}

// ---------------- generic SGEMM: C[M,N] = A[M,K] @ W[N,K]^T + bias (+relu) ----------------
#define BM 64
#define BN 64
#define BK 16
__global__ void sgemm_kernel(const float* __restrict__ A, const float* __restrict__ W,
                             const float* __restrict__ bias, float* __restrict__ C,
                             int M, int N, int K, int relu) {
    __shared__ float As[BK][BM + 4];
    __shared__ float Ws[BK][BN + 4];
    int tid = threadIdx.x;
    int bm = blockIdx.y * BM;
    int bn = blockIdx.x * BN;

    int lrow = tid >> 2;             // 0..63
    int lcol = (tid & 3) << 2;       // 0,4,8,12

    int tm = (tid >> 4) << 2;        // 0..60 step 4
    int tn = (tid & 15) << 2;        // 0..60 step 4

    float acc[4][4] = {};

    for (int k0 = 0; k0 < K; k0 += BK) {
        int gm = bm + lrow;
        float4 av = (gm < M) ? *(const float4*)(A + (size_t)gm * K + k0 + lcol)
                             : make_float4(0.f, 0.f, 0.f, 0.f);
        As[lcol + 0][lrow] = av.x;
        As[lcol + 1][lrow] = av.y;
        As[lcol + 2][lrow] = av.z;
        As[lcol + 3][lrow] = av.w;

        int gn = bn + lrow;          // N tiles always full (N % 64 == 0)
        float4 wv = *(const float4*)(W + (size_t)gn * K + k0 + lcol);
        Ws[lcol + 0][lrow] = wv.x;
        Ws[lcol + 1][lrow] = wv.y;
        Ws[lcol + 2][lrow] = wv.z;
        Ws[lcol + 3][lrow] = wv.w;
        __syncthreads();

        #pragma unroll
        for (int k = 0; k < BK; k++) {
            float a0 = As[k][tm + 0], a1 = As[k][tm + 1], a2 = As[k][tm + 2], a3 = As[k][tm + 3];
            float b0 = Ws[k][tn + 0], b1 = Ws[k][tn + 1], b2 = Ws[k][tn + 2], b3 = Ws[k][tn + 3];
            acc[0][0] += a0*b0; acc[0][1] += a0*b1; acc[0][2] += a0*b2; acc[0][3] += a0*b3;
            acc[1][0] += a1*b0; acc[1][1] += a1*b1; acc[1][2] += a1*b2; acc[1][3] += a1*b3;
            acc[2][0] += a2*b0; acc[2][1] += a2*b1; acc[2][2] += a2*b2; acc[2][3] += a2*b3;
            acc[3][0] += a3*b0; acc[3][1] += a3*b1; acc[3][2] += a3*b2; acc[3][3] += a3*b3;
        }
        __syncthreads();
    }

    #pragma unroll
    for (int i = 0; i < 4; i++) {
        int gm = bm + tm + i;
        if (gm >= M) continue;
        #pragma unroll
        for (int j = 0; j < 4; j++) {
            int gn = bn + tn + j;
            float v = acc[i][j] + bias[gn];
            if (relu) v = fmaxf(v, 0.f);
            C[(size_t)gm * N + gn] = v;
        }
    }
}

// ---------------- self-attention: per (b,h), N=300, DH=32 ----------------
__global__ void attn_kernel(const float* __restrict__ qh, const float* __restrict__ kh,
                            const float* __restrict__ vh, float* __restrict__ out) {
    const float scale = 0.17677669529663687f; // 1/sqrt(32)
    int bh = blockIdx.x;
    int b = bh >> 3, h = bh & 7;
    __shared__ float Ks[NQ * 33];       // 39600 B, padded rows (conflict-free)
    __shared__ float Ps[6][304];        // per-warp probability row

    int tid = threadIdx.x;
    int w = tid >> 5, lane = tid & 31;

    // load K tile
    for (int i = tid; i < NQ * 32; i += 192) {
        int k = i >> 5, c = i & 31;
        Ks[k * 33 + c] = kh[(((size_t)(b * NQ + k) * NH + h) << 5) + c];
    }
    __syncthreads();

    for (int q = w; q < NQ; q += 6) {
        float qreg = qh[(((size_t)(b * NQ + q) * NH + h) << 5) + lane];
        float sj[10];
        float mx = -3.0e38f;
        #pragma unroll
        for (int j = 0; j < 10; j++) {
            int k = lane + 32 * j;
            int kk = (k < NQ) ? k : (NQ - 1);
            float acc = 0.f;
            #pragma unroll
            for (int c = 0; c < 32; c++)
                acc = fmaf(__shfl_sync(0xffffffffu, qreg, c), Ks[kk * 33 + c], acc);
            acc *= scale;
            sj[j] = (k < NQ) ? acc : -3.0e38f;
            mx = fmaxf(mx, sj[j]);
        }
        #pragma unroll
        for (int o = 16; o > 0; o >>= 1)
            mx = fmaxf(mx, __shfl_xor_sync(0xffffffffu, mx, o));
        float lsum = 0.f;
        float pj[10];
        #pragma unroll
        for (int j = 0; j < 10; j++) {
            int k = lane + 32 * j;
            pj[j] = (k < NQ) ? expf(sj[j] - mx) : 0.f;
            lsum += pj[j];
        }
        #pragma unroll
        for (int o = 16; o > 0; o >>= 1)
            lsum += __shfl_xor_sync(0xffffffffu, lsum, o);
        float inv = 1.f / lsum;
        #pragma unroll
        for (int j = 0; j < 10; j++) {
            int k = lane + 32 * j;
            if (k < NQ) Ps[w][k] = pj[j] * inv;
        }
        __syncwarp();
        float acc = 0.f;
        for (int k = 0; k < NQ; k++)
            acc = fmaf(Ps[w][k], vh[(((size_t)(b * NQ + k) * NH + h) << 5) + lane], acc);
        out[(((size_t)(b * NQ + q) * NH + h) << 5) + lane] = acc;
        __syncwarp();
    }
}

// ---------------- layernorm (optional residual): y = LN(x (+ r)) * g + b ----------------
__global__ void ln_kernel(const float* __restrict__ x, const float* __restrict__ r,
                          const float* __restrict__ g, const float* __restrict__ be,
                          float* __restrict__ y) {
    int row = blockIdx.x;
    int d = threadIdx.x;
    size_t base = (size_t)row * D;
    float v = x[base + d];
    if (r) v += r[base + d];
    __shared__ float sh[D];
    sh[d] = v; __syncthreads();
    for (int o = 128; o > 0; o >>= 1) { if (d < o) sh[d] += sh[d + o]; __syncthreads(); }
    float mean = sh[0] * (1.f / D);
    __syncthreads();
    float dv = v - mean;
    sh[d] = dv * dv; __syncthreads();
    for (int o = 128; o > 0; o >>= 1) { if (d < o) sh[d] += sh[d + o]; __syncthreads(); }
    float var = sh[0] * (1.f / D);
    float rstd = rsqrtf(var + 1e-5f);
    y[base + d] = dv * rstd * g[d] + be[d];
}

// ---------------- softmax over last 16 (attention weights) ----------------
__global__ void softmax16_kernel(float* __restrict__ aw, int rows) {
    int rIdx = blockIdx.x * blockDim.x + threadIdx.x;
    if (rIdx >= rows) return;
    float* p = aw + (size_t)rIdx * 16;
    float m = -3.0e38f;
    float e[16];
    #pragma unroll
    for (int i = 0; i < 16; i++) m = fmaxf(m, p[i]);
    float s = 0.f;
    #pragma unroll
    for (int i = 0; i < 16; i++) { e[i] = expf(p[i] - m); s += e[i]; }
    float inv = 1.f / s;
    #pragma unroll
    for (int i = 0; i < 16; i++) p[i] = e[i] * inv;
}

// ---------------- multi-scale deformable sampling ----------------
__device__ __forceinline__ float ms_tap(const float* __restrict__ value,
                                        int b, int h, int lane, int s0, int W, int H,
                                        int xi, int yi, float w) {
    if (xi < 0 || xi >= W || yi < 0 || yi >= H) return 0.f;
    size_t idx = ((((size_t)b * LTOT + s0 + (size_t)yi * W + xi) * NH + h) << 5) + lane;
    return w * value[idx];
}

__global__ void msdeform_kernel(const float* __restrict__ value, const float* __restrict__ off,
                                const float* __restrict__ aw, const float* __restrict__ ref,
                                float* __restrict__ out) {
    const int Hs[4] = {100, 50, 25, 13};
    const int Wls[4] = {134, 67, 34, 17};
    const int S0[4] = {0, 13400, 16750, 17600};

    int bq = blockIdx.x;                 // b*NQ + q
    int h = threadIdx.x >> 5, lane = threadIdx.x & 31;
    int b = bq / NQ;

    const float* offp = off + (size_t)bq * 256 + h * 32;  // (l*4+p)*2 + xy
    const float* awp  = aw  + (size_t)bq * 128 + h * 16;

    float acc = 0.f;
    #pragma unroll
    for (int l = 0; l < 4; l++) {
        float rx = ref[((size_t)bq * NL + l) * 2 + 0];
        float ry = ref[((size_t)bq * NL + l) * 2 + 1];
        float Wf = (float)Wls[l], Hf = (float)Hs[l];
        #pragma unroll
        for (int p = 0; p < 4; p++) {
            float ox = offp[(l * 4 + p) * 2 + 0];
            float oy = offp[(l * 4 + p) * 2 + 1];
            float a = awp[l * 4 + p];
            float locx = rx + ox / Wf;
            float locy = ry + oy / Hf;
            float x = locx * Wf - 0.5f;
            float y = locy * Hf - 0.5f;
            float x0f = floorf(x), y0f = floorf(y);
            int x0 = (int)x0f, y0 = (int)y0f;
            float wx = x - x0f, wy = y - y0f;
            float w00 = (1.f - wx) * (1.f - wy) * a;
            float w10 = wx * (1.f - wy) * a;
            float w01 = (1.f - wx) * wy * a;
            float w11 = wx * wy * a;
            acc += ms_tap(value, b, h, lane, S0[l], Wls[l], Hs[l], x0,     y0,     w00);
            acc += ms_tap(value, b, h, lane, S0[l], Wls[l], Hs[l], x0 + 1, y0,     w10);
            acc += ms_tap(value, b, h, lane, S0[l], Wls[l], Hs[l], x0,     y0 + 1, w01);
            acc += ms_tap(value, b, h, lane, S0[l], Wls[l], Hs[l], x0 + 1, y0 + 1, w11);
        }
    }
    out[(size_t)bq * D + h * 32 + lane] = acc;
}

// ---------------- host side ----------------
static void gemm(const float* A, const float* W, const float* bias, float* C,
                 int M, int N, int K, int relu) {
    dim3 grid(N / BN, (M + BM - 1) / BM);
    sgemm_kernel<<<grid, 256>>>(A, W, bias, C, M, N, K, relu);
}

extern "C" void kernel_launch(void* const* d_in, const int* in_sizes, int n_in,
                              void* d_out_v, int out_size) {
    const float* tgt[2] = {(const float*)d_in[0], (const float*)d_in[1]};
    const float* pos[2] = {(const float*)d_in[2], (const float*)d_in[3]};
    const float* ref[2] = {(const float*)d_in[4], (const float*)d_in[5]};
    const float* src[2] = {(const float*)d_in[6], (const float*)d_in[7]};
    const float* sa_in_w  = (const float*)d_in[8];
    const float* sa_in_b  = (const float*)d_in[9];
    const float* sa_out_w = (const float*)d_in[10];
    const float* sa_out_b = (const float*)d_in[11];
    const float* ln_w     = (const float*)d_in[12];
    const float* ln_b     = (const float*)d_in[13];
    const float* ffn_w1   = (const float*)d_in[14];
    const float* ffn_b1   = (const float*)d_in[15];
    const float* ffn_w2   = (const float*)d_in[16];
    const float* ffn_b2   = (const float*)d_in[17];
    const float* val_w    = (const float*)d_in[18];
    const float* val_b    = (const float*)d_in[19];
    const float* off_w    = (const float*)d_in[20];
    const float* off_b    = (const float*)d_in[21];
    const float* aw_w     = (const float*)d_in[22];
    const float* aw_b     = (const float*)d_in[23];
    const float* cout_w   = (const float*)d_in[24];
    const float* cout_b   = (const float*)d_in[25];
    float* out = (float*)d_out_v;

    float *p_q, *p_qh, *p_kh, *p_vh, *p_attn, *p_sa, *p_tgt2, *p_off, *p_aw,
          *p_samp, *p_ffn, *p_y, *p_x, *p_value;
    cudaGetSymbolAddress((void**)&p_q,    g_q);
    cudaGetSymbolAddress((void**)&p_qh,   g_qh);
    cudaGetSymbolAddress((void**)&p_kh,   g_kh);
    cudaGetSymbolAddress((void**)&p_vh,   g_vh);
    cudaGetSymbolAddress((void**)&p_attn, g_attn);
    cudaGetSymbolAddress((void**)&p_sa,   g_sa);
    cudaGetSymbolAddress((void**)&p_tgt2, g_tgt2);
    cudaGetSymbolAddress((void**)&p_off,  g_off);
    cudaGetSymbolAddress((void**)&p_aw,   g_aw);
    cudaGetSymbolAddress((void**)&p_samp, g_samp);
    cudaGetSymbolAddress((void**)&p_ffn,  g_ffn);
    cudaGetSymbolAddress((void**)&p_y,    g_y);
    cudaGetSymbolAddress((void**)&p_x,    g_x);
    cudaGetSymbolAddress((void**)&p_value,g_value);

    const int NE = BNQ * D;                 // 307200
    const int GRID_E = (NE + 255) / 256;    // 1200

    for (int m = 0; m < 2; m++) {
        float* tgt2m = p_tgt2 + (size_t)m * NE;
        // q = tgt + pos
        add2_kernel<<<GRID_E, 256>>>(tgt[m], pos[m], p_q, NE);
        // qkv projections (q,k from q; v from tgt)
        const float* wbase = sa_in_w + (size_t)m * 3 * D * D;
        const float* bbase = sa_in_b + (size_t)m * 3 * D;
        gemm(p_q,    wbase,             bbase,           p_qh, BNQ, D, D, 0);
        gemm(p_q,    wbase + D * D,     bbase + D,       p_kh, BNQ, D, D, 0);
        gemm(tgt[m], wbase + 2 * D * D, bbase + 2 * D,   p_vh, BNQ, D, D, 0);
        // attention
        attn_kernel<<<BS * NH, 192>>>(p_qh, p_kh, p_vh, p_attn);
        // out proj
        gemm(p_attn, sa_out_w + (size_t)m * D * D, sa_out_b + m * D, p_sa, BNQ, D, D, 0);
        // tgt2 = LN(tgt + sa)  (norm2)
        ln_kernel<<<BNQ, 256>>>(tgt[m], p_sa, ln_w + (m * 3 + 1) * D, ln_b + (m * 3 + 1) * D, tgt2m);
        // qc = tgt2 + pos
        add2_kernel<<<GRID_E, 256>>>(tgt2m, pos[m], p_q, NE);
        // value = src_other @ val_w^T + val_b   (the big one)
        gemm(src[1 - m], val_w + (size_t)m * D * D, val_b + m * D, p_value, MVAL, D, D, 0);
        // offsets, attention weights
        gemm(p_q, off_w + (size_t)m * D * D,       off_b + m * 256, p_off, BNQ, 256, D, 0);
        gemm(p_q, aw_w  + (size_t)m * 128 * D,     aw_b  + m * 128, p_aw,  BNQ, 128, D, 0);
        softmax16_kernel<<<(BNQ * NH + 255) / 256, 256>>>(p_aw, BNQ * NH);
        // sampling
        msdeform_kernel<<<BNQ, 256>>>(p_value, p_off, p_aw, ref[m], p_samp);
        // cout projection -> write straight into output regions F_RGB / F_T
        gemm(p_samp, cout_w + (size_t)m * D * D, cout_b + m * D, out + (size_t)(2 + m) * NE,
             BNQ, D, D, 0);
    }

    // cross residuals: r = tgt2_T + t2_RGB ; t = r + t2_T
    float* p_r = p_qh;   // reuse
    float* p_t = p_kh;   // reuse
    add2_kernel<<<GRID_E, 256>>>(p_tgt2 + (size_t)NE, out + (size_t)2 * NE, p_r, NE);
    add2_kernel<<<GRID_E, 256>>>(p_r, out + (size_t)3 * NE, p_t, NE);
    ln_kernel<<<BNQ, 256>>>(p_r, nullptr, ln_w + 0 * D, ln_b + 0 * D, p_x);              // norm1_RGB
    ln_kernel<<<BNQ, 256>>>(p_t, nullptr, ln_w + 3 * D, ln_b + 3 * D, p_x + (size_t)NE); // norm1_T

    // FFNs
    for (int m = 0; m < 2; m++) {
        float* xm = p_x + (size_t)m * NE;
        gemm(xm,    ffn_w1 + (size_t)m * DFF * D, ffn_b1 + m * DFF, p_ffn, BNQ, DFF, D, 1);
        gemm(p_ffn, ffn_w2 + (size_t)m * D * DFF, ffn_b2 + m * D,   p_y,   BNQ, D, DFF, 0);
        ln_kernel<<<BNQ, 256>>>(xm, p_y, ln_w + (m * 3 + 2) * D, ln_b + (m * 3 + 2) * D,
                                out + (size_t)m * NE);
    }
}

// round 2
// speedup vs baseline: 1.4719x; 1.4719x over previous
#include <cuda_runtime.h>
#include <cuda_bf16.h>
#include <math.h>

// ---------------- problem constants ----------------
#define BS   4
#define NQ   300
#define D    256
#define NH   8
#define DH   32
#define NL   4
#define NP   4
#define DFF  1024
#define LTOT 17821
#define BNQ  (BS*NQ)          // 1200
#define QB   4                // queries per msdeform block

// ---------------- scratch (device globals; no allocation allowed) ----------------
__device__ float g_qk  [BNQ*512];       // fused q|k projections
__device__ float g_vh  [BNQ*D];
__device__ float g_attn[BNQ*D];
__device__ float g_sa  [BNQ*D];
__device__ float g_tgt2[2][BNQ*D];
__device__ float g_off [BNQ*D];
__device__ float g_aw  [BNQ*(NH*NL*NP)];
__device__ float g_samp[BNQ*D];
__device__ float g_ffn [BNQ*DFF];
__device__ float g_y   [BNQ*D];
__device__ float g_x   [2][BNQ*D];
__device__ float g_r   [BNQ*D];
__device__ float g_t   [BNQ*D];
__device__ float g_wT  [D*D];           // transposed val_w for current modality

// ---------------- elementwise add ----------------
__global__ void add2_kernel(const float* __restrict__ a, const float* __restrict__ b,
                            float* __restrict__ c, int n) {
    int i = blockIdx.x * blockDim.x + threadIdx.x;
    if (i < n) c[i] = a[i] + b[i];
}

// ---------------- weight transpose 256x256: wT[c][n] = w[n][c] ----------------
__global__ void transpose256_kernel(const float* __restrict__ w, float* __restrict__ wT) {
    __shared__ float tile[32][33];
    int bx = blockIdx.x * 32, by = blockIdx.y * 32;
    int tx = threadIdx.x, ty = threadIdx.y;
    // read w[by+ty..][bx+tx] coalesced
    #pragma unroll
    for (int i = 0; i < 32; i += 8)
        tile[ty + i][tx] = w[(size_t)(by + ty + i) * D + bx + tx];
    __syncthreads();
    #pragma unroll
    for (int i = 0; i < 32; i += 8)
        wT[(size_t)(bx + ty + i) * D + by + tx] = tile[tx][ty + i];
}

// ---------------- generic SGEMM: C[M,N] = (A1 (+A2))[M,K] @ W[N,K]^T + bias (+relu) ----------------
#define BM 64
#define BN 64
#define BK 16
__global__ __launch_bounds__(256)
void sgemm_kernel(const float* __restrict__ A, const float* __restrict__ A2,
                  const float* __restrict__ W,
                  const float* __restrict__ bias, float* __restrict__ C,
                  int M, int N, int K, int relu) {
    __shared__ float As[BK][BM + 4];
    __shared__ float Ws[BK][BN + 4];
    int tid = threadIdx.x;
    int bm = blockIdx.y * BM;
    int bn = blockIdx.x * BN;

    int lrow = tid >> 2;             // 0..63
    int lcol = (tid & 3) << 2;       // 0,4,8,12

    int tm = (tid >> 4) << 2;        // 0..60 step 4
    int tn = (tid & 15) << 2;        // 0..60 step 4

    float acc[4][4] = {};

    for (int k0 = 0; k0 < K; k0 += BK) {
        int gm = bm + lrow;
        float4 av = make_float4(0.f, 0.f, 0.f, 0.f);
        if (gm < M) {
            av = *(const float4*)(A + (size_t)gm * K + k0 + lcol);
            if (A2) {
                float4 av2 = *(const float4*)(A2 + (size_t)gm * K + k0 + lcol);
                av.x += av2.x; av.y += av2.y; av.z += av2.z; av.w += av2.w;
            }
        }
        As[lcol + 0][lrow] = av.x;
        As[lcol + 1][lrow] = av.y;
        As[lcol + 2][lrow] = av.z;
        As[lcol + 3][lrow] = av.w;

        int gn = bn + lrow;          // N tiles always full (N % 64 == 0)
        float4 wv = *(const float4*)(W + (size_t)gn * K + k0 + lcol);
        Ws[lcol + 0][lrow] = wv.x;
        Ws[lcol + 1][lrow] = wv.y;
        Ws[lcol + 2][lrow] = wv.z;
        Ws[lcol + 3][lrow] = wv.w;
        __syncthreads();

        #pragma unroll
        for (int k = 0; k < BK; k++) {
            float a0 = As[k][tm + 0], a1 = As[k][tm + 1], a2 = As[k][tm + 2], a3 = As[k][tm + 3];
            float b0 = Ws[k][tn + 0], b1 = Ws[k][tn + 1], b2 = Ws[k][tn + 2], b3 = Ws[k][tn + 3];
            acc[0][0] += a0*b0; acc[0][1] += a0*b1; acc[0][2] += a0*b2; acc[0][3] += a0*b3;
            acc[1][0] += a1*b0; acc[1][1] += a1*b1; acc[1][2] += a1*b2; acc[1][3] += a1*b3;
            acc[2][0] += a2*b0; acc[2][1] += a2*b1; acc[2][2] += a2*b2; acc[2][3] += a2*b3;
            acc[3][0] += a3*b0; acc[3][1] += a3*b1; acc[3][2] += a3*b2; acc[3][3] += a3*b3;
        }
        __syncthreads();
    }

    #pragma unroll
    for (int i = 0; i < 4; i++) {
        int gm = bm + tm + i;
        if (gm >= M) continue;
        #pragma unroll
        for (int j = 0; j < 4; j++) {
            int gn = bn + tn + j;
            float v = acc[i][j] + bias[gn];
            if (relu) v = fmaxf(v, 0.f);
            C[(size_t)gm * N + gn] = v;
        }
    }
}

// ---------------- self-attention: per (b,h), N=300, DH=32, q|k fused layout ----------------
__global__ void attn_kernel(const float* __restrict__ qk,
                            const float* __restrict__ vh, float* __restrict__ out) {
    const float scale = 0.17677669529663687f; // 1/sqrt(32)
    int bh = blockIdx.x;
    int b = bh >> 3, h = bh & 7;
    __shared__ float Ks[NQ * 33];
    __shared__ float Ps[6][304];

    int tid = threadIdx.x;
    int w = tid >> 5, lane = tid & 31;

    // load K tile: k at qk[bq*512 + 256 + h*32 + c]
    for (int i = tid; i < NQ * 32; i += 192) {
        int k = i >> 5, c = i & 31;
        Ks[k * 33 + c] = qk[(size_t)(b * NQ + k) * 512 + 256 + h * 32 + c];
    }
    __syncthreads();

    for (int q = w; q < NQ; q += 6) {
        float qreg = qk[(size_t)(b * NQ + q) * 512 + h * 32 + lane];
        float sj[10];
        float mx = -3.0e38f;
        #pragma unroll
        for (int j = 0; j < 10; j++) {
            int k = lane + 32 * j;
            int kk = (k < NQ) ? k : (NQ - 1);
            float acc = 0.f;
            #pragma unroll
            for (int c = 0; c < 32; c++)
                acc = fmaf(__shfl_sync(0xffffffffu, qreg, c), Ks[kk * 33 + c], acc);
            acc *= scale;
            sj[j] = (k < NQ) ? acc : -3.0e38f;
            mx = fmaxf(mx, sj[j]);
        }
        #pragma unroll
        for (int o = 16; o > 0; o >>= 1)
            mx = fmaxf(mx, __shfl_xor_sync(0xffffffffu, mx, o));
        float lsum = 0.f;
        float pj[10];
        #pragma unroll
        for (int j = 0; j < 10; j++) {
            int k = lane + 32 * j;
            pj[j] = (k < NQ) ? expf(sj[j] - mx) : 0.f;
            lsum += pj[j];
        }
        #pragma unroll
        for (int o = 16; o > 0; o >>= 1)
            lsum += __shfl_xor_sync(0xffffffffu, lsum, o);
        float inv = 1.f / lsum;
        #pragma unroll
        for (int j = 0; j < 10; j++) {
            int k = lane + 32 * j;
            if (k < NQ) Ps[w][k] = pj[j] * inv;
        }
        __syncwarp();
        float acc = 0.f;
        for (int k = 0; k < NQ; k++)
            acc = fmaf(Ps[w][k], vh[(size_t)(b * NQ + k) * D + h * 32 + lane], acc);
        out[(size_t)(b * NQ + q) * D + h * 32 + lane] = acc;
        __syncwarp();
    }
}

// ---------------- layernorm (optional residual) ----------------
__global__ void ln_kernel(const float* __restrict__ x, const float* __restrict__ r,
                          const float* __restrict__ g, const float* __restrict__ be,
                          float* __restrict__ y) {
    int row = blockIdx.x;
    int d = threadIdx.x;
    size_t base = (size_t)row * D;
    float v = x[base + d];
    if (r) v += r[base + d];
    __shared__ float sh[D];
    sh[d] = v; __syncthreads();
    for (int o = 128; o > 0; o >>= 1) { if (d < o) sh[d] += sh[d + o]; __syncthreads(); }
    float mean = sh[0] * (1.f / D);
    __syncthreads();
    float dv = v - mean;
    sh[d] = dv * dv; __syncthreads();
    for (int o = 128; o > 0; o >>= 1) { if (d < o) sh[d] += sh[d + o]; __syncthreads(); }
    float var = sh[0] * (1.f / D);
    float rstd = rsqrtf(var + 1e-5f);
    y[base + d] = dv * rstd * g[d] + be[d];
}

// ---------------- softmax over last 16 ----------------
__global__ void softmax16_kernel(float* __restrict__ aw, int rows) {
    int rIdx = blockIdx.x * blockDim.x + threadIdx.x;
    if (rIdx >= rows) return;
    float* p = aw + (size_t)rIdx * 16;
    float m = -3.0e38f;
    float e[16];
    #pragma unroll
    for (int i = 0; i < 16; i++) m = fmaxf(m, p[i]);
    float s = 0.f;
    #pragma unroll
    for (int i = 0; i < 16; i++) { e[i] = expf(p[i] - m); s += e[i]; }
    float inv = 1.f / s;
    #pragma unroll
    for (int i = 0; i < 16; i++) p[i] = e[i] * inv;
}

// ---------------- deformable sampling in src space + fused head projection ----------------
// grid = BNQ/QB blocks, 256 threads. Warp h samples head h for QB queries into
// smem s[qq][h][256] (raw 256-dim src accumulation) + wsum; then each thread
// computes one of 256 outputs of the block-diagonal val_w projection.
__global__ __launch_bounds__(256)
void msdeform_kernel(const float* __restrict__ src, const float* __restrict__ off,
                     const float* __restrict__ aw, const float* __restrict__ ref,
                     const float* __restrict__ valwT, const float* __restrict__ valb,
                     float* __restrict__ samp) {
    const int Hs[4]  = {100, 50, 25, 13};
    const int Wls[4] = {134, 67, 34, 17};
    const int S0[4]  = {0, 13400, 16750, 17600};

    __shared__ float sh_s[QB][NH][256];
    __shared__ float sh_ws[QB][NH];

    int h = threadIdx.x >> 5, lane = threadIdx.x & 31;
    int bq0 = blockIdx.x * QB;
    int b = bq0 / NQ;   // QB-aligned groups never cross batch (300 % 4 == 0)

    for (int qq = 0; qq < QB; qq++) {
        int bq = bq0 + qq;
        const float* offp = off + (size_t)bq * 256 + h * 32;
        const float* awp  = aw  + (size_t)bq * 128 + h * 16;
        const float* refp = ref + (size_t)bq * (NL * 2);

        float acc[8] = {};
        float wsum = 0.f;

        #pragma unroll
        for (int l = 0; l < 4; l++) {
            float rx = refp[l * 2 + 0];
            float ry = refp[l * 2 + 1];
            int Wl = Wls[l], Hl = Hs[l];
            float Wf = (float)Wl, Hf = (float)Hl;
            int rowbase = b * LTOT + S0[l];
            #pragma unroll
            for (int p = 0; p < 4; p++) {
                float ox = offp[(l * 4 + p) * 2 + 0];
                float oy = offp[(l * 4 + p) * 2 + 1];
                float a  = awp[l * 4 + p];
                float x = fmaf(rx, Wf, ox) - 0.5f;
                float y = fmaf(ry, Hf, oy) - 0.5f;
                float x0f = floorf(x), y0f = floorf(y);
                int x0 = (int)x0f, y0 = (int)y0f;
                float wx = x - x0f, wy = y - y0f;
                float tw[4] = {(1.f - wx) * (1.f - wy) * a, wx * (1.f - wy) * a,
                               (1.f - wx) * wy * a,          wx * wy * a};
                int xs[4] = {x0, x0 + 1, x0,     x0 + 1};
                int ys[4] = {y0, y0,     y0 + 1, y0 + 1};
                #pragma unroll
                for (int t = 0; t < 4; t++) {
                    int xi = xs[t], yi = ys[t];
                    if (xi < 0 || xi >= Wl || yi < 0 || yi >= Hl) continue;
                    const float4* pr = (const float4*)(src + ((size_t)rowbase + (size_t)yi * Wl + xi) * 256);
                    float w = tw[t];
                    float4 v0 = __ldg(pr + lane);
                    float4 v1 = __ldg(pr + 32 + lane);
                    acc[0] = fmaf(w, v0.x, acc[0]);
                    acc[1] = fmaf(w, v0.y, acc[1]);
                    acc[2] = fmaf(w, v0.z, acc[2]);
                    acc[3] = fmaf(w, v0.w, acc[3]);
                    acc[4] = fmaf(w, v1.x, acc[4]);
                    acc[5] = fmaf(w, v1.y, acc[5]);
                    acc[6] = fmaf(w, v1.z, acc[6]);
                    acc[7] = fmaf(w, v1.w, acc[7]);
                    wsum += w;
                }
            }
        }
        // store to smem: channels c = lane*4..+3 and 128+lane*4..+3
        float4* sp = (float4*)&sh_s[qq][h][0];
        sp[lane]      = make_float4(acc[0], acc[1], acc[2], acc[3]);
        sp[32 + lane] = make_float4(acc[4], acc[5], acc[6], acc[7]);
        if (lane == 0) sh_ws[qq][h] = wsum;
    }
    __syncthreads();

    // ---- block-diagonal projection: out n = dot(s[h(n)], val_w[n,:]) + wsum*val_b[n]
    int n = threadIdx.x;
    int h2 = n >> 5;
    float t0 = 0.f, t1 = 0.f, t2 = 0.f, t3 = 0.f;
    #pragma unroll 4
    for (int c = 0; c < 256; c++) {
        float w = __ldg(valwT + (size_t)c * 256 + n);   // coalesced
        t0 = fmaf(sh_s[0][h2][c], w, t0);
        t1 = fmaf(sh_s[1][h2][c], w, t1);
        t2 = fmaf(sh_s[2][h2][c], w, t2);
        t3 = fmaf(sh_s[3][h2][c], w, t3);
    }
    float vb = valb[n];
    samp[(size_t)(bq0 + 0) * 256 + n] = t0 + sh_ws[0][h2] * vb;
    samp[(size_t)(bq0 + 1) * 256 + n] = t1 + sh_ws[1][h2] * vb;
    samp[(size_t)(bq0 + 2) * 256 + n] = t2 + sh_ws[2][h2] * vb;
    samp[(size_t)(bq0 + 3) * 256 + n] = t3 + sh_ws[3][h2] * vb;
}

// ---------------- host side ----------------
static void gemm(const float* A, const float* A2, const float* W, const float* bias,
                 float* C, int M, int N, int K, int relu) {
    dim3 grid(N / BN, (M + BM - 1) / BM);
    sgemm_kernel<<<grid, 256>>>(A, A2, W, bias, C, M, N, K, relu);
}

extern "C" void kernel_launch(void* const* d_in, const int* in_sizes, int n_in,
                              void* d_out_v, int out_size) {
    const float* tgt[2] = {(const float*)d_in[0], (const float*)d_in[1]};
    const float* pos[2] = {(const float*)d_in[2], (const float*)d_in[3]};
    const float* ref[2] = {(const float*)d_in[4], (const float*)d_in[5]};
    const float* src[2] = {(const float*)d_in[6], (const float*)d_in[7]};
    const float* sa_in_w  = (const float*)d_in[8];
    const float* sa_in_b  = (const float*)d_in[9];
    const float* sa_out_w = (const float*)d_in[10];
    const float* sa_out_b = (const float*)d_in[11];
    const float* ln_w     = (const float*)d_in[12];
    const float* ln_b     = (const float*)d_in[13];
    const float* ffn_w1   = (const float*)d_in[14];
    const float* ffn_b1   = (const float*)d_in[15];
    const float* ffn_w2   = (const float*)d_in[16];
    const float* ffn_b2   = (const float*)d_in[17];
    const float* val_w    = (const float*)d_in[18];
    const float* val_b    = (const float*)d_in[19];
    const float* off_w    = (const float*)d_in[20];
    const float* off_b    = (const float*)d_in[21];
    const float* aw_w     = (const float*)d_in[22];
    const float* aw_b     = (const float*)d_in[23];
    const float* cout_w   = (const float*)d_in[24];
    const float* cout_b   = (const float*)d_in[25];
    float* out = (float*)d_out_v;

    float *p_qk, *p_vh, *p_attn, *p_sa, *p_tgt2, *p_off, *p_aw,
          *p_samp, *p_ffn, *p_y, *p_x, *p_r, *p_t, *p_wT;
    cudaGetSymbolAddress((void**)&p_qk,   g_qk);
    cudaGetSymbolAddress((void**)&p_vh,   g_vh);
    cudaGetSymbolAddress((void**)&p_attn, g_attn);
    cudaGetSymbolAddress((void**)&p_sa,   g_sa);
    cudaGetSymbolAddress((void**)&p_tgt2, g_tgt2);
    cudaGetSymbolAddress((void**)&p_off,  g_off);
    cudaGetSymbolAddress((void**)&p_aw,   g_aw);
    cudaGetSymbolAddress((void**)&p_samp, g_samp);
    cudaGetSymbolAddress((void**)&p_ffn,  g_ffn);
    cudaGetSymbolAddress((void**)&p_y,    g_y);
    cudaGetSymbolAddress((void**)&p_x,    g_x);
    cudaGetSymbolAddress((void**)&p_r,    g_r);
    cudaGetSymbolAddress((void**)&p_t,    g_t);
    cudaGetSymbolAddress((void**)&p_wT,   g_wT);

    const int NE = BNQ * D;                 // 307200
    const int GRID_E = (NE + 255) / 256;

    for (int m = 0; m < 2; m++) {
        float* tgt2m = p_tgt2 + (size_t)m * NE;
        const float* wbase = sa_in_w + (size_t)m * 3 * D * D;
        const float* bbase = sa_in_b + (size_t)m * 3 * D;

        // fused q|k projection from (tgt+pos), v projection from tgt
        gemm(tgt[m], pos[m], wbase,             bbase,         p_qk, BNQ, 512, D, 0);
        gemm(tgt[m], nullptr, wbase + 2 * D * D, bbase + 2 * D, p_vh, BNQ, D,   D, 0);
        attn_kernel<<<BS * NH, 192>>>(p_qk, p_vh, p_attn);
        gemm(p_attn, nullptr, sa_out_w + (size_t)m * D * D, sa_out_b + m * D, p_sa, BNQ, D, D, 0);
        // tgt2 = LN(tgt + sa)  (norm2)
        ln_kernel<<<BNQ, 256>>>(tgt[m], p_sa, ln_w + (m * 3 + 1) * D, ln_b + (m * 3 + 1) * D, tgt2m);

        // offsets / attention weights from (tgt2 + pos), add fused into GEMM
        gemm(tgt2m, pos[m], off_w + (size_t)m * D * D,   off_b + m * 256, p_off, BNQ, 256, D, 0);
        gemm(tgt2m, pos[m], aw_w  + (size_t)m * 128 * D, aw_b  + m * 128, p_aw,  BNQ, 128, D, 0);
        softmax16_kernel<<<(BNQ * NH + 255) / 256, 256>>>(p_aw, BNQ * NH);

        // sample raw src (other modality), fused val_w projection
        transpose256_kernel<<<dim3(8, 8), dim3(32, 8)>>>(val_w + (size_t)m * D * D, p_wT);
        msdeform_kernel<<<BNQ / QB, 256>>>(src[1 - m], p_off, p_aw, ref[m],
                                           p_wT, val_b + m * D, p_samp);
        // cout projection -> straight into output regions F_RGB / F_T
        gemm(p_samp, nullptr, cout_w + (size_t)m * D * D, cout_b + m * D,
             out + (size_t)(2 + m) * NE, BNQ, D, D, 0);
    }

    // cross residuals: r = tgt2_T + t2_RGB ; t = r + t2_T
    add2_kernel<<<GRID_E, 256>>>(p_tgt2 + (size_t)NE, out + (size_t)2 * NE, p_r, NE);
    add2_kernel<<<GRID_E, 256>>>(p_r, out + (size_t)3 * NE, p_t, NE);
    ln_kernel<<<BNQ, 256>>>(p_r, nullptr, ln_w + 0 * D, ln_b + 0 * D, p_x);
    ln_kernel<<<BNQ, 256>>>(p_t, nullptr, ln_w + 3 * D, ln_b + 3 * D, p_x + (size_t)NE);

    // FFNs
    for (int m = 0; m < 2; m++) {
        float* xm = p_x + (size_t)m * NE;
        gemm(xm,    nullptr, ffn_w1 + (size_t)m * DFF * D, ffn_b1 + m * DFF, p_ffn, BNQ, DFF, D, 1);
        gemm(p_ffn, nullptr, ffn_w2 + (size_t)m * D * DFF, ffn_b2 + m * D,   p_y,   BNQ, D, DFF, 0);
        ln_kernel<<<BNQ, 256>>>(xm, p_y, ln_w + (m * 3 + 2) * D, ln_b + (m * 3 + 2) * D,
                                out + (size_t)m * NE);
    }
}

// round 3
// speedup vs baseline: 2.1620x; 1.4688x over previous
#include <cuda_runtime.h>
#include <cuda_bf16.h>
#include <math.h>

// ---------------- problem constants ----------------
#define BS   4
#define NQ   300
#define D    256
#define NH   8
#define DH   32
#define NL   4
#define NP   4
#define DFF  1024
#define LTOT 17821
#define BNQ  (BS*NQ)          // 1200
#define QB   4                // queries per msdeform block
#define NE   (BNQ*D)          // 307200

// ---------------- scratch (device globals; no allocation allowed) ----------------
__device__ float g_qk  [2][BNQ*512];
__device__ float g_vh  [2][BNQ*D];
__device__ float g_attn[2][BNQ*D];
__device__ float g_sa  [2][BNQ*D];
__device__ float g_tgt2[2][BNQ*D];
__device__ float g_off [2][BNQ*D];
__device__ float g_aw  [2*BNQ*(NH*NL*NP)];
__device__ float g_samp[2][BNQ*D];
__device__ float g_ffn [2][BNQ*DFF];
__device__ float g_y   [2][BNQ*D];
__device__ float g_x   [2][BNQ*D];
__device__ float g_r   [BNQ*D];
__device__ float g_t   [BNQ*D];
__device__ float g_wT  [2][D*D];

// ---------------- pointer-pack structs (passed by value) ----------------
struct GPtrs {
    const float* A[2];
    const float* A2[2];
    const float* W[2];
    const float* B[2];
    float*       C[2];
};
struct LnArgs {
    const float* x[2];
    const float* r[2];
    const float* g[2];
    const float* b[2];
    float*       y[2];
};
struct AttnArgs {
    const float* qk[2];
    const float* vh[2];
    float*       out[2];
};
struct MsdArgs {
    const float* src[2];
    const float* off[2];
    const float* aw[2];
    const float* ref[2];
    const float* wT[2];
    const float* vb[2];
    float*       samp[2];
};

// ---------------- fused cross residual ----------------
__global__ void cross_res_kernel(const float* __restrict__ tgt2T, const float* __restrict__ t2R,
                                 const float* __restrict__ t2T,
                                 float* __restrict__ r, float* __restrict__ t, int n) {
    int i = blockIdx.x * blockDim.x + threadIdx.x;
    if (i < n) {
        float rv = tgt2T[i] + t2R[i];
        r[i] = rv;
        t[i] = rv + t2T[i];
    }
}

// ---------------- weight transpose 256x256, z-batched ----------------
__global__ void transpose256_kernel(const float* __restrict__ w, float* __restrict__ wT) {
    __shared__ float tile[32][33];
    int z = blockIdx.z;
    const float* ws = w + (size_t)z * D * D;
    float* wd = wT + (size_t)z * D * D;
    int bx = blockIdx.x * 32, by = blockIdx.y * 32;
    int tx = threadIdx.x, ty = threadIdx.y;
    #pragma unroll
    for (int i = 0; i < 32; i += 8)
        tile[ty + i][tx] = ws[(size_t)(by + ty + i) * D + bx + tx];
    __syncthreads();
    #pragma unroll
    for (int i = 0; i < 32; i += 8)
        wd[(size_t)(bx + ty + i) * D + by + tx] = tile[tx][ty + i];
}

// ---------------- pipelined SGEMM, z-batched over modality ----------------
// C[M,N] = (A (+A2))[M,K] @ W[N,K]^T + bias (+relu)
#define BM 64
#define BN 64
#define BK 16
__global__ __launch_bounds__(256)
void sgemm2_kernel(GPtrs g, int M, int N, int K, int relu) {
    int z = blockIdx.z;
    const float* __restrict__ A  = g.A[z];
    const float* __restrict__ A2 = g.A2[z];
    const float* __restrict__ W  = g.W[z];
    const float* __restrict__ bias = g.B[z];
    float* __restrict__ C = g.C[z];

    __shared__ float As[2][BK][BM + 4];
    __shared__ float Ws[2][BK][BN + 4];

    int tid = threadIdx.x;
    int bm = blockIdx.y * BM;
    int bn = blockIdx.x * BN;

    int lrow = tid >> 2;             // 0..63
    int lcol = (tid & 3) << 2;       // 0,4,8,12
    int tm = (tid >> 4) << 2;
    int tn = (tid & 15) << 2;

    int gm = bm + lrow;
    bool mv = gm < M;
    const float* Ap  = A + (size_t)(mv ? gm : 0) * K + lcol;
    const float* A2p = A2 ? A2 + (size_t)(mv ? gm : 0) * K + lcol : nullptr;
    const float* Wp  = W + (size_t)(bn + lrow) * K + lcol;

    float4 av, wv;
    // tile 0 load
    av = make_float4(0.f, 0.f, 0.f, 0.f);
    if (mv) {
        av = *(const float4*)Ap;
        if (A2p) {
            float4 t2 = *(const float4*)A2p;
            av.x += t2.x; av.y += t2.y; av.z += t2.z; av.w += t2.w;
        }
    }
    wv = *(const float4*)Wp;
    As[0][lcol + 0][lrow] = av.x; As[0][lcol + 1][lrow] = av.y;
    As[0][lcol + 2][lrow] = av.z; As[0][lcol + 3][lrow] = av.w;
    Ws[0][lcol + 0][lrow] = wv.x; Ws[0][lcol + 1][lrow] = wv.y;
    Ws[0][lcol + 2][lrow] = wv.z; Ws[0][lcol + 3][lrow] = wv.w;
    __syncthreads();

    float acc[4][4] = {};
    int T = K / BK;
    for (int t = 0; t < T; t++) {
        int buf = t & 1;
        if (t + 1 < T) {
            int ko = (t + 1) * BK;
            av = make_float4(0.f, 0.f, 0.f, 0.f);
            if (mv) {
                av = *(const float4*)(Ap + ko);
                if (A2p) {
                    float4 t2 = *(const float4*)(A2p + ko);
                    av.x += t2.x; av.y += t2.y; av.z += t2.z; av.w += t2.w;
                }
            }
            wv = *(const float4*)(Wp + ko);
        }
        const float (*Ac)[BM + 4] = As[buf];
        const float (*Wc)[BN + 4] = Ws[buf];
        #pragma unroll
        for (int k = 0; k < BK; k++) {
            float4 a = *(const float4*)&Ac[k][tm];
            float4 b = *(const float4*)&Wc[k][tn];
            acc[0][0] += a.x*b.x; acc[0][1] += a.x*b.y; acc[0][2] += a.x*b.z; acc[0][3] += a.x*b.w;
            acc[1][0] += a.y*b.x; acc[1][1] += a.y*b.y; acc[1][2] += a.y*b.z; acc[1][3] += a.y*b.w;
            acc[2][0] += a.z*b.x; acc[2][1] += a.z*b.y; acc[2][2] += a.z*b.z; acc[2][3] += a.z*b.w;
            acc[3][0] += a.w*b.x; acc[3][1] += a.w*b.y; acc[3][2] += a.w*b.z; acc[3][3] += a.w*b.w;
        }
        if (t + 1 < T) {
            int nb = buf ^ 1;
            As[nb][lcol + 0][lrow] = av.x; As[nb][lcol + 1][lrow] = av.y;
            As[nb][lcol + 2][lrow] = av.z; As[nb][lcol + 3][lrow] = av.w;
            Ws[nb][lcol + 0][lrow] = wv.x; Ws[nb][lcol + 1][lrow] = wv.y;
            Ws[nb][lcol + 2][lrow] = wv.z; Ws[nb][lcol + 3][lrow] = wv.w;
            __syncthreads();
        }
    }

    #pragma unroll
    for (int i = 0; i < 4; i++) {
        int gmo = bm + tm + i;
        if (gmo >= M) continue;
        #pragma unroll
        for (int j = 0; j < 4; j++) {
            int gn = bn + tn + j;
            float v = acc[i][j] + bias[gn];
            if (relu) v = fmaxf(v, 0.f);
            C[(size_t)gmo * N + gn] = v;
        }
    }
}

// ---------------- self-attention: per (b,h,z), N=300, DH=32 ----------------
__global__ void attn_kernel(AttnArgs a) {
    const float scale = 0.17677669529663687f; // 1/sqrt(32)
    int z = blockIdx.y;
    const float* __restrict__ qk = a.qk[z];
    const float* __restrict__ vh = a.vh[z];
    float* __restrict__ out = a.out[z];

    int bh = blockIdx.x;
    int b = bh >> 3, h = bh & 7;
    __shared__ float Ks[NQ * 33];
    __shared__ float Ps[6][304];

    int tid = threadIdx.x;
    int w = tid >> 5, lane = tid & 31;

    for (int i = tid; i < NQ * 32; i += 192) {
        int k = i >> 5, c = i & 31;
        Ks[k * 33 + c] = qk[(size_t)(b * NQ + k) * 512 + 256 + h * 32 + c];
    }
    __syncthreads();

    for (int q = w; q < NQ; q += 6) {
        float qreg = qk[(size_t)(b * NQ + q) * 512 + h * 32 + lane];
        float sj[10];
        float mx = -3.0e38f;
        #pragma unroll
        for (int j = 0; j < 10; j++) {
            int k = lane + 32 * j;
            int kk = (k < NQ) ? k : (NQ - 1);
            float acc = 0.f;
            #pragma unroll
            for (int c = 0; c < 32; c++)
                acc = fmaf(__shfl_sync(0xffffffffu, qreg, c), Ks[kk * 33 + c], acc);
            acc *= scale;
            sj[j] = (k < NQ) ? acc : -3.0e38f;
            mx = fmaxf(mx, sj[j]);
        }
        #pragma unroll
        for (int o = 16; o > 0; o >>= 1)
            mx = fmaxf(mx, __shfl_xor_sync(0xffffffffu, mx, o));
        float lsum = 0.f;
        float pj[10];
        #pragma unroll
        for (int j = 0; j < 10; j++) {
            int k = lane + 32 * j;
            pj[j] = (k < NQ) ? expf(sj[j] - mx) : 0.f;
            lsum += pj[j];
        }
        #pragma unroll
        for (int o = 16; o > 0; o >>= 1)
            lsum += __shfl_xor_sync(0xffffffffu, lsum, o);
        float inv = 1.f / lsum;
        #pragma unroll
        for (int j = 0; j < 10; j++) {
            int k = lane + 32 * j;
            if (k < NQ) Ps[w][k] = pj[j] * inv;
        }
        __syncwarp();
        float acc = 0.f;
        for (int k = 0; k < NQ; k++)
            acc = fmaf(Ps[w][k], vh[(size_t)(b * NQ + k) * D + h * 32 + lane], acc);
        out[(size_t)(b * NQ + q) * D + h * 32 + lane] = acc;
        __syncwarp();
    }
}

// ---------------- layernorm (optional residual), z-batched ----------------
__global__ void ln_kernel(LnArgs a) {
    int z = blockIdx.y;
    int row = blockIdx.x;
    int d = threadIdx.x;
    size_t base = (size_t)row * D;
    float v = a.x[z][base + d];
    if (a.r[z]) v += a.r[z][base + d];
    __shared__ float sh[D];
    sh[d] = v; __syncthreads();
    for (int o = 128; o > 0; o >>= 1) { if (d < o) sh[d] += sh[d + o]; __syncthreads(); }
    float mean = sh[0] * (1.f / D);
    __syncthreads();
    float dv = v - mean;
    sh[d] = dv * dv; __syncthreads();
    for (int o = 128; o > 0; o >>= 1) { if (d < o) sh[d] += sh[d + o]; __syncthreads(); }
    float var = sh[0] * (1.f / D);
    float rstd = rsqrtf(var + 1e-5f);
    a.y[z][base + d] = dv * rstd * a.g[z][d] + a.b[z][d];
}

// ---------------- softmax over last 16 ----------------
__global__ void softmax16_kernel(float* __restrict__ aw, int rows) {
    int rIdx = blockIdx.x * blockDim.x + threadIdx.x;
    if (rIdx >= rows) return;
    float* p = aw + (size_t)rIdx * 16;
    float m = -3.0e38f;
    float e[16];
    #pragma unroll
    for (int i = 0; i < 16; i++) m = fmaxf(m, p[i]);
    float s = 0.f;
    #pragma unroll
    for (int i = 0; i < 16; i++) { e[i] = expf(p[i] - m); s += e[i]; }
    float inv = 1.f / s;
    #pragma unroll
    for (int i = 0; i < 16; i++) p[i] = e[i] * inv;
}

// ---------------- deformable sampling in src space + fused head projection ----------------
__global__ __launch_bounds__(256)
void msdeform_kernel(MsdArgs ar) {
    const int Hs[4]  = {100, 50, 25, 13};
    const int Wls[4] = {134, 67, 34, 17};
    const int S0[4]  = {0, 13400, 16750, 17600};

    int z = blockIdx.y;
    const float* __restrict__ src = ar.src[z];
    const float* __restrict__ off = ar.off[z];
    const float* __restrict__ aw  = ar.aw[z];
    const float* __restrict__ ref = ar.ref[z];
    const float* __restrict__ valwT = ar.wT[z];
    const float* __restrict__ valb  = ar.vb[z];
    float* __restrict__ samp = ar.samp[z];

    __shared__ float sh_s[QB][NH][256];
    __shared__ float sh_ws[QB][NH];

    int h = threadIdx.x >> 5, lane = threadIdx.x & 31;
    int bq0 = blockIdx.x * QB;
    int b = bq0 / NQ;

    for (int qq = 0; qq < QB; qq++) {
        int bq = bq0 + qq;
        const float* offp = off + (size_t)bq * 256 + h * 32;
        const float* awp  = aw  + (size_t)bq * 128 + h * 16;
        const float* refp = ref + (size_t)bq * (NL * 2);

        float acc[8] = {};
        float wsum = 0.f;

        #pragma unroll
        for (int l = 0; l < 4; l++) {
            float rx = refp[l * 2 + 0];
            float ry = refp[l * 2 + 1];
            int Wl = Wls[l], Hl = Hs[l];
            float Wf = (float)Wl, Hf = (float)Hl;
            int rowbase = b * LTOT + S0[l];
            #pragma unroll
            for (int p = 0; p < 4; p++) {
                float ox = offp[(l * 4 + p) * 2 + 0];
                float oy = offp[(l * 4 + p) * 2 + 1];
                float a  = awp[l * 4 + p];
                float x = fmaf(rx, Wf, ox) - 0.5f;
                float y = fmaf(ry, Hf, oy) - 0.5f;
                float x0f = floorf(x), y0f = floorf(y);
                int x0 = (int)x0f, y0 = (int)y0f;
                float wx = x - x0f, wy = y - y0f;
                float tw[4] = {(1.f - wx) * (1.f - wy) * a, wx * (1.f - wy) * a,
                               (1.f - wx) * wy * a,          wx * wy * a};
                int xs[4] = {x0, x0 + 1, x0,     x0 + 1};
                int ys[4] = {y0, y0,     y0 + 1, y0 + 1};
                #pragma unroll
                for (int t = 0; t < 4; t++) {
                    int xi = xs[t], yi = ys[t];
                    if (xi < 0 || xi >= Wl || yi < 0 || yi >= Hl) continue;
                    const float4* pr = (const float4*)(src + ((size_t)rowbase + (size_t)yi * Wl + xi) * 256);
                    float w = tw[t];
                    float4 v0 = __ldg(pr + lane);
                    float4 v1 = __ldg(pr + 32 + lane);
                    acc[0] = fmaf(w, v0.x, acc[0]);
                    acc[1] = fmaf(w, v0.y, acc[1]);
                    acc[2] = fmaf(w, v0.z, acc[2]);
                    acc[3] = fmaf(w, v0.w, acc[3]);
                    acc[4] = fmaf(w, v1.x, acc[4]);
                    acc[5] = fmaf(w, v1.y, acc[5]);
                    acc[6] = fmaf(w, v1.z, acc[6]);
                    acc[7] = fmaf(w, v1.w, acc[7]);
                    wsum += w;
                }
            }
        }
        float4* sp = (float4*)&sh_s[qq][h][0];
        sp[lane]      = make_float4(acc[0], acc[1], acc[2], acc[3]);
        sp[32 + lane] = make_float4(acc[4], acc[5], acc[6], acc[7]);
        if (lane == 0) sh_ws[qq][h] = wsum;
    }
    __syncthreads();

    int n = threadIdx.x;
    int h2 = n >> 5;
    float t0 = 0.f, t1 = 0.f, t2 = 0.f, t3 = 0.f;
    #pragma unroll 4
    for (int c = 0; c < 256; c++) {
        float w = __ldg(valwT + (size_t)c * 256 + n);
        t0 = fmaf(sh_s[0][h2][c], w, t0);
        t1 = fmaf(sh_s[1][h2][c], w, t1);
        t2 = fmaf(sh_s[2][h2][c], w, t2);
        t3 = fmaf(sh_s[3][h2][c], w, t3);
    }
    float vb = valb[n];
    samp[(size_t)(bq0 + 0) * 256 + n] = t0 + sh_ws[0][h2] * vb;
    samp[(size_t)(bq0 + 1) * 256 + n] = t1 + sh_ws[1][h2] * vb;
    samp[(size_t)(bq0 + 2) * 256 + n] = t2 + sh_ws[2][h2] * vb;
    samp[(size_t)(bq0 + 3) * 256 + n] = t3 + sh_ws[3][h2] * vb;
}

// ---------------- host side ----------------
static void gemm2(GPtrs& g, int M, int N, int K, int relu) {
    dim3 grid(N / BN, (M + BM - 1) / BM, 2);
    sgemm2_kernel<<<grid, 256>>>(g, M, N, K, relu);
}

extern "C" void kernel_launch(void* const* d_in, const int* in_sizes, int n_in,
                              void* d_out_v, int out_size) {
    const float* tgt[2] = {(const float*)d_in[0], (const float*)d_in[1]};
    const float* pos[2] = {(const float*)d_in[2], (const float*)d_in[3]};
    const float* refp[2] = {(const float*)d_in[4], (const float*)d_in[5]};
    const float* src[2] = {(const float*)d_in[6], (const float*)d_in[7]};
    const float* sa_in_w  = (const float*)d_in[8];
    const float* sa_in_b  = (const float*)d_in[9];
    const float* sa_out_w = (const float*)d_in[10];
    const float* sa_out_b = (const float*)d_in[11];
    const float* ln_w     = (const float*)d_in[12];
    const float* ln_b     = (const float*)d_in[13];
    const float* ffn_w1   = (const float*)d_in[14];
    const float* ffn_b1   = (const float*)d_in[15];
    const float* ffn_w2   = (const float*)d_in[16];
    const float* ffn_b2   = (const float*)d_in[17];
    const float* val_w    = (const float*)d_in[18];
    const float* val_b    = (const float*)d_in[19];
    const float* off_w    = (const float*)d_in[20];
    const float* off_b    = (const float*)d_in[21];
    const float* aw_w     = (const float*)d_in[22];
    const float* aw_b     = (const float*)d_in[23];
    const float* cout_w   = (const float*)d_in[24];
    const float* cout_b   = (const float*)d_in[25];
    float* out = (float*)d_out_v;

    float *p_qk, *p_vh, *p_attn, *p_sa, *p_tgt2, *p_off, *p_aw,
          *p_samp, *p_ffn, *p_y, *p_x, *p_r, *p_t, *p_wT;
    cudaGetSymbolAddress((void**)&p_qk,   g_qk);
    cudaGetSymbolAddress((void**)&p_vh,   g_vh);
    cudaGetSymbolAddress((void**)&p_attn, g_attn);
    cudaGetSymbolAddress((void**)&p_sa,   g_sa);
    cudaGetSymbolAddress((void**)&p_tgt2, g_tgt2);
    cudaGetSymbolAddress((void**)&p_off,  g_off);
    cudaGetSymbolAddress((void**)&p_aw,   g_aw);
    cudaGetSymbolAddress((void**)&p_samp, g_samp);
    cudaGetSymbolAddress((void**)&p_ffn,  g_ffn);
    cudaGetSymbolAddress((void**)&p_y,    g_y);
    cudaGetSymbolAddress((void**)&p_x,    g_x);
    cudaGetSymbolAddress((void**)&p_r,    g_r);
    cudaGetSymbolAddress((void**)&p_t,    g_t);
    cudaGetSymbolAddress((void**)&p_wT,   g_wT);

    const int GRID_E = (NE + 255) / 256;

    // ---- q|k projection (both modalities), A = tgt+pos
    {
        GPtrs g = {{tgt[0], tgt[1]}, {pos[0], pos[1]},
                   {sa_in_w, sa_in_w + (size_t)3 * D * D},
                   {sa_in_b, sa_in_b + 3 * D},
                   {p_qk, p_qk + (size_t)BNQ * 512}};
        gemm2(g, BNQ, 512, D, 0);
    }
    // ---- v projection, A = tgt
    {
        GPtrs g = {{tgt[0], tgt[1]}, {nullptr, nullptr},
                   {sa_in_w + (size_t)2 * D * D, sa_in_w + (size_t)5 * D * D},
                   {sa_in_b + 2 * D, sa_in_b + 5 * D},
                   {p_vh, p_vh + NE}};
        gemm2(g, BNQ, D, D, 0);
    }
    // ---- attention
    {
        AttnArgs a = {{p_qk, p_qk + (size_t)BNQ * 512}, {p_vh, p_vh + NE}, {p_attn, p_attn + NE}};
        attn_kernel<<<dim3(BS * NH, 2), 192>>>(a);
    }
    // ---- out projection
    {
        GPtrs g = {{p_attn, p_attn + NE}, {nullptr, nullptr},
                   {sa_out_w, sa_out_w + (size_t)D * D},
                   {sa_out_b, sa_out_b + D},
                   {p_sa, p_sa + NE}};
        gemm2(g, BNQ, D, D, 0);
    }
    // ---- tgt2 = LN(tgt + sa)  (norm2)
    {
        LnArgs a = {{tgt[0], tgt[1]}, {p_sa, p_sa + NE},
                    {ln_w + 1 * D, ln_w + 4 * D}, {ln_b + 1 * D, ln_b + 4 * D},
                    {p_tgt2, p_tgt2 + NE}};
        ln_kernel<<<dim3(BNQ, 2), 256>>>(a);
    }
    // ---- offsets and attention weights from (tgt2 + pos)
    {
        GPtrs g = {{p_tgt2, p_tgt2 + NE}, {pos[0], pos[1]},
                   {off_w, off_w + (size_t)D * D},
                   {off_b, off_b + 256},
                   {p_off, p_off + NE}};
        gemm2(g, BNQ, 256, D, 0);
    }
    {
        GPtrs g = {{p_tgt2, p_tgt2 + NE}, {pos[0], pos[1]},
                   {aw_w, aw_w + (size_t)128 * D},
                   {aw_b, aw_b + 128},
                   {p_aw, p_aw + (size_t)BNQ * 128}};
        gemm2(g, BNQ, 128, D, 0);
    }
    softmax16_kernel<<<(2 * BNQ * NH + 255) / 256, 256>>>(p_aw, 2 * BNQ * NH);

    // ---- val_w transpose + sampling (note: modality m samples src[1-m])
    transpose256_kernel<<<dim3(8, 8, 2), dim3(32, 8)>>>(val_w, p_wT);
    {
        MsdArgs a = {{src[1], src[0]},
                     {p_off, p_off + NE},
                     {p_aw, p_aw + (size_t)BNQ * 128},
                     {refp[0], refp[1]},
                     {p_wT, p_wT + (size_t)D * D},
                     {val_b, val_b + D},
                     {p_samp, p_samp + NE}};
        msdeform_kernel<<<dim3(BNQ / QB, 2), 256>>>(a);
    }
    // ---- cout projection -> output regions F_RGB / F_T
    {
        GPtrs g = {{p_samp, p_samp + NE}, {nullptr, nullptr},
                   {cout_w, cout_w + (size_t)D * D},
                   {cout_b, cout_b + D},
                   {out + (size_t)2 * NE, out + (size_t)3 * NE}};
        gemm2(g, BNQ, D, D, 0);
    }

    // ---- cross residuals: r = tgt2_T + t2_RGB ; t = r + t2_T
    cross_res_kernel<<<GRID_E, 256>>>(p_tgt2 + NE, out + (size_t)2 * NE, out + (size_t)3 * NE,
                                      p_r, p_t, NE);
    {
        LnArgs a = {{p_r, p_t}, {nullptr, nullptr},
                    {ln_w + 0 * D, ln_w + 3 * D}, {ln_b + 0 * D, ln_b + 3 * D},
                    {p_x, p_x + NE}};
        ln_kernel<<<dim3(BNQ, 2), 256>>>(a);
    }

    // ---- FFNs
    {
        GPtrs g = {{p_x, p_x + NE}, {nullptr, nullptr},
                   {ffn_w1, ffn_w1 + (size_t)DFF * D},
                   {ffn_b1, ffn_b1 + DFF},
                   {p_ffn, p_ffn + (size_t)BNQ * DFF}};
        gemm2(g, BNQ, DFF, D, 1);
    }
    {
        GPtrs g = {{p_ffn, p_ffn + (size_t)BNQ * DFF}, {nullptr, nullptr},
                   {ffn_w2, ffn_w2 + (size_t)D * DFF},
                   {ffn_b2, ffn_b2 + D},
                   {p_y, p_y + NE}};
        gemm2(g, BNQ, D, DFF, 0);
    }
    {
        LnArgs a = {{p_x, p_x + NE}, {p_y, p_y + NE},
                    {ln_w + 2 * D, ln_w + 5 * D}, {ln_b + 2 * D, ln_b + 5 * D},
                    {out, out + NE}};
        ln_kernel<<<dim3(BNQ, 2), 256>>>(a);
    }
}

// round 4
// speedup vs baseline: 2.4969x; 1.1549x over previous
#include <cuda_runtime.h>
#include <cuda_bf16.h>
#include <math.h>
#include <stdint.h>

// ---------------- problem constants ----------------
#define BS   4
#define NQ   300
#define D    256
#define NH   8
#define DH   32
#define NL   4
#define NP   4
#define DFF  1024
#define LTOT 17821
#define BNQ  (BS*NQ)          // 1200
#define QB   4                // queries per msdeform block
#define NE   (BNQ*D)          // 307200

// ---------------- scratch (device globals; no allocation allowed) ----------------
__device__ float g_qk  [2][BNQ*512];
__device__ float g_vh  [2][BNQ*D];
__device__ float g_attn[2][BNQ*D];
__device__ float g_sa  [2][BNQ*D];
__device__ float g_tgt2[2][BNQ*D];
__device__ float g_off [2][BNQ*D];
__device__ float g_aw  [2*BNQ*(NH*NL*NP)];
__device__ float g_samp[2][BNQ*D];
__device__ float g_ffn [2][BNQ*DFF];
__device__ float g_y   [2][BNQ*D];
__device__ float g_x   [2][BNQ*D];
__device__ float g_r   [BNQ*D];
__device__ float g_t   [BNQ*D];
__device__ float g_wT  [2][D*D];

// ---------------- pointer-pack structs (passed by value) ----------------
struct GPtrs {
    const float* A[2];
    const float* A2[2];
    const float* W[2];
    const float* B[2];
    float*       C[2];
};
struct LnArgs {
    const float* x[2];
    const float* r[2];
    const float* g[2];
    const float* b[2];
    float*       y[2];
};
struct AttnArgs {
    const float* qk[2];
    const float* vh[2];
    float*       out[2];
};
struct MsdArgs {
    const float* src[2];
    const float* off[2];
    const float* aw[2];
    const float* ref[2];
    const float* wT[2];
    const float* vb[2];
    float*       samp[2];
};

// ---------------- fused cross residual ----------------
__global__ void cross_res_kernel(const float* __restrict__ tgt2T, const float* __restrict__ t2R,
                                 const float* __restrict__ t2T,
                                 float* __restrict__ r, float* __restrict__ t, int n) {
    int i = blockIdx.x * blockDim.x + threadIdx.x;
    if (i < n) {
        float rv = tgt2T[i] + t2R[i];
        r[i] = rv;
        t[i] = rv + t2T[i];
    }
}

// ---------------- weight transpose 256x256, z-batched ----------------
__global__ void transpose256_kernel(const float* __restrict__ w, float* __restrict__ wT) {
    __shared__ float tile[32][33];
    int z = blockIdx.z;
    const float* ws = w + (size_t)z * D * D;
    float* wd = wT + (size_t)z * D * D;
    int bx = blockIdx.x * 32, by = blockIdx.y * 32;
    int tx = threadIdx.x, ty = threadIdx.y;
    #pragma unroll
    for (int i = 0; i < 32; i += 8)
        tile[ty + i][tx] = ws[(size_t)(by + ty + i) * D + bx + tx];
    __syncthreads();
    #pragma unroll
    for (int i = 0; i < 32; i += 8)
        wd[(size_t)(bx + ty + i) * D + by + tx] = tile[tx][ty + i];
}

// ---------------- tf32 tensor-core GEMM, z-batched over modality ----------------
// C[M,N] = (A (+A2))[M,K] @ W[N,K]^T + bias (+relu)
// 256 threads = 8 warps; BM=64 BN=64 BK=32; warp tile 16x32 via m16n8k8 tf32 mma.
#define BMt 64
#define BNt 64
#define BKt 32
#define TST 36   // padded row stride (floats)

__device__ __forceinline__ uint32_t f2tf(float f) {
    uint32_t u;
    asm("cvt.rna.tf32.f32 %0, %1;" : "=r"(u) : "f"(f));
    return u;
}

__device__ __forceinline__ void mma_tf32(float4& d, const uint32_t a0, const uint32_t a1,
                                         const uint32_t a2, const uint32_t a3,
                                         const uint32_t b0, const uint32_t b1) {
    asm volatile(
        "mma.sync.aligned.m16n8k8.row.col.f32.tf32.tf32.f32 "
        "{%0,%1,%2,%3}, {%4,%5,%6,%7}, {%8,%9}, {%0,%1,%2,%3};\n"
        : "+f"(d.x), "+f"(d.y), "+f"(d.z), "+f"(d.w)
        : "r"(a0), "r"(a1), "r"(a2), "r"(a3), "r"(b0), "r"(b1));
}

__global__ __launch_bounds__(256)
void tgemm_kernel(GPtrs g, int M, int N, int K, int relu) {
    int z = blockIdx.z;
    const float* __restrict__ A  = g.A[z];
    const float* __restrict__ A2 = g.A2[z];
    const float* __restrict__ W  = g.W[z];
    const float* __restrict__ bias = g.B[z];
    float* __restrict__ C = g.C[z];

    __shared__ float As[2][BMt * TST];
    __shared__ float Ws[2][BNt * TST];

    int tid = threadIdx.x;
    int lane = tid & 31, warp = tid >> 5;
    int wm = (warp & 3) << 4;       // 0,16,32,48
    int wn = (warp >> 2) << 5;      // 0,32
    int g8 = lane >> 2, tig = lane & 3;

    int bm = blockIdx.y * BMt, bn = blockIdx.x * BNt;

    // global load role: lrow 0..63, q 0..3 -> float4 at k = 4q and k = 16+4q
    int lrow = tid >> 2;
    int q = tid & 3;
    int gmr = bm + lrow;
    bool am_ok = gmr < M;
    const float* Ap  = A + (size_t)(am_ok ? gmr : 0) * K;
    const float* A2p = A2 ? A2 + (size_t)(am_ok ? gmr : 0) * K : nullptr;
    const float* Wp  = W + (size_t)(bn + lrow) * K;

    // smem store offsets (k-permuted): pos(k) = (k>>3)*8 + (k&3)*2 + ((k>>2)&1)
    int o0 = (q >> 1) * 8 + (q & 1);            // for k-quarter q
    int o1 = ((q + 4) >> 1) * 8 + (q & 1);      // for k-quarter q+4

    float4 a0r, a1r, w0r, w1r;

    auto gload = [&](int k0) {
        a0r = make_float4(0.f, 0.f, 0.f, 0.f);
        a1r = a0r;
        if (am_ok) {
            a0r = *(const float4*)(Ap + k0 + 4 * q);
            a1r = *(const float4*)(Ap + k0 + 16 + 4 * q);
            if (A2p) {
                float4 t0 = *(const float4*)(A2p + k0 + 4 * q);
                float4 t1 = *(const float4*)(A2p + k0 + 16 + 4 * q);
                a0r.x += t0.x; a0r.y += t0.y; a0r.z += t0.z; a0r.w += t0.w;
                a1r.x += t1.x; a1r.y += t1.y; a1r.z += t1.z; a1r.w += t1.w;
            }
        }
        w0r = *(const float4*)(Wp + k0 + 4 * q);
        w1r = *(const float4*)(Wp + k0 + 16 + 4 * q);
    };
    auto sstore = [&](int buf) {
        float* as = &As[buf][lrow * TST];
        as[o0 + 0] = __uint_as_float(f2tf(a0r.x));
        as[o0 + 2] = __uint_as_float(f2tf(a0r.y));
        as[o0 + 4] = __uint_as_float(f2tf(a0r.z));
        as[o0 + 6] = __uint_as_float(f2tf(a0r.w));
        as[o1 + 0] = __uint_as_float(f2tf(a1r.x));
        as[o1 + 2] = __uint_as_float(f2tf(a1r.y));
        as[o1 + 4] = __uint_as_float(f2tf(a1r.z));
        as[o1 + 6] = __uint_as_float(f2tf(a1r.w));
        float* ws = &Ws[buf][lrow * TST];
        ws[o0 + 0] = __uint_as_float(f2tf(w0r.x));
        ws[o0 + 2] = __uint_as_float(f2tf(w0r.y));
        ws[o0 + 4] = __uint_as_float(f2tf(w0r.z));
        ws[o0 + 6] = __uint_as_float(f2tf(w0r.w));
        ws[o1 + 0] = __uint_as_float(f2tf(w1r.x));
        ws[o1 + 2] = __uint_as_float(f2tf(w1r.y));
        ws[o1 + 4] = __uint_as_float(f2tf(w1r.z));
        ws[o1 + 6] = __uint_as_float(f2tf(w1r.w));
    };

    gload(0);
    sstore(0);
    __syncthreads();

    float4 acc[4];
    acc[0] = make_float4(0.f, 0.f, 0.f, 0.f);
    acc[1] = acc[0]; acc[2] = acc[0]; acc[3] = acc[0];

    int T = K / BKt;
    for (int t = 0; t < T; t++) {
        int buf = t & 1;
        if (t + 1 < T) gload((t + 1) * BKt);

        const float* asb = &As[buf][0];
        const float* wsb = &Ws[buf][0];
        #pragma unroll
        for (int ks = 0; ks < 4; ks++) {
            int fo = ks * 8 + 2 * tig;
            float2 A0 = *(const float2*)&asb[(wm + g8) * TST + fo];
            float2 A1 = *(const float2*)&asb[(wm + g8 + 8) * TST + fo];
            uint32_t fa0 = __float_as_uint(A0.x);
            uint32_t fa1 = __float_as_uint(A1.x);
            uint32_t fa2 = __float_as_uint(A0.y);
            uint32_t fa3 = __float_as_uint(A1.y);
            #pragma unroll
            for (int j = 0; j < 4; j++) {
                float2 Bv = *(const float2*)&wsb[(wn + 8 * j + g8) * TST + fo];
                mma_tf32(acc[j], fa0, fa1, fa2, fa3,
                         __float_as_uint(Bv.x), __float_as_uint(Bv.y));
            }
        }

        if (t + 1 < T) {
            sstore(buf ^ 1);
            __syncthreads();
        }
    }

    // epilogue
    int r0 = bm + wm + g8;
    int r1 = r0 + 8;
    #pragma unroll
    for (int j = 0; j < 4; j++) {
        int gn = bn + wn + 8 * j + 2 * tig;
        float b0 = bias[gn], b1 = bias[gn + 1];
        float v00 = acc[j].x + b0, v01 = acc[j].y + b1;
        float v10 = acc[j].z + b0, v11 = acc[j].w + b1;
        if (relu) {
            v00 = fmaxf(v00, 0.f); v01 = fmaxf(v01, 0.f);
            v10 = fmaxf(v10, 0.f); v11 = fmaxf(v11, 0.f);
        }
        if (r0 < M) *(float2*)&C[(size_t)r0 * N + gn] = make_float2(v00, v01);
        if (r1 < M) *(float2*)&C[(size_t)r1 * N + gn] = make_float2(v10, v11);
    }
}

// ---------------- self-attention: per (b,h,z), N=300, DH=32 ----------------
__global__ void attn_kernel(AttnArgs a) {
    const float scale = 0.17677669529663687f; // 1/sqrt(32)
    int z = blockIdx.y;
    const float* __restrict__ qk = a.qk[z];
    const float* __restrict__ vh = a.vh[z];
    float* __restrict__ out = a.out[z];

    int bh = blockIdx.x;
    int b = bh >> 3, h = bh & 7;
    __shared__ float Ks[NQ * 33];
    __shared__ float Ps[6][304];

    int tid = threadIdx.x;
    int w = tid >> 5, lane = tid & 31;

    for (int i = tid; i < NQ * 32; i += 192) {
        int k = i >> 5, c = i & 31;
        Ks[k * 33 + c] = qk[(size_t)(b * NQ + k) * 512 + 256 + h * 32 + c];
    }
    __syncthreads();

    for (int q = w; q < NQ; q += 6) {
        float qreg = qk[(size_t)(b * NQ + q) * 512 + h * 32 + lane];
        float sj[10];
        float mx = -3.0e38f;
        #pragma unroll
        for (int j = 0; j < 10; j++) {
            int k = lane + 32 * j;
            int kk = (k < NQ) ? k : (NQ - 1);
            float acc = 0.f;
            #pragma unroll
            for (int c = 0; c < 32; c++)
                acc = fmaf(__shfl_sync(0xffffffffu, qreg, c), Ks[kk * 33 + c], acc);
            acc *= scale;
            sj[j] = (k < NQ) ? acc : -3.0e38f;
            mx = fmaxf(mx, sj[j]);
        }
        #pragma unroll
        for (int o = 16; o > 0; o >>= 1)
            mx = fmaxf(mx, __shfl_xor_sync(0xffffffffu, mx, o));
        float lsum = 0.f;
        float pj[10];
        #pragma unroll
        for (int j = 0; j < 10; j++) {
            int k = lane + 32 * j;
            pj[j] = (k < NQ) ? expf(sj[j] - mx) : 0.f;
            lsum += pj[j];
        }
        #pragma unroll
        for (int o = 16; o > 0; o >>= 1)
            lsum += __shfl_xor_sync(0xffffffffu, lsum, o);
        float inv = 1.f / lsum;
        #pragma unroll
        for (int j = 0; j < 10; j++) {
            int k = lane + 32 * j;
            if (k < NQ) Ps[w][k] = pj[j] * inv;
        }
        __syncwarp();
        float acc = 0.f;
        for (int k = 0; k < NQ; k++)
            acc = fmaf(Ps[w][k], vh[(size_t)(b * NQ + k) * D + h * 32 + lane], acc);
        out[(size_t)(b * NQ + q) * D + h * 32 + lane] = acc;
        __syncwarp();
    }
}

// ---------------- layernorm (optional residual), z-batched ----------------
__global__ void ln_kernel(LnArgs a) {
    int z = blockIdx.y;
    int row = blockIdx.x;
    int d = threadIdx.x;
    size_t base = (size_t)row * D;
    float v = a.x[z][base + d];
    if (a.r[z]) v += a.r[z][base + d];
    __shared__ float sh[D];
    sh[d] = v; __syncthreads();
    for (int o = 128; o > 0; o >>= 1) { if (d < o) sh[d] += sh[d + o]; __syncthreads(); }
    float mean = sh[0] * (1.f / D);
    __syncthreads();
    float dv = v - mean;
    sh[d] = dv * dv; __syncthreads();
    for (int o = 128; o > 0; o >>= 1) { if (d < o) sh[d] += sh[d + o]; __syncthreads(); }
    float var = sh[0] * (1.f / D);
    float rstd = rsqrtf(var + 1e-5f);
    a.y[z][base + d] = dv * rstd * a.g[z][d] + a.b[z][d];
}

// ---------------- softmax over last 16 ----------------
__global__ void softmax16_kernel(float* __restrict__ aw, int rows) {
    int rIdx = blockIdx.x * blockDim.x + threadIdx.x;
    if (rIdx >= rows) return;
    float* p = aw + (size_t)rIdx * 16;
    float m = -3.0e38f;
    float e[16];
    #pragma unroll
    for (int i = 0; i < 16; i++) m = fmaxf(m, p[i]);
    float s = 0.f;
    #pragma unroll
    for (int i = 0; i < 16; i++) { e[i] = expf(p[i] - m); s += e[i]; }
    float inv = 1.f / s;
    #pragma unroll
    for (int i = 0; i < 16; i++) p[i] = e[i] * inv;
}

// ---------------- deformable sampling in src space + fused head projection ----------------
__global__ __launch_bounds__(256)
void msdeform_kernel(MsdArgs ar) {
    const int Hs[4]  = {100, 50, 25, 13};
    const int Wls[4] = {134, 67, 34, 17};
    const int S0[4]  = {0, 13400, 16750, 17600};

    int z = blockIdx.y;
    const float* __restrict__ src = ar.src[z];
    const float* __restrict__ off = ar.off[z];
    const float* __restrict__ aw  = ar.aw[z];
    const float* __restrict__ ref = ar.ref[z];
    const float* __restrict__ valwT = ar.wT[z];
    const float* __restrict__ valb  = ar.vb[z];
    float* __restrict__ samp = ar.samp[z];

    __shared__ float sh_s[QB][NH][256];
    __shared__ float sh_ws[QB][NH];

    int h = threadIdx.x >> 5, lane = threadIdx.x & 31;
    int bq0 = blockIdx.x * QB;
    int b = bq0 / NQ;

    for (int qq = 0; qq < QB; qq++) {
        int bq = bq0 + qq;
        const float* offp = off + (size_t)bq * 256 + h * 32;
        const float* awp  = aw  + (size_t)bq * 128 + h * 16;
        const float* refp = ref + (size_t)bq * (NL * 2);

        float acc[8] = {};
        float wsum = 0.f;

        #pragma unroll
        for (int l = 0; l < 4; l++) {
            float rx = refp[l * 2 + 0];
            float ry = refp[l * 2 + 1];
            int Wl = Wls[l], Hl = Hs[l];
            float Wf = (float)Wl, Hf = (float)Hl;
            int rowbase = b * LTOT + S0[l];
            #pragma unroll
            for (int p = 0; p < 4; p++) {
                float ox = offp[(l * 4 + p) * 2 + 0];
                float oy = offp[(l * 4 + p) * 2 + 1];
                float a  = awp[l * 4 + p];
                float x = fmaf(rx, Wf, ox) - 0.5f;
                float y = fmaf(ry, Hf, oy) - 0.5f;
                float x0f = floorf(x), y0f = floorf(y);
                int x0 = (int)x0f, y0 = (int)y0f;
                float wx = x - x0f, wy = y - y0f;
                float tw[4] = {(1.f - wx) * (1.f - wy) * a, wx * (1.f - wy) * a,
                               (1.f - wx) * wy * a,          wx * wy * a};
                int xs[4] = {x0, x0 + 1, x0,     x0 + 1};
                int ys[4] = {y0, y0,     y0 + 1, y0 + 1};
                #pragma unroll
                for (int t = 0; t < 4; t++) {
                    int xi = xs[t], yi = ys[t];
                    if (xi < 0 || xi >= Wl || yi < 0 || yi >= Hl) continue;
                    const float4* pr = (const float4*)(src + ((size_t)rowbase + (size_t)yi * Wl + xi) * 256);
                    float w = tw[t];
                    float4 v0 = __ldg(pr + lane);
                    float4 v1 = __ldg(pr + 32 + lane);
                    acc[0] = fmaf(w, v0.x, acc[0]);
                    acc[1] = fmaf(w, v0.y, acc[1]);
                    acc[2] = fmaf(w, v0.z, acc[2]);
                    acc[3] = fmaf(w, v0.w, acc[3]);
                    acc[4] = fmaf(w, v1.x, acc[4]);
                    acc[5] = fmaf(w, v1.y, acc[5]);
                    acc[6] = fmaf(w, v1.z, acc[6]);
                    acc[7] = fmaf(w, v1.w, acc[7]);
                    wsum += w;
                }
            }
        }
        float4* sp = (float4*)&sh_s[qq][h][0];
        sp[lane]      = make_float4(acc[0], acc[1], acc[2], acc[3]);
        sp[32 + lane] = make_float4(acc[4], acc[5], acc[6], acc[7]);
        if (lane == 0) sh_ws[qq][h] = wsum;
    }
    __syncthreads();

    int n = threadIdx.x;
    int h2 = n >> 5;
    float t0 = 0.f, t1 = 0.f, t2 = 0.f, t3 = 0.f;
    #pragma unroll 4
    for (int c = 0; c < 256; c++) {
        float w = __ldg(valwT + (size_t)c * 256 + n);
        t0 = fmaf(sh_s[0][h2][c], w, t0);
        t1 = fmaf(sh_s[1][h2][c], w, t1);
        t2 = fmaf(sh_s[2][h2][c], w, t2);
        t3 = fmaf(sh_s[3][h2][c], w, t3);
    }
    float vb = valb[n];
    samp[(size_t)(bq0 + 0) * 256 + n] = t0 + sh_ws[0][h2] * vb;
    samp[(size_t)(bq0 + 1) * 256 + n] = t1 + sh_ws[1][h2] * vb;
    samp[(size_t)(bq0 + 2) * 256 + n] = t2 + sh_ws[2][h2] * vb;
    samp[(size_t)(bq0 + 3) * 256 + n] = t3 + sh_ws[3][h2] * vb;
}

// ---------------- host side ----------------
static void gemm2(GPtrs& g, int M, int N, int K, int relu) {
    dim3 grid(N / BNt, (M + BMt - 1) / BMt, 2);
    tgemm_kernel<<<grid, 256>>>(g, M, N, K, relu);
}

extern "C" void kernel_launch(void* const* d_in, const int* in_sizes, int n_in,
                              void* d_out_v, int out_size) {
    const float* tgt[2] = {(const float*)d_in[0], (const float*)d_in[1]};
    const float* pos[2] = {(const float*)d_in[2], (const float*)d_in[3]};
    const float* refp[2] = {(const float*)d_in[4], (const float*)d_in[5]};
    const float* src[2] = {(const float*)d_in[6], (const float*)d_in[7]};
    const float* sa_in_w  = (const float*)d_in[8];
    const float* sa_in_b  = (const float*)d_in[9];
    const float* sa_out_w = (const float*)d_in[10];
    const float* sa_out_b = (const float*)d_in[11];
    const float* ln_w     = (const float*)d_in[12];
    const float* ln_b     = (const float*)d_in[13];
    const float* ffn_w1   = (const float*)d_in[14];
    const float* ffn_b1   = (const float*)d_in[15];
    const float* ffn_w2   = (const float*)d_in[16];
    const float* ffn_b2   = (const float*)d_in[17];
    const float* val_w    = (const float*)d_in[18];
    const float* val_b    = (const float*)d_in[19];
    const float* off_w    = (const float*)d_in[20];
    const float* off_b    = (const float*)d_in[21];
    const float* aw_w     = (const float*)d_in[22];
    const float* aw_b     = (const float*)d_in[23];
    const float* cout_w   = (const float*)d_in[24];
    const float* cout_b   = (const float*)d_in[25];
    float* out = (float*)d_out_v;

    float *p_qk, *p_vh, *p_attn, *p_sa, *p_tgt2, *p_off, *p_aw,
          *p_samp, *p_ffn, *p_y, *p_x, *p_r, *p_t, *p_wT;
    cudaGetSymbolAddress((void**)&p_qk,   g_qk);
    cudaGetSymbolAddress((void**)&p_vh,   g_vh);
    cudaGetSymbolAddress((void**)&p_attn, g_attn);
    cudaGetSymbolAddress((void**)&p_sa,   g_sa);
    cudaGetSymbolAddress((void**)&p_tgt2, g_tgt2);
    cudaGetSymbolAddress((void**)&p_off,  g_off);
    cudaGetSymbolAddress((void**)&p_aw,   g_aw);
    cudaGetSymbolAddress((void**)&p_samp, g_samp);
    cudaGetSymbolAddress((void**)&p_ffn,  g_ffn);
    cudaGetSymbolAddress((void**)&p_y,    g_y);
    cudaGetSymbolAddress((void**)&p_x,    g_x);
    cudaGetSymbolAddress((void**)&p_r,    g_r);
    cudaGetSymbolAddress((void**)&p_t,    g_t);
    cudaGetSymbolAddress((void**)&p_wT,   g_wT);

    const int GRID_E = (NE + 255) / 256;

    // ---- q|k projection (both modalities), A = tgt+pos
    {
        GPtrs g = {{tgt[0], tgt[1]}, {pos[0], pos[1]},
                   {sa_in_w, sa_in_w + (size_t)3 * D * D},
                   {sa_in_b, sa_in_b + 3 * D},
                   {p_qk, p_qk + (size_t)BNQ * 512}};
        gemm2(g, BNQ, 512, D, 0);
    }
    // ---- v projection, A = tgt
    {
        GPtrs g = {{tgt[0], tgt[1]}, {nullptr, nullptr},
                   {sa_in_w + (size_t)2 * D * D, sa_in_w + (size_t)5 * D * D},
                   {sa_in_b + 2 * D, sa_in_b + 5 * D},
                   {p_vh, p_vh + NE}};
        gemm2(g, BNQ, D, D, 0);
    }
    // ---- attention
    {
        AttnArgs a = {{p_qk, p_qk + (size_t)BNQ * 512}, {p_vh, p_vh + NE}, {p_attn, p_attn + NE}};
        attn_kernel<<<dim3(BS * NH, 2), 192>>>(a);
    }
    // ---- out projection
    {
        GPtrs g = {{p_attn, p_attn + NE}, {nullptr, nullptr},
                   {sa_out_w, sa_out_w + (size_t)D * D},
                   {sa_out_b, sa_out_b + D},
                   {p_sa, p_sa + NE}};
        gemm2(g, BNQ, D, D, 0);
    }
    // ---- tgt2 = LN(tgt + sa)  (norm2)
    {
        LnArgs a = {{tgt[0], tgt[1]}, {p_sa, p_sa + NE},
                    {ln_w + 1 * D, ln_w + 4 * D}, {ln_b + 1 * D, ln_b + 4 * D},
                    {p_tgt2, p_tgt2 + NE}};
        ln_kernel<<<dim3(BNQ, 2), 256>>>(a);
    }
    // ---- offsets and attention weights from (tgt2 + pos)
    {
        GPtrs g = {{p_tgt2, p_tgt2 + NE}, {pos[0], pos[1]},
                   {off_w, off_w + (size_t)D * D},
                   {off_b, off_b + 256},
                   {p_off, p_off + NE}};
        gemm2(g, BNQ, 256, D, 0);
    }
    {
        GPtrs g = {{p_tgt2, p_tgt2 + NE}, {pos[0], pos[1]},
                   {aw_w, aw_w + (size_t)128 * D},
                   {aw_b, aw_b + 128},
                   {p_aw, p_aw + (size_t)BNQ * 128}};
        gemm2(g, BNQ, 128, D, 0);
    }
    softmax16_kernel<<<(2 * BNQ * NH + 255) / 256, 256>>>(p_aw, 2 * BNQ * NH);

    // ---- val_w transpose + sampling (note: modality m samples src[1-m])
    transpose256_kernel<<<dim3(8, 8, 2), dim3(32, 8)>>>(val_w, p_wT);
    {
        MsdArgs a = {{src[1], src[0]},
                     {p_off, p_off + NE},
                     {p_aw, p_aw + (size_t)BNQ * 128},
                     {refp[0], refp[1]},
                     {p_wT, p_wT + (size_t)D * D},
                     {val_b, val_b + D},
                     {p_samp, p_samp + NE}};
        msdeform_kernel<<<dim3(BNQ / QB, 2), 256>>>(a);
    }
    // ---- cout projection -> output regions F_RGB / F_T
    {
        GPtrs g = {{p_samp, p_samp + NE}, {nullptr, nullptr},
                   {cout_w, cout_w + (size_t)D * D},
                   {cout_b, cout_b + D},
                   {out + (size_t)2 * NE, out + (size_t)3 * NE}};
        gemm2(g, BNQ, D, D, 0);
    }

    // ---- cross residuals: r = tgt2_T + t2_RGB ; t = r + t2_T
    cross_res_kernel<<<GRID_E, 256>>>(p_tgt2 + NE, out + (size_t)2 * NE, out + (size_t)3 * NE,
                                      p_r, p_t, NE);
    {
        LnArgs a = {{p_r, p_t}, {nullptr, nullptr},
                    {ln_w + 0 * D, ln_w + 3 * D}, {ln_b + 0 * D, ln_b + 3 * D},
                    {p_x, p_x + NE}};
        ln_kernel<<<dim3(BNQ, 2), 256>>>(a);
    }

    // ---- FFNs
    {
        GPtrs g = {{p_x, p_x + NE}, {nullptr, nullptr},
                   {ffn_w1, ffn_w1 + (size_t)DFF * D},
                   {ffn_b1, ffn_b1 + DFF},
                   {p_ffn, p_ffn + (size_t)BNQ * DFF}};
        gemm2(g, BNQ, DFF, D, 1);
    }
    {
        GPtrs g = {{p_ffn, p_ffn + (size_t)BNQ * DFF}, {nullptr, nullptr},
                   {ffn_w2, ffn_w2 + (size_t)D * DFF},
                   {ffn_b2, ffn_b2 + D},
                   {p_y, p_y + NE}};
        gemm2(g, BNQ, D, DFF, 0);
    }
    {
        LnArgs a = {{p_x, p_x + NE}, {p_y, p_y + NE},
                    {ln_w + 2 * D, ln_w + 5 * D}, {ln_b + 2 * D, ln_b + 5 * D},
                    {out, out + NE}};
        ln_kernel<<<dim3(BNQ, 2), 256>>>(a);
    }
}

// round 6
// speedup vs baseline: 2.8025x; 1.1224x over previous
#include <cuda_runtime.h>
#include <cuda_bf16.h>
#include <math.h>
#include <stdint.h>

// ---------------- problem constants ----------------
#define BS   4
#define NQ   300
#define D    256
#define NH   8
#define DH   32
#define NL   4
#define NP   4
#define DFF  1024
#define LTOT 17821
#define BNQ  (BS*NQ)          // 1200
#define QB   4                // queries per msdeform block
#define NE   (BNQ*D)          // 307200

// ---------------- scratch (device globals; no allocation allowed) ----------------
__device__ float g_qkv [2][BNQ*768];
__device__ float g_attn[2][BNQ*D];
__device__ float g_sa  [2][BNQ*D];
__device__ float g_tgt2[2][BNQ*D];
__device__ float g_off [2][BNQ*D];
__device__ float g_aw  [2*BNQ*(NH*NL*NP)];
__device__ float g_samp[2][BNQ*D];
__device__ float g_ffn [2][BNQ*DFF];
__device__ float g_y   [2][BNQ*D];
__device__ float g_x   [2][BNQ*D];
__device__ float g_r   [BNQ*D];
__device__ float g_t   [BNQ*D];
__device__ float g_wT  [2][D*D];

// ---------------- pointer-pack structs (passed by value) ----------------
struct GPtrs {
    const float* A[2];
    const float* A2[2];     // optional addend (A rows), used when bn < a2lim
    const float* W[2];      // primary weight  [N1, K]
    const float* W2[2];     // secondary weight [N2, K] (for column-split)
    const float* Bi[2];     // primary bias
    const float* Bi2[2];    // secondary bias
    float*       C[2];      // primary output, row stride N1
    float*       C2[2];     // secondary output, row stride N2
    int N1, N2, a2lim;
};
struct LnArgs {
    const float* x[2];
    const float* r[2];
    const float* g[2];
    const float* b[2];
    float*       y[2];
};
struct AttnArgs {
    const float* qkv[2];
    float*       out[2];
};
struct MsdArgs {
    const float* src[2];
    const float* off[2];
    const float* aw[2];
    const float* ref[2];
    const float* wT[2];
    const float* vb[2];
    float*       samp[2];
};

// ---------------- fused cross residual ----------------
__global__ void cross_res_kernel(const float* __restrict__ tgt2T, const float* __restrict__ t2R,
                                 const float* __restrict__ t2T,
                                 float* __restrict__ r, float* __restrict__ t, int n) {
    int i = blockIdx.x * blockDim.x + threadIdx.x;
    if (i < n) {
        float rv = tgt2T[i] + t2R[i];
        r[i] = rv;
        t[i] = rv + t2T[i];
    }
}

// ---------------- weight transpose 256x256, z-batched ----------------
__global__ void transpose256_kernel(const float* __restrict__ w, float* __restrict__ wT) {
    __shared__ float tile[32][33];
    int z = blockIdx.z;
    const float* ws = w + (size_t)z * D * D;
    float* wd = wT + (size_t)z * D * D;
    int bx = blockIdx.x * 32, by = blockIdx.y * 32;
    int tx = threadIdx.x, ty = threadIdx.y;
    #pragma unroll
    for (int i = 0; i < 32; i += 8)
        tile[ty + i][tx] = ws[(size_t)(by + ty + i) * D + bx + tx];
    __syncthreads();
    #pragma unroll
    for (int i = 0; i < 32; i += 8)
        wd[(size_t)(bx + ty + i) * D + by + tx] = tile[tx][ty + i];
}

// ---------------- tf32x3 tensor-core GEMM, z-batched, column-split capable ----------------
// C[M,N] = (A (+A2))[M,K] @ [W|W2][N,K]^T + bias (+relu), fp32-accurate via hi/lo split.
#define BMt 32
#define BNt 64
#define BKt 32
#define TST 36   // padded row stride (floats)

#define ASZ (BMt * TST)          // per-buffer A tile floats
#define WSZ (BNt * TST)          // per-buffer W tile floats
#define SMEM_FLOATS (2*ASZ + 2*ASZ + 2*WSZ + 2*WSZ)  // AsH,AsL,WsH,WsL x 2 bufs
#define SMEM_BYTES  (SMEM_FLOATS * 4)                // 55296

__device__ __forceinline__ uint32_t f2tf(float f) {
    uint32_t u;
    asm("cvt.rna.tf32.f32 %0, %1;" : "=r"(u) : "f"(f));
    return u;
}

__device__ __forceinline__ void mma_tf32(float4& d, const uint32_t a0, const uint32_t a1,
                                         const uint32_t a2, const uint32_t a3,
                                         const uint32_t b0, const uint32_t b1) {
    asm volatile(
        "mma.sync.aligned.m16n8k8.row.col.f32.tf32.tf32.f32 "
        "{%0,%1,%2,%3}, {%4,%5,%6,%7}, {%8,%9}, {%0,%1,%2,%3};\n"
        : "+f"(d.x), "+f"(d.y), "+f"(d.z), "+f"(d.w)
        : "r"(a0), "r"(a1), "r"(a2), "r"(a3), "r"(b0), "r"(b1));
}

__global__ __launch_bounds__(256)
void tgemm_kernel(GPtrs g, int M, int K, int relu) {
    extern __shared__ float sm[];
    float* AsH = sm;                    // [2][ASZ]
    float* AsL = AsH + 2 * ASZ;         // [2][ASZ]
    float* WsH = AsL + 2 * ASZ;         // [2][WSZ]
    float* WsL = WsH + 2 * WSZ;         // [2][WSZ]

    int z = blockIdx.z;
    int bm = blockIdx.y * BMt, bn = blockIdx.x * BNt;

    const float* __restrict__ A  = g.A[z];
    const float* __restrict__ A2 = (bn < g.a2lim) ? g.A2[z] : nullptr;
    const float* __restrict__ W;
    const float* __restrict__ bias;
    float* __restrict__ C;
    int colbase, cstride;
    if (bn < g.N1) {
        W = g.W[z];  bias = g.Bi[z];  C = g.C[z];
        colbase = bn; cstride = g.N1;
    } else {
        W = g.W2[z]; bias = g.Bi2[z]; C = g.C2[z];
        colbase = bn - g.N1; cstride = g.N2;
    }

    int tid = threadIdx.x;
    int lane = tid & 31, warp = tid >> 5;
    int wm = (warp & 1) << 4;        // 0,16
    int wn = (warp >> 1) << 4;       // 0..48
    int g8 = lane >> 2, tig = lane & 3;

    // loader roles
    int q = tid & 3;
    int o0 = (q >> 1) * 8 + (q & 1);
    int o1 = ((q + 4) >> 1) * 8 + (q & 1);
    int lrowB = tid >> 2;                 // 0..63 (W rows)
    int lrowA = tid >> 2;                 // 0..31 valid when tid < 128
    bool aLoader = tid < 128;
    int gmr = bm + lrowA;
    bool am_ok = aLoader && gmr < M;
    const float* Ap  = A + (size_t)(am_ok ? gmr : 0) * K;
    const float* A2p = A2 ? A2 + (size_t)(am_ok ? gmr : 0) * K : nullptr;
    const float* Wp  = W + (size_t)(colbase + lrowB) * K;

    float4 a0r, a1r, w0r, w1r;

    auto gload = [&](int k0) {
        a0r = make_float4(0.f, 0.f, 0.f, 0.f);
        a1r = a0r;
        if (am_ok) {
            a0r = *(const float4*)(Ap + k0 + 4 * q);
            a1r = *(const float4*)(Ap + k0 + 16 + 4 * q);
            if (A2p) {
                float4 t0 = *(const float4*)(A2p + k0 + 4 * q);
                float4 t1 = *(const float4*)(A2p + k0 + 16 + 4 * q);
                a0r.x += t0.x; a0r.y += t0.y; a0r.z += t0.z; a0r.w += t0.w;
                a1r.x += t1.x; a1r.y += t1.y; a1r.z += t1.z; a1r.w += t1.w;
            }
        }
        w0r = *(const float4*)(Wp + k0 + 4 * q);
        w1r = *(const float4*)(Wp + k0 + 16 + 4 * q);
    };
    auto splitStore = [](float* __restrict__ H, float* __restrict__ L, int idx, float v) {
        uint32_t hi = f2tf(v);
        H[idx] = __uint_as_float(hi);
        L[idx] = __uint_as_float(f2tf(v - __uint_as_float(hi)));
    };
    auto sstore = [&](int buf) {
        if (aLoader) {
            float* ah = &AsH[buf * ASZ + lrowA * TST];
            float* al = &AsL[buf * ASZ + lrowA * TST];
            splitStore(ah, al, o0 + 0, a0r.x);
            splitStore(ah, al, o0 + 2, a0r.y);
            splitStore(ah, al, o0 + 4, a0r.z);
            splitStore(ah, al, o0 + 6, a0r.w);
            splitStore(ah, al, o1 + 0, a1r.x);
            splitStore(ah, al, o1 + 2, a1r.y);
            splitStore(ah, al, o1 + 4, a1r.z);
            splitStore(ah, al, o1 + 6, a1r.w);
        }
        float* wh = &WsH[buf * WSZ + lrowB * TST];
        float* wl = &WsL[buf * WSZ + lrowB * TST];
        splitStore(wh, wl, o0 + 0, w0r.x);
        splitStore(wh, wl, o0 + 2, w0r.y);
        splitStore(wh, wl, o0 + 4, w0r.z);
        splitStore(wh, wl, o0 + 6, w0r.w);
        splitStore(wh, wl, o1 + 0, w1r.x);
        splitStore(wh, wl, o1 + 2, w1r.y);
        splitStore(wh, wl, o1 + 4, w1r.z);
        splitStore(wh, wl, o1 + 6, w1r.w);
    };

    gload(0);
    sstore(0);
    __syncthreads();

    float4 accA[2], accB[2], accC[2];
    #pragma unroll
    for (int j = 0; j < 2; j++) {
        accA[j] = make_float4(0.f, 0.f, 0.f, 0.f);
        accB[j] = accA[j]; accC[j] = accA[j];
    }

    int T = K / BKt;
    for (int t = 0; t < T; t++) {
        int buf = t & 1;
        if (t + 1 < T) gload((t + 1) * BKt);

        const float* ah = &AsH[buf * ASZ];
        const float* al = &AsL[buf * ASZ];
        const float* wh = &WsH[buf * WSZ];
        const float* wl = &WsL[buf * WSZ];
        #pragma unroll
        for (int ks = 0; ks < 4; ks++) {
            int fo = ks * 8 + 2 * tig;
            int ra = (wm + g8) * TST + fo;
            int rb = (wm + g8 + 8) * TST + fo;
            float2 AH0 = *(const float2*)&ah[ra];
            float2 AH1 = *(const float2*)&ah[rb];
            float2 AL0 = *(const float2*)&al[ra];
            float2 AL1 = *(const float2*)&al[rb];
            uint32_t h0 = __float_as_uint(AH0.x), h1 = __float_as_uint(AH1.x);
            uint32_t h2 = __float_as_uint(AH0.y), h3 = __float_as_uint(AH1.y);
            uint32_t l0 = __float_as_uint(AL0.x), l1 = __float_as_uint(AL1.x);
            uint32_t l2 = __float_as_uint(AL0.y), l3 = __float_as_uint(AL1.y);
            #pragma unroll
            for (int j = 0; j < 2; j++) {
                int rw = (wn + 8 * j + g8) * TST + fo;
                float2 BH = *(const float2*)&wh[rw];
                float2 BL = *(const float2*)&wl[rw];
                uint32_t bh0 = __float_as_uint(BH.x), bh1 = __float_as_uint(BH.y);
                uint32_t bl0 = __float_as_uint(BL.x), bl1 = __float_as_uint(BL.y);
                mma_tf32(accA[j], h0, h1, h2, h3, bh0, bh1);
                mma_tf32(accB[j], h0, h1, h2, h3, bl0, bl1);
                mma_tf32(accC[j], l0, l1, l2, l3, bh0, bh1);
            }
        }

        if (t + 1 < T) {
            sstore(buf ^ 1);
            __syncthreads();
        }
    }

    // epilogue
    int r0 = bm + wm + g8;
    int r1 = r0 + 8;
    #pragma unroll
    for (int j = 0; j < 2; j++) {
        int cl = colbase + wn + 8 * j + 2 * tig;
        float b0 = bias[cl], b1 = bias[cl + 1];
        float v00 = accA[j].x + accB[j].x + accC[j].x + b0;
        float v01 = accA[j].y + accB[j].y + accC[j].y + b1;
        float v10 = accA[j].z + accB[j].z + accC[j].z + b0;
        float v11 = accA[j].w + accB[j].w + accC[j].w + b1;
        if (relu) {
            v00 = fmaxf(v00, 0.f); v01 = fmaxf(v01, 0.f);
            v10 = fmaxf(v10, 0.f); v11 = fmaxf(v11, 0.f);
        }
        if (r0 < M) *(float2*)&C[(size_t)r0 * cstride + cl] = make_float2(v00, v01);
        if (r1 < M) *(float2*)&C[(size_t)r1 * cstride + cl] = make_float2(v10, v11);
    }
}

// ---------------- self-attention: per (b,h,z,qchunk), N=300, DH=32 ----------------
// qkv layout: row stride 768; q at +0, k at +256, v at +512.
__global__ void attn_kernel(AttnArgs a) {
    const float scale = 0.17677669529663687f; // 1/sqrt(32)
    int z = blockIdx.y;
    const float* __restrict__ qkv = a.qkv[z];
    float* __restrict__ out = a.out[z];

    int bh = blockIdx.x;
    int b = bh >> 3, h = bh & 7;
    int qbase = blockIdx.z * 60;
    __shared__ float Ks[NQ * 33];
    __shared__ float Ps[6][304];

    int tid = threadIdx.x;
    int w = tid >> 5, lane = tid & 31;

    for (int i = tid; i < NQ * 32; i += 192) {
        int k = i >> 5, c = i & 31;
        Ks[k * 33 + c] = qkv[(size_t)(b * NQ + k) * 768 + 256 + h * 32 + c];
    }
    __syncthreads();

    for (int q = qbase + w; q < qbase + 60; q += 6) {
        float qreg = qkv[(size_t)(b * NQ + q) * 768 + h * 32 + lane];
        float sj[10];
        float mx = -3.0e38f;
        #pragma unroll
        for (int j = 0; j < 10; j++) {
            int k = lane + 32 * j;
            int kk = (k < NQ) ? k : (NQ - 1);
            float acc = 0.f;
            #pragma unroll
            for (int c = 0; c < 32; c++)
                acc = fmaf(__shfl_sync(0xffffffffu, qreg, c), Ks[kk * 33 + c], acc);
            acc *= scale;
            sj[j] = (k < NQ) ? acc : -3.0e38f;
            mx = fmaxf(mx, sj[j]);
        }
        #pragma unroll
        for (int o = 16; o > 0; o >>= 1)
            mx = fmaxf(mx, __shfl_xor_sync(0xffffffffu, mx, o));
        float lsum = 0.f;
        float pj[10];
        #pragma unroll
        for (int j = 0; j < 10; j++) {
            int k = lane + 32 * j;
            pj[j] = (k < NQ) ? expf(sj[j] - mx) : 0.f;
            lsum += pj[j];
        }
        #pragma unroll
        for (int o = 16; o > 0; o >>= 1)
            lsum += __shfl_xor_sync(0xffffffffu, lsum, o);
        float inv = 1.f / lsum;
        #pragma unroll
        for (int j = 0; j < 10; j++) {
            int k = lane + 32 * j;
            if (k < NQ) Ps[w][k] = pj[j] * inv;
        }
        __syncwarp();
        float acc = 0.f;
        for (int k = 0; k < NQ; k++)
            acc = fmaf(Ps[w][k], qkv[(size_t)(b * NQ + k) * 768 + 512 + h * 32 + lane], acc);
        out[(size_t)(b * NQ + q) * D + h * 32 + lane] = acc;
        __syncwarp();
    }
}

// ---------------- layernorm (optional residual), z-batched ----------------
__global__ void ln_kernel(LnArgs a) {
    int z = blockIdx.y;
    int row = blockIdx.x;
    int d = threadIdx.x;
    size_t base = (size_t)row * D;
    float v = a.x[z][base + d];
    if (a.r[z]) v += a.r[z][base + d];
    __shared__ float sh[D];
    sh[d] = v; __syncthreads();
    for (int o = 128; o > 0; o >>= 1) { if (d < o) sh[d] += sh[d + o]; __syncthreads(); }
    float mean = sh[0] * (1.f / D);
    __syncthreads();
    float dv = v - mean;
    sh[d] = dv * dv; __syncthreads();
    for (int o = 128; o > 0; o >>= 1) { if (d < o) sh[d] += sh[d + o]; __syncthreads(); }
    float var = sh[0] * (1.f / D);
    float rstd = rsqrtf(var + 1e-5f);
    a.y[z][base + d] = dv * rstd * a.g[z][d] + a.b[z][d];
}

// ---------------- softmax over last 16 ----------------
__global__ void softmax16_kernel(float* __restrict__ aw, int rows) {
    int rIdx = blockIdx.x * blockDim.x + threadIdx.x;
    if (rIdx >= rows) return;
    float* p = aw + (size_t)rIdx * 16;
    float m = -3.0e38f;
    float e[16];
    #pragma unroll
    for (int i = 0; i < 16; i++) m = fmaxf(m, p[i]);
    float s = 0.f;
    #pragma unroll
    for (int i = 0; i < 16; i++) { e[i] = expf(p[i] - m); s += e[i]; }
    float inv = 1.f / s;
    #pragma unroll
    for (int i = 0; i < 16; i++) p[i] = e[i] * inv;
}

// ---------------- deformable sampling in src space + fused head projection ----------------
__global__ __launch_bounds__(256)
void msdeform_kernel(MsdArgs ar) {
    const int Hs[4]  = {100, 50, 25, 13};
    const int Wls[4] = {134, 67, 34, 17};
    const int S0[4]  = {0, 13400, 16750, 17600};

    int z = blockIdx.y;
    const float* __restrict__ src = ar.src[z];
    const float* __restrict__ off = ar.off[z];
    const float* __restrict__ aw  = ar.aw[z];
    const float* __restrict__ ref = ar.ref[z];
    const float* __restrict__ valwT = ar.wT[z];
    const float* __restrict__ valb  = ar.vb[z];
    float* __restrict__ samp = ar.samp[z];

    __shared__ float sh_s[QB][NH][256];
    __shared__ float sh_ws[QB][NH];

    int h = threadIdx.x >> 5, lane = threadIdx.x & 31;
    int bq0 = blockIdx.x * QB;
    int b = bq0 / NQ;

    for (int qq = 0; qq < QB; qq++) {
        int bq = bq0 + qq;
        const float* offp = off + (size_t)bq * 256 + h * 32;
        const float* awp  = aw  + (size_t)bq * 128 + h * 16;
        const float* refp = ref + (size_t)bq * (NL * 2);

        float acc[8] = {};
        float wsum = 0.f;

        #pragma unroll
        for (int l = 0; l < 4; l++) {
            float rx = refp[l * 2 + 0];
            float ry = refp[l * 2 + 1];
            int Wl = Wls[l], Hl = Hs[l];
            float Wf = (float)Wl, Hf = (float)Hl;
            int rowbase = b * LTOT + S0[l];
            #pragma unroll
            for (int p = 0; p < 4; p++) {
                float ox = offp[(l * 4 + p) * 2 + 0];
                float oy = offp[(l * 4 + p) * 2 + 1];
                float a  = awp[l * 4 + p];
                float x = fmaf(rx, Wf, ox) - 0.5f;
                float y = fmaf(ry, Hf, oy) - 0.5f;
                float x0f = floorf(x), y0f = floorf(y);
                int x0 = (int)x0f, y0 = (int)y0f;
                float wx = x - x0f, wy = y - y0f;
                float tw[4] = {(1.f - wx) * (1.f - wy) * a, wx * (1.f - wy) * a,
                               (1.f - wx) * wy * a,          wx * wy * a};
                int xs[4] = {x0, x0 + 1, x0,     x0 + 1};
                int ys[4] = {y0, y0,     y0 + 1, y0 + 1};
                #pragma unroll
                for (int t = 0; t < 4; t++) {
                    int xi = xs[t], yi = ys[t];
                    if (xi < 0 || xi >= Wl || yi < 0 || yi >= Hl) continue;
                    const float4* pr = (const float4*)(src + ((size_t)rowbase + (size_t)yi * Wl + xi) * 256);
                    float w = tw[t];
                    float4 v0 = __ldg(pr + lane);
                    float4 v1 = __ldg(pr + 32 + lane);
                    acc[0] = fmaf(w, v0.x, acc[0]);
                    acc[1] = fmaf(w, v0.y, acc[1]);
                    acc[2] = fmaf(w, v0.z, acc[2]);
                    acc[3] = fmaf(w, v0.w, acc[3]);
                    acc[4] = fmaf(w, v1.x, acc[4]);
                    acc[5] = fmaf(w, v1.y, acc[5]);
                    acc[6] = fmaf(w, v1.z, acc[6]);
                    acc[7] = fmaf(w, v1.w, acc[7]);
                    wsum += w;
                }
            }
        }
        float4* sp = (float4*)&sh_s[qq][h][0];
        sp[lane]      = make_float4(acc[0], acc[1], acc[2], acc[3]);
        sp[32 + lane] = make_float4(acc[4], acc[5], acc[6], acc[7]);
        if (lane == 0) sh_ws[qq][h] = wsum;
    }
    __syncthreads();

    int n = threadIdx.x;
    int h2 = n >> 5;
    float t0 = 0.f, t1 = 0.f, t2 = 0.f, t3 = 0.f;
    #pragma unroll 4
    for (int c = 0; c < 256; c++) {
        float w = __ldg(valwT + (size_t)c * 256 + n);
        t0 = fmaf(sh_s[0][h2][c], w, t0);
        t1 = fmaf(sh_s[1][h2][c], w, t1);
        t2 = fmaf(sh_s[2][h2][c], w, t2);
        t3 = fmaf(sh_s[3][h2][c], w, t3);
    }
    float vb = valb[n];
    samp[(size_t)(bq0 + 0) * 256 + n] = t0 + sh_ws[0][h2] * vb;
    samp[(size_t)(bq0 + 1) * 256 + n] = t1 + sh_ws[1][h2] * vb;
    samp[(size_t)(bq0 + 2) * 256 + n] = t2 + sh_ws[2][h2] * vb;
    samp[(size_t)(bq0 + 3) * 256 + n] = t3 + sh_ws[3][h2] * vb;
}

// ---------------- host side ----------------
static void gemm2(GPtrs& g, int M, int K, int relu) {
    static bool attr_done = false;
    if (!attr_done) {
        cudaFuncSetAttribute(tgemm_kernel, cudaFuncAttributeMaxDynamicSharedMemorySize,
                             SMEM_BYTES);
        attr_done = true;
    }
    int Ntot = g.N1 + g.N2;
    dim3 grid(Ntot / BNt, (M + BMt - 1) / BMt, 2);
    tgemm_kernel<<<grid, 256, SMEM_BYTES>>>(g, M, K, relu);
}

extern "C" void kernel_launch(void* const* d_in, const int* in_sizes, int n_in,
                              void* d_out_v, int out_size) {
    const float* tgt[2] = {(const float*)d_in[0], (const float*)d_in[1]};
    const float* pos[2] = {(const float*)d_in[2], (const float*)d_in[3]};
    const float* refp[2] = {(const float*)d_in[4], (const float*)d_in[5]};
    const float* src[2] = {(const float*)d_in[6], (const float*)d_in[7]};
    const float* sa_in_w  = (const float*)d_in[8];
    const float* sa_in_b  = (const float*)d_in[9];
    const float* sa_out_w = (const float*)d_in[10];
    const float* sa_out_b = (const float*)d_in[11];
    const float* ln_w     = (const float*)d_in[12];
    const float* ln_b     = (const float*)d_in[13];
    const float* ffn_w1   = (const float*)d_in[14];
    const float* ffn_b1   = (const float*)d_in[15];
    const float* ffn_w2   = (const float*)d_in[16];
    const float* ffn_b2   = (const float*)d_in[17];
    const float* val_w    = (const float*)d_in[18];
    const float* val_b    = (const float*)d_in[19];
    const float* off_w    = (const float*)d_in[20];
    const float* off_b    = (const float*)d_in[21];
    const float* aw_w     = (const float*)d_in[22];
    const float* aw_b     = (const float*)d_in[23];
    const float* cout_w   = (const float*)d_in[24];
    const float* cout_b   = (const float*)d_in[25];
    float* out = (float*)d_out_v;

    float *p_qkv, *p_attn, *p_sa, *p_tgt2, *p_off, *p_aw,
          *p_samp, *p_ffn, *p_y, *p_x, *p_r, *p_t, *p_wT;
    cudaGetSymbolAddress((void**)&p_qkv,  g_qkv);
    cudaGetSymbolAddress((void**)&p_attn, g_attn);
    cudaGetSymbolAddress((void**)&p_sa,   g_sa);
    cudaGetSymbolAddress((void**)&p_tgt2, g_tgt2);
    cudaGetSymbolAddress((void**)&p_off,  g_off);
    cudaGetSymbolAddress((void**)&p_aw,   g_aw);
    cudaGetSymbolAddress((void**)&p_samp, g_samp);
    cudaGetSymbolAddress((void**)&p_ffn,  g_ffn);
    cudaGetSymbolAddress((void**)&p_y,    g_y);
    cudaGetSymbolAddress((void**)&p_x,    g_x);
    cudaGetSymbolAddress((void**)&p_r,    g_r);
    cudaGetSymbolAddress((void**)&p_t,    g_t);
    cudaGetSymbolAddress((void**)&p_wT,   g_wT);

    const int GRID_E = (NE + 255) / 256;

    // ---- fused qkv projection: q,k use tgt+pos (cols <512), v uses tgt
    {
        GPtrs g = {};
        g.A[0] = tgt[0]; g.A[1] = tgt[1];
        g.A2[0] = pos[0]; g.A2[1] = pos[1];
        g.W[0] = sa_in_w; g.W[1] = sa_in_w + (size_t)3 * D * D;
        g.Bi[0] = sa_in_b; g.Bi[1] = sa_in_b + 3 * D;
        g.C[0] = p_qkv; g.C[1] = p_qkv + (size_t)BNQ * 768;
        g.N1 = 768; g.N2 = 0; g.a2lim = 512;
        gemm2(g, BNQ, D, 0);
    }
    // ---- attention (5 q-chunks)
    {
        AttnArgs a = {{p_qkv, p_qkv + (size_t)BNQ * 768}, {p_attn, p_attn + NE}};
        attn_kernel<<<dim3(BS * NH, 2, 5), 192>>>(a);
    }
    // ---- out projection
    {
        GPtrs g = {};
        g.A[0] = p_attn; g.A[1] = p_attn + NE;
        g.W[0] = sa_out_w; g.W[1] = sa_out_w + (size_t)D * D;
        g.Bi[0] = sa_out_b; g.Bi[1] = sa_out_b + D;
        g.C[0] = p_sa; g.C[1] = p_sa + NE;
        g.N1 = 256; g.N2 = 0; g.a2lim = 0;
        gemm2(g, BNQ, D, 0);
    }
    // ---- tgt2 = LN(tgt + sa)  (norm2)
    {
        LnArgs a = {{tgt[0], tgt[1]}, {p_sa, p_sa + NE},
                    {ln_w + 1 * D, ln_w + 4 * D}, {ln_b + 1 * D, ln_b + 4 * D},
                    {p_tgt2, p_tgt2 + NE}};
        ln_kernel<<<dim3(BNQ, 2), 256>>>(a);
    }
    // ---- fused offsets|aw projection from (tgt2 + pos)
    {
        GPtrs g = {};
        g.A[0] = p_tgt2; g.A[1] = p_tgt2 + NE;
        g.A2[0] = pos[0]; g.A2[1] = pos[1];
        g.W[0] = off_w; g.W[1] = off_w + (size_t)256 * D;
        g.W2[0] = aw_w; g.W2[1] = aw_w + (size_t)128 * D;
        g.Bi[0] = off_b; g.Bi[1] = off_b + 256;
        g.Bi2[0] = aw_b; g.Bi2[1] = aw_b + 128;
        g.C[0] = p_off; g.C[1] = p_off + NE;
        g.C2[0] = p_aw; g.C2[1] = p_aw + (size_t)BNQ * 128;
        g.N1 = 256; g.N2 = 128; g.a2lim = 384;
        gemm2(g, BNQ, D, 0);
    }
    softmax16_kernel<<<(2 * BNQ * NH + 255) / 256, 256>>>(p_aw, 2 * BNQ * NH);

    // ---- val_w transpose + sampling (modality m samples src[1-m])
    transpose256_kernel<<<dim3(8, 8, 2), dim3(32, 8)>>>(val_w, p_wT);
    {
        MsdArgs a = {{src[1], src[0]},
                     {p_off, p_off + NE},
                     {p_aw, p_aw + (size_t)BNQ * 128},
                     {refp[0], refp[1]},
                     {p_wT, p_wT + (size_t)D * D},
                     {val_b, val_b + D},
                     {p_samp, p_samp + NE}};
        msdeform_kernel<<<dim3(BNQ / QB, 2), 256>>>(a);
    }
    // ---- cout projection -> output regions F_RGB / F_T
    {
        GPtrs g = {};
        g.A[0] = p_samp; g.A[1] = p_samp + NE;
        g.W[0] = cout_w; g.W[1] = cout_w + (size_t)D * D;
        g.Bi[0] = cout_b; g.Bi[1] = cout_b + D;
        g.C[0] = out + (size_t)2 * NE; g.C[1] = out + (size_t)3 * NE;
        g.N1 = 256; g.N2 = 0; g.a2lim = 0;
        gemm2(g, BNQ, D, 0);
    }

    // ---- cross residuals: r = tgt2_T + t2_RGB ; t = r + t2_T
    cross_res_kernel<<<GRID_E, 256>>>(p_tgt2 + NE, out + (size_t)2 * NE, out + (size_t)3 * NE,
                                      p_r, p_t, NE);
    {
        LnArgs a = {{p_r, p_t}, {nullptr, nullptr},
                    {ln_w + 0 * D, ln_w + 3 * D}, {ln_b + 0 * D, ln_b + 3 * D},
                    {p_x, p_x + NE}};
        ln_kernel<<<dim3(BNQ, 2), 256>>>(a);
    }

    // ---- FFNs
    {
        GPtrs g = {};
        g.A[0] = p_x; g.A[1] = p_x + NE;
        g.W[0] = ffn_w1; g.W[1] = ffn_w1 + (size_t)DFF * D;
        g.Bi[0] = ffn_b1; g.Bi[1] = ffn_b1 + DFF;
        g.C[0] = p_ffn; g.C[1] = p_ffn + (size_t)BNQ * DFF;
        g.N1 = 1024; g.N2 = 0; g.a2lim = 0;
        gemm2(g, BNQ, D, 1);
    }
    {
        GPtrs g = {};
        g.A[0] = p_ffn; g.A[1] = p_ffn + (size_t)BNQ * DFF;
        g.W[0] = ffn_w2; g.W[1] = ffn_w2 + (size_t)D * DFF;
        g.Bi[0] = ffn_b2; g.Bi[1] = ffn_b2 + D;
        g.C[0] = p_y; g.C[1] = p_y + NE;
        g.N1 = 256; g.N2 = 0; g.a2lim = 0;
        gemm2(g, BNQ, DFF, 0);
    }
    {
        LnArgs a = {{p_x, p_x + NE}, {p_y, p_y + NE},
                    {ln_w + 2 * D, ln_w + 5 * D}, {ln_b + 2 * D, ln_b + 5 * D},
                    {out, out + NE}};
        ln_kernel<<<dim3(BNQ, 2), 256>>>(a);
    }
}

// round 7
// speedup vs baseline: 2.8604x; 1.0206x over previous
#include <cuda_runtime.h>
#include <cuda_bf16.h>
#include <math.h>
#include <stdint.h>

// ---------------- problem constants ----------------
#define BS   4
#define NQ   300
#define D    256
#define NH   8
#define DH   32
#define NL   4
#define NP   4
#define DFF  1024
#define LTOT 17821
#define BNQ  (BS*NQ)          // 1200
#define QB   4                // queries per msdeform block
#define NE   (BNQ*D)          // 307200

// ---------------- scratch (device globals; no allocation allowed) ----------------
__device__ float g_qkv [2][BNQ*768];
__device__ float g_attn[2][BNQ*D];
__device__ float g_sa  [2][BNQ*D];
__device__ float g_tgt2[2][BNQ*D];
__device__ float g_off [2][BNQ*D];
__device__ float g_aw  [2*BNQ*(NH*NL*NP)];
__device__ float g_samp[2][BNQ*D];
__device__ float g_ffn [2][BNQ*DFF];
__device__ float g_y   [2][BNQ*D];
__device__ float g_x   [2][BNQ*D];
__device__ float g_r   [BNQ*D];
__device__ float g_t   [BNQ*D];
__device__ float g_wT  [2][D*D];

// ---------------- pointer-pack structs (passed by value) ----------------
struct GPtrs {
    const float* A[2];
    const float* A2[2];     // optional addend (A rows), used when bn < a2lim
    const float* W[2];      // primary weight  [N1, K]
    const float* W2[2];     // secondary weight [N2, K] (for column-split)
    const float* Bi[2];     // primary bias
    const float* Bi2[2];    // secondary bias
    float*       C[2];      // primary output, row stride N1
    float*       C2[2];     // secondary output, row stride N2
    int N1, N2, a2lim;
};
struct LnArgs {
    const float* x[2];
    const float* r[2];
    const float* g[2];
    const float* b[2];
    float*       y[2];
};
struct AttnArgs {
    const float* qkv[2];
    float*       out[2];
};
struct MsdArgs {
    const float* src[2];
    const float* off[2];
    const float* aw[2];
    const float* ref[2];
    const float* wT[2];
    const float* vb[2];
    float*       samp[2];
};

// ---------------- fused cross residual ----------------
__global__ void cross_res_kernel(const float* __restrict__ tgt2T, const float* __restrict__ t2R,
                                 const float* __restrict__ t2T,
                                 float* __restrict__ r, float* __restrict__ t, int n) {
    int i = blockIdx.x * blockDim.x + threadIdx.x;
    if (i < n) {
        float rv = tgt2T[i] + t2R[i];
        r[i] = rv;
        t[i] = rv + t2T[i];
    }
}

// ---------------- weight transpose 256x256, z-batched ----------------
__global__ void transpose256_kernel(const float* __restrict__ w, float* __restrict__ wT) {
    __shared__ float tile[32][33];
    int z = blockIdx.z;
    const float* ws = w + (size_t)z * D * D;
    float* wd = wT + (size_t)z * D * D;
    int bx = blockIdx.x * 32, by = blockIdx.y * 32;
    int tx = threadIdx.x, ty = threadIdx.y;
    #pragma unroll
    for (int i = 0; i < 32; i += 8)
        tile[ty + i][tx] = ws[(size_t)(by + ty + i) * D + bx + tx];
    __syncthreads();
    #pragma unroll
    for (int i = 0; i < 32; i += 8)
        wd[(size_t)(bx + ty + i) * D + by + tx] = tile[tx][ty + i];
}

// ---------------- tf32x3 tensor-core GEMM, z-batched, column-split capable ----------------
// C[M,N] = (A (+A2))[M,K] @ [W|W2][N,K]^T + bias (+relu), fp32-accurate via hi/lo split.
#define BMt 32
#define BNt 64
#define BKt 32
#define TST 36   // padded row stride (floats)

#define ASZ (BMt * TST)
#define WSZ (BNt * TST)
#define SMEM_FLOATS (2*ASZ + 2*ASZ + 2*WSZ + 2*WSZ)
#define SMEM_BYTES  (SMEM_FLOATS * 4)                // 55296

__device__ __forceinline__ uint32_t f2tf(float f) {
    uint32_t u;
    asm("cvt.rna.tf32.f32 %0, %1;" : "=r"(u) : "f"(f));
    return u;
}

__device__ __forceinline__ void mma_tf32(float4& d, const uint32_t a0, const uint32_t a1,
                                         const uint32_t a2, const uint32_t a3,
                                         const uint32_t b0, const uint32_t b1) {
    asm volatile(
        "mma.sync.aligned.m16n8k8.row.col.f32.tf32.tf32.f32 "
        "{%0,%1,%2,%3}, {%4,%5,%6,%7}, {%8,%9}, {%0,%1,%2,%3};\n"
        : "+f"(d.x), "+f"(d.y), "+f"(d.z), "+f"(d.w)
        : "r"(a0), "r"(a1), "r"(a2), "r"(a3), "r"(b0), "r"(b1));
}

__global__ __launch_bounds__(256)
void tgemm_kernel(GPtrs g, int M, int K, int relu) {
    extern __shared__ float sm[];
    float* AsH = sm;
    float* AsL = AsH + 2 * ASZ;
    float* WsH = AsL + 2 * ASZ;
    float* WsL = WsH + 2 * WSZ;

    int z = blockIdx.z;
    int bm = blockIdx.y * BMt, bn = blockIdx.x * BNt;

    const float* __restrict__ A  = g.A[z];
    const float* __restrict__ A2 = (bn < g.a2lim) ? g.A2[z] : nullptr;
    const float* __restrict__ W;
    const float* __restrict__ bias;
    float* __restrict__ C;
    int colbase, cstride;
    if (bn < g.N1) {
        W = g.W[z];  bias = g.Bi[z];  C = g.C[z];
        colbase = bn; cstride = g.N1;
    } else {
        W = g.W2[z]; bias = g.Bi2[z]; C = g.C2[z];
        colbase = bn - g.N1; cstride = g.N2;
    }

    int tid = threadIdx.x;
    int lane = tid & 31, warp = tid >> 5;
    int wm = (warp & 1) << 4;
    int wn = (warp >> 1) << 4;
    int g8 = lane >> 2, tig = lane & 3;

    int q = tid & 3;
    int o0 = (q >> 1) * 8 + (q & 1);
    int o1 = ((q + 4) >> 1) * 8 + (q & 1);
    int lrowB = tid >> 2;
    int lrowA = tid >> 2;
    bool aLoader = tid < 128;
    int gmr = bm + lrowA;
    bool am_ok = aLoader && gmr < M;
    const float* Ap  = A + (size_t)(am_ok ? gmr : 0) * K;
    const float* A2p = A2 ? A2 + (size_t)(am_ok ? gmr : 0) * K : nullptr;
    const float* Wp  = W + (size_t)(colbase + lrowB) * K;

    float4 a0r, a1r, w0r, w1r;

    auto gload = [&](int k0) {
        a0r = make_float4(0.f, 0.f, 0.f, 0.f);
        a1r = a0r;
        if (am_ok) {
            a0r = *(const float4*)(Ap + k0 + 4 * q);
            a1r = *(const float4*)(Ap + k0 + 16 + 4 * q);
            if (A2p) {
                float4 t0 = *(const float4*)(A2p + k0 + 4 * q);
                float4 t1 = *(const float4*)(A2p + k0 + 16 + 4 * q);
                a0r.x += t0.x; a0r.y += t0.y; a0r.z += t0.z; a0r.w += t0.w;
                a1r.x += t1.x; a1r.y += t1.y; a1r.z += t1.z; a1r.w += t1.w;
            }
        }
        w0r = *(const float4*)(Wp + k0 + 4 * q);
        w1r = *(const float4*)(Wp + k0 + 16 + 4 * q);
    };
    auto splitStore = [](float* __restrict__ H, float* __restrict__ L, int idx, float v) {
        uint32_t hi = f2tf(v);
        H[idx] = __uint_as_float(hi);
        L[idx] = __uint_as_float(f2tf(v - __uint_as_float(hi)));
    };
    auto sstore = [&](int buf) {
        if (aLoader) {
            float* ah = &AsH[buf * ASZ + lrowA * TST];
            float* al = &AsL[buf * ASZ + lrowA * TST];
            splitStore(ah, al, o0 + 0, a0r.x);
            splitStore(ah, al, o0 + 2, a0r.y);
            splitStore(ah, al, o0 + 4, a0r.z);
            splitStore(ah, al, o0 + 6, a0r.w);
            splitStore(ah, al, o1 + 0, a1r.x);
            splitStore(ah, al, o1 + 2, a1r.y);
            splitStore(ah, al, o1 + 4, a1r.z);
            splitStore(ah, al, o1 + 6, a1r.w);
        }
        float* wh = &WsH[buf * WSZ + lrowB * TST];
        float* wl = &WsL[buf * WSZ + lrowB * TST];
        splitStore(wh, wl, o0 + 0, w0r.x);
        splitStore(wh, wl, o0 + 2, w0r.y);
        splitStore(wh, wl, o0 + 4, w0r.z);
        splitStore(wh, wl, o0 + 6, w0r.w);
        splitStore(wh, wl, o1 + 0, w1r.x);
        splitStore(wh, wl, o1 + 2, w1r.y);
        splitStore(wh, wl, o1 + 4, w1r.z);
        splitStore(wh, wl, o1 + 6, w1r.w);
    };

    gload(0);
    sstore(0);
    __syncthreads();

    float4 accA[2], accB[2], accC[2];
    #pragma unroll
    for (int j = 0; j < 2; j++) {
        accA[j] = make_float4(0.f, 0.f, 0.f, 0.f);
        accB[j] = accA[j]; accC[j] = accA[j];
    }

    int T = K / BKt;
    for (int t = 0; t < T; t++) {
        int buf = t & 1;
        if (t + 1 < T) gload((t + 1) * BKt);

        const float* ah = &AsH[buf * ASZ];
        const float* al = &AsL[buf * ASZ];
        const float* wh = &WsH[buf * WSZ];
        const float* wl = &WsL[buf * WSZ];
        #pragma unroll
        for (int ks = 0; ks < 4; ks++) {
            int fo = ks * 8 + 2 * tig;
            int ra = (wm + g8) * TST + fo;
            int rb = (wm + g8 + 8) * TST + fo;
            float2 AH0 = *(const float2*)&ah[ra];
            float2 AH1 = *(const float2*)&ah[rb];
            float2 AL0 = *(const float2*)&al[ra];
            float2 AL1 = *(const float2*)&al[rb];
            uint32_t h0 = __float_as_uint(AH0.x), h1 = __float_as_uint(AH1.x);
            uint32_t h2 = __float_as_uint(AH0.y), h3 = __float_as_uint(AH1.y);
            uint32_t l0 = __float_as_uint(AL0.x), l1 = __float_as_uint(AL1.x);
            uint32_t l2 = __float_as_uint(AL0.y), l3 = __float_as_uint(AL1.y);
            #pragma unroll
            for (int j = 0; j < 2; j++) {
                int rw = (wn + 8 * j + g8) * TST + fo;
                float2 BH = *(const float2*)&wh[rw];
                float2 BL = *(const float2*)&wl[rw];
                uint32_t bh0 = __float_as_uint(BH.x), bh1 = __float_as_uint(BH.y);
                uint32_t bl0 = __float_as_uint(BL.x), bl1 = __float_as_uint(BL.y);
                mma_tf32(accA[j], h0, h1, h2, h3, bh0, bh1);
                mma_tf32(accB[j], h0, h1, h2, h3, bl0, bl1);
                mma_tf32(accC[j], l0, l1, l2, l3, bh0, bh1);
            }
        }

        if (t + 1 < T) {
            sstore(buf ^ 1);
            __syncthreads();
        }
    }

    int r0 = bm + wm + g8;
    int r1 = r0 + 8;
    #pragma unroll
    for (int j = 0; j < 2; j++) {
        int cl = colbase + wn + 8 * j + 2 * tig;
        float b0 = bias[cl], b1 = bias[cl + 1];
        float v00 = accA[j].x + accB[j].x + accC[j].x + b0;
        float v01 = accA[j].y + accB[j].y + accC[j].y + b1;
        float v10 = accA[j].z + accB[j].z + accC[j].z + b0;
        float v11 = accA[j].w + accB[j].w + accC[j].w + b1;
        if (relu) {
            v00 = fmaxf(v00, 0.f); v01 = fmaxf(v01, 0.f);
            v10 = fmaxf(v10, 0.f); v11 = fmaxf(v11, 0.f);
        }
        if (r0 < M) *(float2*)&C[(size_t)r0 * cstride + cl] = make_float2(v00, v01);
        if (r1 < M) *(float2*)&C[(size_t)r1 * cstride + cl] = make_float2(v10, v11);
    }
}

// ---------------- self-attention: per (b,h,z,qchunk), N=300, DH=32 ----------------
__global__ void attn_kernel(AttnArgs a) {
    const float scale = 0.17677669529663687f; // 1/sqrt(32)
    int z = blockIdx.y;
    const float* __restrict__ qkv = a.qkv[z];
    float* __restrict__ out = a.out[z];

    int bh = blockIdx.x;
    int b = bh >> 3, h = bh & 7;
    int qbase = blockIdx.z * 60;
    __shared__ float Ks[NQ * 33];
    __shared__ float Ps[6][304];

    int tid = threadIdx.x;
    int w = tid >> 5, lane = tid & 31;

    for (int i = tid; i < NQ * 32; i += 192) {
        int k = i >> 5, c = i & 31;
        Ks[k * 33 + c] = qkv[(size_t)(b * NQ + k) * 768 + 256 + h * 32 + c];
    }
    __syncthreads();

    for (int q = qbase + w; q < qbase + 60; q += 6) {
        float qreg = qkv[(size_t)(b * NQ + q) * 768 + h * 32 + lane];
        float sj[10];
        float mx = -3.0e38f;
        #pragma unroll
        for (int j = 0; j < 10; j++) {
            int k = lane + 32 * j;
            int kk = (k < NQ) ? k : (NQ - 1);
            float acc = 0.f;
            #pragma unroll
            for (int c = 0; c < 32; c++)
                acc = fmaf(__shfl_sync(0xffffffffu, qreg, c), Ks[kk * 33 + c], acc);
            acc *= scale;
            sj[j] = (k < NQ) ? acc : -3.0e38f;
            mx = fmaxf(mx, sj[j]);
        }
        #pragma unroll
        for (int o = 16; o > 0; o >>= 1)
            mx = fmaxf(mx, __shfl_xor_sync(0xffffffffu, mx, o));
        float lsum = 0.f;
        float pj[10];
        #pragma unroll
        for (int j = 0; j < 10; j++) {
            int k = lane + 32 * j;
            pj[j] = (k < NQ) ? expf(sj[j] - mx) : 0.f;
            lsum += pj[j];
        }
        #pragma unroll
        for (int o = 16; o > 0; o >>= 1)
            lsum += __shfl_xor_sync(0xffffffffu, lsum, o);
        float inv = 1.f / lsum;
        #pragma unroll
        for (int j = 0; j < 10; j++) {
            int k = lane + 32 * j;
            if (k < NQ) Ps[w][k] = pj[j] * inv;
        }
        __syncwarp();
        float acc = 0.f;
        for (int k = 0; k < NQ; k++)
            acc = fmaf(Ps[w][k], qkv[(size_t)(b * NQ + k) * 768 + 512 + h * 32 + lane], acc);
        out[(size_t)(b * NQ + q) * D + h * 32 + lane] = acc;
        __syncwarp();
    }
}

// ---------------- layernorm: warp-per-row, barrier-free ----------------
__global__ __launch_bounds__(256)
void ln_kernel(LnArgs a) {
    int z = blockIdx.y;
    int w = threadIdx.x >> 5, lane = threadIdx.x & 31;
    int row = blockIdx.x * 8 + w;
    size_t base = (size_t)row * D;

    const float4* xp = (const float4*)(a.x[z] + base);
    float4 v0 = xp[lane];
    float4 v1 = xp[32 + lane];
    if (a.r[z]) {
        const float4* rp = (const float4*)(a.r[z] + base);
        float4 r0 = rp[lane], r1 = rp[32 + lane];
        v0.x += r0.x; v0.y += r0.y; v0.z += r0.z; v0.w += r0.w;
        v1.x += r1.x; v1.y += r1.y; v1.z += r1.z; v1.w += r1.w;
    }
    float s  = v0.x + v0.y + v0.z + v0.w + v1.x + v1.y + v1.z + v1.w;
    float s2 = v0.x*v0.x + v0.y*v0.y + v0.z*v0.z + v0.w*v0.w
             + v1.x*v1.x + v1.y*v1.y + v1.z*v1.z + v1.w*v1.w;
    #pragma unroll
    for (int o = 16; o > 0; o >>= 1) {
        s  += __shfl_xor_sync(0xffffffffu, s, o);
        s2 += __shfl_xor_sync(0xffffffffu, s2, o);
    }
    float mean = s * (1.f / D);
    float var = s2 * (1.f / D) - mean * mean;
    float rstd = rsqrtf(var + 1e-5f);

    const float4* gp = (const float4*)a.g[z];
    const float4* bp = (const float4*)a.b[z];
    float4 g0 = gp[lane], g1 = gp[32 + lane];
    float4 b0 = bp[lane], b1 = bp[32 + lane];
    float4 y0, y1;
    y0.x = (v0.x - mean) * rstd * g0.x + b0.x;
    y0.y = (v0.y - mean) * rstd * g0.y + b0.y;
    y0.z = (v0.z - mean) * rstd * g0.z + b0.z;
    y0.w = (v0.w - mean) * rstd * g0.w + b0.w;
    y1.x = (v1.x - mean) * rstd * g1.x + b1.x;
    y1.y = (v1.y - mean) * rstd * g1.y + b1.y;
    y1.z = (v1.z - mean) * rstd * g1.z + b1.z;
    y1.w = (v1.w - mean) * rstd * g1.w + b1.w;
    float4* yp = (float4*)(a.y[z] + base);
    yp[lane] = y0;
    yp[32 + lane] = y1;
}

// ---------------- softmax over last 16 ----------------
__global__ void softmax16_kernel(float* __restrict__ aw, int rows) {
    int rIdx = blockIdx.x * blockDim.x + threadIdx.x;
    if (rIdx >= rows) return;
    float* p = aw + (size_t)rIdx * 16;
    float m = -3.0e38f;
    float e[16];
    #pragma unroll
    for (int i = 0; i < 16; i++) m = fmaxf(m, p[i]);
    float s = 0.f;
    #pragma unroll
    for (int i = 0; i < 16; i++) { e[i] = expf(p[i] - m); s += e[i]; }
    float inv = 1.f / s;
    #pragma unroll
    for (int i = 0; i < 16; i++) p[i] = e[i] * inv;
}

// ---------------- deformable sampling + fused head projection (per modality) ----------------
__global__ __launch_bounds__(256)
void msdeform_kernel(MsdArgs ar, int z) {
    const int Hs[4]  = {100, 50, 25, 13};
    const int Wls[4] = {134, 67, 34, 17};
    const int S0[4]  = {0, 13400, 16750, 17600};

    const float* __restrict__ src = ar.src[z];
    const float* __restrict__ off = ar.off[z];
    const float* __restrict__ aw  = ar.aw[z];
    const float* __restrict__ ref = ar.ref[z];
    const float* __restrict__ valwT = ar.wT[z];
    const float* __restrict__ valb  = ar.vb[z];
    float* __restrict__ samp = ar.samp[z];

    __shared__ float sh_s[QB][NH][256];
    __shared__ float sh_ws[QB][NH];

    int h = threadIdx.x >> 5, lane = threadIdx.x & 31;
    int bq0 = blockIdx.x * QB;
    int b = bq0 / NQ;

    for (int qq = 0; qq < QB; qq++) {
        int bq = bq0 + qq;
        const float* offp = off + (size_t)bq * 256 + h * 32;
        const float* awp  = aw  + (size_t)bq * 128 + h * 16;
        const float* refp = ref + (size_t)bq * (NL * 2);

        float acc[8] = {};
        float wsum = 0.f;

        #pragma unroll
        for (int l = 0; l < 4; l++) {
            float rx = refp[l * 2 + 0];
            float ry = refp[l * 2 + 1];
            int Wl = Wls[l], Hl = Hs[l];
            float Wf = (float)Wl, Hf = (float)Hl;
            int rowbase = b * LTOT + S0[l];
            #pragma unroll
            for (int p = 0; p < 4; p++) {
                float ox = offp[(l * 4 + p) * 2 + 0];
                float oy = offp[(l * 4 + p) * 2 + 1];
                float a  = awp[l * 4 + p];
                float x = fmaf(rx, Wf, ox) - 0.5f;
                float y = fmaf(ry, Hf, oy) - 0.5f;
                float x0f = floorf(x), y0f = floorf(y);
                int x0 = (int)x0f, y0 = (int)y0f;
                float wx = x - x0f, wy = y - y0f;
                float tw[4] = {(1.f - wx) * (1.f - wy) * a, wx * (1.f - wy) * a,
                               (1.f - wx) * wy * a,          wx * wy * a};
                int xs[4] = {x0, x0 + 1, x0,     x0 + 1};
                int ys[4] = {y0, y0,     y0 + 1, y0 + 1};
                #pragma unroll
                for (int t = 0; t < 4; t++) {
                    int xi = xs[t], yi = ys[t];
                    if (xi < 0 || xi >= Wl || yi < 0 || yi >= Hl) continue;
                    const float4* pr = (const float4*)(src + ((size_t)rowbase + (size_t)yi * Wl + xi) * 256);
                    float w = tw[t];
                    float4 v0 = __ldg(pr + lane);
                    float4 v1 = __ldg(pr + 32 + lane);
                    acc[0] = fmaf(w, v0.x, acc[0]);
                    acc[1] = fmaf(w, v0.y, acc[1]);
                    acc[2] = fmaf(w, v0.z, acc[2]);
                    acc[3] = fmaf(w, v0.w, acc[3]);
                    acc[4] = fmaf(w, v1.x, acc[4]);
                    acc[5] = fmaf(w, v1.y, acc[5]);
                    acc[6] = fmaf(w, v1.z, acc[6]);
                    acc[7] = fmaf(w, v1.w, acc[7]);
                    wsum += w;
                }
            }
        }
        float4* sp = (float4*)&sh_s[qq][h][0];
        sp[lane]      = make_float4(acc[0], acc[1], acc[2], acc[3]);
        sp[32 + lane] = make_float4(acc[4], acc[5], acc[6], acc[7]);
        if (lane == 0) sh_ws[qq][h] = wsum;
    }
    __syncthreads();

    int n = threadIdx.x;
    int h2 = n >> 5;
    float t0 = 0.f, t1 = 0.f, t2 = 0.f, t3 = 0.f;
    #pragma unroll 4
    for (int c = 0; c < 256; c++) {
        float w = __ldg(valwT + (size_t)c * 256 + n);
        t0 = fmaf(sh_s[0][h2][c], w, t0);
        t1 = fmaf(sh_s[1][h2][c], w, t1);
        t2 = fmaf(sh_s[2][h2][c], w, t2);
        t3 = fmaf(sh_s[3][h2][c], w, t3);
    }
    float vb = valb[n];
    samp[(size_t)(bq0 + 0) * 256 + n] = t0 + sh_ws[0][h2] * vb;
    samp[(size_t)(bq0 + 1) * 256 + n] = t1 + sh_ws[1][h2] * vb;
    samp[(size_t)(bq0 + 2) * 256 + n] = t2 + sh_ws[2][h2] * vb;
    samp[(size_t)(bq0 + 3) * 256 + n] = t3 + sh_ws[3][h2] * vb;
}

// ---------------- host side ----------------
static void gemm2(GPtrs& g, int M, int K, int relu) {
    static bool attr_done = false;
    if (!attr_done) {
        cudaFuncSetAttribute(tgemm_kernel, cudaFuncAttributeMaxDynamicSharedMemorySize,
                             SMEM_BYTES);
        attr_done = true;
    }
    int Ntot = g.N1 + g.N2;
    dim3 grid(Ntot / BNt, (M + BMt - 1) / BMt, 2);
    tgemm_kernel<<<grid, 256, SMEM_BYTES>>>(g, M, K, relu);
}

extern "C" void kernel_launch(void* const* d_in, const int* in_sizes, int n_in,
                              void* d_out_v, int out_size) {
    const float* tgt[2] = {(const float*)d_in[0], (const float*)d_in[1]};
    const float* pos[2] = {(const float*)d_in[2], (const float*)d_in[3]};
    const float* refp[2] = {(const float*)d_in[4], (const float*)d_in[5]};
    const float* src[2] = {(const float*)d_in[6], (const float*)d_in[7]};
    const float* sa_in_w  = (const float*)d_in[8];
    const float* sa_in_b  = (const float*)d_in[9];
    const float* sa_out_w = (const float*)d_in[10];
    const float* sa_out_b = (const float*)d_in[11];
    const float* ln_w     = (const float*)d_in[12];
    const float* ln_b     = (const float*)d_in[13];
    const float* ffn_w1   = (const float*)d_in[14];
    const float* ffn_b1   = (const float*)d_in[15];
    const float* ffn_w2   = (const float*)d_in[16];
    const float* ffn_b2   = (const float*)d_in[17];
    const float* val_w    = (const float*)d_in[18];
    const float* val_b    = (const float*)d_in[19];
    const float* off_w    = (const float*)d_in[20];
    const float* off_b    = (const float*)d_in[21];
    const float* aw_w     = (const float*)d_in[22];
    const float* aw_b     = (const float*)d_in[23];
    const float* cout_w   = (const float*)d_in[24];
    const float* cout_b   = (const float*)d_in[25];
    float* out = (float*)d_out_v;

    float *p_qkv, *p_attn, *p_sa, *p_tgt2, *p_off, *p_aw,
          *p_samp, *p_ffn, *p_y, *p_x, *p_r, *p_t, *p_wT;
    cudaGetSymbolAddress((void**)&p_qkv,  g_qkv);
    cudaGetSymbolAddress((void**)&p_attn, g_attn);
    cudaGetSymbolAddress((void**)&p_sa,   g_sa);
    cudaGetSymbolAddress((void**)&p_tgt2, g_tgt2);
    cudaGetSymbolAddress((void**)&p_off,  g_off);
    cudaGetSymbolAddress((void**)&p_aw,   g_aw);
    cudaGetSymbolAddress((void**)&p_samp, g_samp);
    cudaGetSymbolAddress((void**)&p_ffn,  g_ffn);
    cudaGetSymbolAddress((void**)&p_y,    g_y);
    cudaGetSymbolAddress((void**)&p_x,    g_x);
    cudaGetSymbolAddress((void**)&p_r,    g_r);
    cudaGetSymbolAddress((void**)&p_t,    g_t);
    cudaGetSymbolAddress((void**)&p_wT,   g_wT);

    const int GRID_E = (NE + 255) / 256;

    // ---- fused qkv projection: q,k use tgt+pos (cols <512), v uses tgt
    {
        GPtrs g = {};
        g.A[0] = tgt[0]; g.A[1] = tgt[1];
        g.A2[0] = pos[0]; g.A2[1] = pos[1];
        g.W[0] = sa_in_w; g.W[1] = sa_in_w + (size_t)3 * D * D;
        g.Bi[0] = sa_in_b; g.Bi[1] = sa_in_b + 3 * D;
        g.C[0] = p_qkv; g.C[1] = p_qkv + (size_t)BNQ * 768;
        g.N1 = 768; g.N2 = 0; g.a2lim = 512;
        gemm2(g, BNQ, D, 0);
    }
    // ---- attention (5 q-chunks)
    {
        AttnArgs a = {{p_qkv, p_qkv + (size_t)BNQ * 768}, {p_attn, p_attn + NE}};
        attn_kernel<<<dim3(BS * NH, 2, 5), 192>>>(a);
    }
    // ---- out projection
    {
        GPtrs g = {};
        g.A[0] = p_attn; g.A[1] = p_attn + NE;
        g.W[0] = sa_out_w; g.W[1] = sa_out_w + (size_t)D * D;
        g.Bi[0] = sa_out_b; g.Bi[1] = sa_out_b + D;
        g.C[0] = p_sa; g.C[1] = p_sa + NE;
        g.N1 = 256; g.N2 = 0; g.a2lim = 0;
        gemm2(g, BNQ, D, 0);
    }
    // ---- tgt2 = LN(tgt + sa)  (norm2)
    {
        LnArgs a = {{tgt[0], tgt[1]}, {p_sa, p_sa + NE},
                    {ln_w + 1 * D, ln_w + 4 * D}, {ln_b + 1 * D, ln_b + 4 * D},
                    {p_tgt2, p_tgt2 + NE}};
        ln_kernel<<<dim3(BNQ / 8, 2), 256>>>(a);
    }
    // ---- fused offsets|aw projection from (tgt2 + pos)
    {
        GPtrs g = {};
        g.A[0] = p_tgt2; g.A[1] = p_tgt2 + NE;
        g.A2[0] = pos[0]; g.A2[1] = pos[1];
        g.W[0] = off_w; g.W[1] = off_w + (size_t)256 * D;
        g.W2[0] = aw_w; g.W2[1] = aw_w + (size_t)128 * D;
        g.Bi[0] = off_b; g.Bi[1] = off_b + 256;
        g.Bi2[0] = aw_b; g.Bi2[1] = aw_b + 128;
        g.C[0] = p_off; g.C[1] = p_off + NE;
        g.C2[0] = p_aw; g.C2[1] = p_aw + (size_t)BNQ * 128;
        g.N1 = 256; g.N2 = 128; g.a2lim = 384;
        gemm2(g, BNQ, D, 0);
    }
    softmax16_kernel<<<(2 * BNQ * NH + 255) / 256, 256>>>(p_aw, 2 * BNQ * NH);

    // ---- val_w transpose + sampling, one modality per launch (L2 residency)
    transpose256_kernel<<<dim3(8, 8, 2), dim3(32, 8)>>>(val_w, p_wT);
    {
        MsdArgs a = {{src[1], src[0]},
                     {p_off, p_off + NE},
                     {p_aw, p_aw + (size_t)BNQ * 128},
                     {refp[0], refp[1]},
                     {p_wT, p_wT + (size_t)D * D},
                     {val_b, val_b + D},
                     {p_samp, p_samp + NE}};
        msdeform_kernel<<<BNQ / QB, 256>>>(a, 0);
        msdeform_kernel<<<BNQ / QB, 256>>>(a, 1);
    }
    // ---- cout projection -> output regions F_RGB / F_T
    {
        GPtrs g = {};
        g.A[0] = p_samp; g.A[1] = p_samp + NE;
        g.W[0] = cout_w; g.W[1] = cout_w + (size_t)D * D;
        g.Bi[0] = cout_b; g.Bi[1] = cout_b + D;
        g.C[0] = out + (size_t)2 * NE; g.C[1] = out + (size_t)3 * NE;
        g.N1 = 256; g.N2 = 0; g.a2lim = 0;
        gemm2(g, BNQ, D, 0);
    }

    // ---- cross residuals: r = tgt2_T + t2_RGB ; t = r + t2_T
    cross_res_kernel<<<GRID_E, 256>>>(p_tgt2 + NE, out + (size_t)2 * NE, out + (size_t)3 * NE,
                                      p_r, p_t, NE);
    {
        LnArgs a = {{p_r, p_t}, {nullptr, nullptr},
                    {ln_w + 0 * D, ln_w + 3 * D}, {ln_b + 0 * D, ln_b + 3 * D},
                    {p_x, p_x + NE}};
        ln_kernel<<<dim3(BNQ / 8, 2), 256>>>(a);
    }

    // ---- FFNs
    {
        GPtrs g = {};
        g.A[0] = p_x; g.A[1] = p_x + NE;
        g.W[0] = ffn_w1; g.W[1] = ffn_w1 + (size_t)DFF * D;
        g.Bi[0] = ffn_b1; g.Bi[1] = ffn_b1 + DFF;
        g.C[0] = p_ffn; g.C[1] = p_ffn + (size_t)BNQ * DFF;
        g.N1 = 1024; g.N2 = 0; g.a2lim = 0;
        gemm2(g, BNQ, D, 1);
    }
    {
        GPtrs g = {};
        g.A[0] = p_ffn; g.A[1] = p_ffn + (size_t)BNQ * DFF;
        g.W[0] = ffn_w2; g.W[1] = ffn_w2 + (size_t)D * DFF;
        g.Bi[0] = ffn_b2; g.Bi[1] = ffn_b2 + D;
        g.C[0] = p_y; g.C[1] = p_y + NE;
        g.N1 = 256; g.N2 = 0; g.a2lim = 0;
        gemm2(g, BNQ, DFF, 0);
    }
    {
        LnArgs a = {{p_x, p_x + NE}, {p_y, p_y + NE},
                    {ln_w + 2 * D, ln_w + 5 * D}, {ln_b + 2 * D, ln_b + 5 * D},
                    {out, out + NE}};
        ln_kernel<<<dim3(BNQ / 8, 2), 256>>>(a);
    }
}

// round 8
// speedup vs baseline: 2.9700x; 1.0383x over previous
#include <cuda_runtime.h>
#include <cuda_bf16.h>
#include <math.h>
#include <stdint.h>

// ---------------- problem constants ----------------
#define BS   4
#define NQ   300
#define D    256
#define NH   8
#define DH   32
#define NL   4
#define NP   4
#define DFF  1024
#define LTOT 17821
#define BNQ  (BS*NQ)          // 1200
#define QB   4                // queries per msdeform block
#define NE   (BNQ*D)          // 307200

// ---------------- scratch (device globals; no allocation allowed) ----------------
__device__ float g_qkv [2][BNQ*768];
__device__ float g_attn[2][BNQ*D];
__device__ float g_sa  [2][BNQ*D];
__device__ float g_tgt2[2][BNQ*D];
__device__ float g_off [2][BNQ*D];
__device__ float g_aw  [2*BNQ*(NH*NL*NP)];
__device__ float g_samp[2][BNQ*D];
__device__ float g_ffn [2][BNQ*DFF];
__device__ float g_y   [2][BNQ*D];
__device__ float g_x   [2][BNQ*D];
__device__ float g_wT  [2][D*D];

// ---------------- pointer-pack structs (passed by value) ----------------
struct GPtrs {
    const float* A[2];
    const float* A2[2];
    const float* W[2];
    const float* W2[2];
    const float* Bi[2];
    const float* Bi2[2];
    float*       C[2];
    float*       C2[2];
    int N1, N2, a2lim;
};
struct LnArgs {
    const float* x[2];
    const float* r[2];
    const float* g[2];
    const float* b[2];
    float*       y[2];
};
struct AttnArgs {
    const float* qkv[2];
    float*       out[2];
};
struct MsdArgs {
    const float* src[2];
    const float* off[2];
    const float* aw[2];
    const float* ref[2];
    const float* wT[2];
    const float* vb[2];
    float*       samp[2];
};

// ---------------- weight transpose 256x256, z-batched ----------------
__global__ void transpose256_kernel(const float* __restrict__ w, float* __restrict__ wT) {
    __shared__ float tile[32][33];
    int z = blockIdx.z;
    const float* ws = w + (size_t)z * D * D;
    float* wd = wT + (size_t)z * D * D;
    int bx = blockIdx.x * 32, by = blockIdx.y * 32;
    int tx = threadIdx.x, ty = threadIdx.y;
    #pragma unroll
    for (int i = 0; i < 32; i += 8)
        tile[ty + i][tx] = ws[(size_t)(by + ty + i) * D + bx + tx];
    __syncthreads();
    #pragma unroll
    for (int i = 0; i < 32; i += 8)
        wd[(size_t)(bx + ty + i) * D + by + tx] = tile[tx][ty + i];
}

// ---------------- tf32x3 tensor-core GEMM, z-batched, column-split capable ----------------
#define BMt 32
#define BNt 64
#define BKt 32
#define TST 36

#define ASZ (BMt * TST)
#define WSZ (BNt * TST)
#define SMEM_FLOATS (2*ASZ + 2*ASZ + 2*WSZ + 2*WSZ)
#define SMEM_BYTES  (SMEM_FLOATS * 4)                // 55296

__device__ __forceinline__ uint32_t f2tf(float f) {
    uint32_t u;
    asm("cvt.rna.tf32.f32 %0, %1;" : "=r"(u) : "f"(f));
    return u;
}

__device__ __forceinline__ void mma_tf32(float4& d, const uint32_t a0, const uint32_t a1,
                                         const uint32_t a2, const uint32_t a3,
                                         const uint32_t b0, const uint32_t b1) {
    asm volatile(
        "mma.sync.aligned.m16n8k8.row.col.f32.tf32.tf32.f32 "
        "{%0,%1,%2,%3}, {%4,%5,%6,%7}, {%8,%9}, {%0,%1,%2,%3};\n"
        : "+f"(d.x), "+f"(d.y), "+f"(d.z), "+f"(d.w)
        : "r"(a0), "r"(a1), "r"(a2), "r"(a3), "r"(b0), "r"(b1));
}

__global__ __launch_bounds__(256)
void tgemm_kernel(GPtrs g, int M, int K, int relu) {
    extern __shared__ float sm[];
    float* AsH = sm;
    float* AsL = AsH + 2 * ASZ;
    float* WsH = AsL + 2 * ASZ;
    float* WsL = WsH + 2 * WSZ;

    int z = blockIdx.z;
    int bm = blockIdx.y * BMt, bn = blockIdx.x * BNt;

    const float* __restrict__ A  = g.A[z];
    const float* __restrict__ A2 = (bn < g.a2lim) ? g.A2[z] : nullptr;
    const float* __restrict__ W;
    const float* __restrict__ bias;
    float* __restrict__ C;
    int colbase, cstride;
    if (bn < g.N1) {
        W = g.W[z];  bias = g.Bi[z];  C = g.C[z];
        colbase = bn; cstride = g.N1;
    } else {
        W = g.W2[z]; bias = g.Bi2[z]; C = g.C2[z];
        colbase = bn - g.N1; cstride = g.N2;
    }

    int tid = threadIdx.x;
    int lane = tid & 31, warp = tid >> 5;
    int wm = (warp & 1) << 4;
    int wn = (warp >> 1) << 4;
    int g8 = lane >> 2, tig = lane & 3;

    int q = tid & 3;
    int o0 = (q >> 1) * 8 + (q & 1);
    int o1 = ((q + 4) >> 1) * 8 + (q & 1);
    int lrowB = tid >> 2;
    int lrowA = tid >> 2;
    bool aLoader = tid < 128;
    int gmr = bm + lrowA;
    bool am_ok = aLoader && gmr < M;
    const float* Ap  = A + (size_t)(am_ok ? gmr : 0) * K;
    const float* A2p = A2 ? A2 + (size_t)(am_ok ? gmr : 0) * K : nullptr;
    const float* Wp  = W + (size_t)(colbase + lrowB) * K;

    float4 a0r, a1r, w0r, w1r;

    auto gload = [&](int k0) {
        a0r = make_float4(0.f, 0.f, 0.f, 0.f);
        a1r = a0r;
        if (am_ok) {
            a0r = *(const float4*)(Ap + k0 + 4 * q);
            a1r = *(const float4*)(Ap + k0 + 16 + 4 * q);
            if (A2p) {
                float4 t0 = *(const float4*)(A2p + k0 + 4 * q);
                float4 t1 = *(const float4*)(A2p + k0 + 16 + 4 * q);
                a0r.x += t0.x; a0r.y += t0.y; a0r.z += t0.z; a0r.w += t0.w;
                a1r.x += t1.x; a1r.y += t1.y; a1r.z += t1.z; a1r.w += t1.w;
            }
        }
        w0r = *(const float4*)(Wp + k0 + 4 * q);
        w1r = *(const float4*)(Wp + k0 + 16 + 4 * q);
    };
    auto splitStore = [](float* __restrict__ H, float* __restrict__ L, int idx, float v) {
        uint32_t hi = f2tf(v);
        H[idx] = __uint_as_float(hi);
        L[idx] = __uint_as_float(f2tf(v - __uint_as_float(hi)));
    };
    auto sstore = [&](int buf) {
        if (aLoader) {
            float* ah = &AsH[buf * ASZ + lrowA * TST];
            float* al = &AsL[buf * ASZ + lrowA * TST];
            splitStore(ah, al, o0 + 0, a0r.x);
            splitStore(ah, al, o0 + 2, a0r.y);
            splitStore(ah, al, o0 + 4, a0r.z);
            splitStore(ah, al, o0 + 6, a0r.w);
            splitStore(ah, al, o1 + 0, a1r.x);
            splitStore(ah, al, o1 + 2, a1r.y);
            splitStore(ah, al, o1 + 4, a1r.z);
            splitStore(ah, al, o1 + 6, a1r.w);
        }
        float* wh = &WsH[buf * WSZ + lrowB * TST];
        float* wl = &WsL[buf * WSZ + lrowB * TST];
        splitStore(wh, wl, o0 + 0, w0r.x);
        splitStore(wh, wl, o0 + 2, w0r.y);
        splitStore(wh, wl, o0 + 4, w0r.z);
        splitStore(wh, wl, o0 + 6, w0r.w);
        splitStore(wh, wl, o1 + 0, w1r.x);
        splitStore(wh, wl, o1 + 2, w1r.y);
        splitStore(wh, wl, o1 + 4, w1r.z);
        splitStore(wh, wl, o1 + 6, w1r.w);
    };

    gload(0);
    sstore(0);
    __syncthreads();

    float4 accA[2], accB[2], accC[2];
    #pragma unroll
    for (int j = 0; j < 2; j++) {
        accA[j] = make_float4(0.f, 0.f, 0.f, 0.f);
        accB[j] = accA[j]; accC[j] = accA[j];
    }

    int T = K / BKt;
    for (int t = 0; t < T; t++) {
        int buf = t & 1;
        if (t + 1 < T) gload((t + 1) * BKt);

        const float* ah = &AsH[buf * ASZ];
        const float* al = &AsL[buf * ASZ];
        const float* wh = &WsH[buf * WSZ];
        const float* wl = &WsL[buf * WSZ];
        #pragma unroll
        for (int ks = 0; ks < 4; ks++) {
            int fo = ks * 8 + 2 * tig;
            int ra = (wm + g8) * TST + fo;
            int rb = (wm + g8 + 8) * TST + fo;
            float2 AH0 = *(const float2*)&ah[ra];
            float2 AH1 = *(const float2*)&ah[rb];
            float2 AL0 = *(const float2*)&al[ra];
            float2 AL1 = *(const float2*)&al[rb];
            uint32_t h0 = __float_as_uint(AH0.x), h1 = __float_as_uint(AH1.x);
            uint32_t h2 = __float_as_uint(AH0.y), h3 = __float_as_uint(AH1.y);
            uint32_t l0 = __float_as_uint(AL0.x), l1 = __float_as_uint(AL1.x);
            uint32_t l2 = __float_as_uint(AL0.y), l3 = __float_as_uint(AL1.y);
            #pragma unroll
            for (int j = 0; j < 2; j++) {
                int rw = (wn + 8 * j + g8) * TST + fo;
                float2 BH = *(const float2*)&wh[rw];
                float2 BL = *(const float2*)&wl[rw];
                uint32_t bh0 = __float_as_uint(BH.x), bh1 = __float_as_uint(BH.y);
                uint32_t bl0 = __float_as_uint(BL.x), bl1 = __float_as_uint(BL.y);
                mma_tf32(accA[j], h0, h1, h2, h3, bh0, bh1);
                mma_tf32(accB[j], h0, h1, h2, h3, bl0, bl1);
                mma_tf32(accC[j], l0, l1, l2, l3, bh0, bh1);
            }
        }

        if (t + 1 < T) {
            sstore(buf ^ 1);
            __syncthreads();
        }
    }

    int r0 = bm + wm + g8;
    int r1 = r0 + 8;
    #pragma unroll
    for (int j = 0; j < 2; j++) {
        int cl = colbase + wn + 8 * j + 2 * tig;
        float b0 = bias[cl], b1 = bias[cl + 1];
        float v00 = accA[j].x + accB[j].x + accC[j].x + b0;
        float v01 = accA[j].y + accB[j].y + accC[j].y + b1;
        float v10 = accA[j].z + accB[j].z + accC[j].z + b0;
        float v11 = accA[j].w + accB[j].w + accC[j].w + b1;
        if (relu) {
            v00 = fmaxf(v00, 0.f); v01 = fmaxf(v01, 0.f);
            v10 = fmaxf(v10, 0.f); v11 = fmaxf(v11, 0.f);
        }
        if (r0 < M) *(float2*)&C[(size_t)r0 * cstride + cl] = make_float2(v00, v01);
        if (r1 < M) *(float2*)&C[(size_t)r1 * cstride + cl] = make_float2(v10, v11);
    }
}

// ---------------- self-attention: per (b,h,z,qchunk), N=300, DH=32 ----------------
__global__ void attn_kernel(AttnArgs a) {
    const float scale = 0.17677669529663687f;
    int z = blockIdx.y;
    const float* __restrict__ qkv = a.qkv[z];
    float* __restrict__ out = a.out[z];

    int bh = blockIdx.x;
    int b = bh >> 3, h = bh & 7;
    int qbase = blockIdx.z * 60;
    __shared__ float Ks[NQ * 33];
    __shared__ float Ps[6][304];

    int tid = threadIdx.x;
    int w = tid >> 5, lane = tid & 31;

    for (int i = tid; i < NQ * 32; i += 192) {
        int k = i >> 5, c = i & 31;
        Ks[k * 33 + c] = qkv[(size_t)(b * NQ + k) * 768 + 256 + h * 32 + c];
    }
    __syncthreads();

    for (int q = qbase + w; q < qbase + 60; q += 6) {
        float qreg = qkv[(size_t)(b * NQ + q) * 768 + h * 32 + lane];
        float sj[10];
        float mx = -3.0e38f;
        #pragma unroll
        for (int j = 0; j < 10; j++) {
            int k = lane + 32 * j;
            int kk = (k < NQ) ? k : (NQ - 1);
            float acc = 0.f;
            #pragma unroll
            for (int c = 0; c < 32; c++)
                acc = fmaf(__shfl_sync(0xffffffffu, qreg, c), Ks[kk * 33 + c], acc);
            acc *= scale;
            sj[j] = (k < NQ) ? acc : -3.0e38f;
            mx = fmaxf(mx, sj[j]);
        }
        #pragma unroll
        for (int o = 16; o > 0; o >>= 1)
            mx = fmaxf(mx, __shfl_xor_sync(0xffffffffu, mx, o));
        float lsum = 0.f;
        float pj[10];
        #pragma unroll
        for (int j = 0; j < 10; j++) {
            int k = lane + 32 * j;
            pj[j] = (k < NQ) ? expf(sj[j] - mx) : 0.f;
            lsum += pj[j];
        }
        #pragma unroll
        for (int o = 16; o > 0; o >>= 1)
            lsum += __shfl_xor_sync(0xffffffffu, lsum, o);
        float inv = 1.f / lsum;
        #pragma unroll
        for (int j = 0; j < 10; j++) {
            int k = lane + 32 * j;
            if (k < NQ) Ps[w][k] = pj[j] * inv;
        }
        __syncwarp();
        float acc = 0.f;
        for (int k = 0; k < NQ; k++)
            acc = fmaf(Ps[w][k], qkv[(size_t)(b * NQ + k) * 768 + 512 + h * 32 + lane], acc);
        out[(size_t)(b * NQ + q) * D + h * 32 + lane] = acc;
        __syncwarp();
    }
}

// ---------------- layernorm: warp-per-row, barrier-free ----------------
__device__ __forceinline__ void ln_row(float4 v0, float4 v1,
                                       const float* __restrict__ g,
                                       const float* __restrict__ b,
                                       int lane, float* __restrict__ yout) {
    float s  = v0.x + v0.y + v0.z + v0.w + v1.x + v1.y + v1.z + v1.w;
    float s2 = v0.x*v0.x + v0.y*v0.y + v0.z*v0.z + v0.w*v0.w
             + v1.x*v1.x + v1.y*v1.y + v1.z*v1.z + v1.w*v1.w;
    #pragma unroll
    for (int o = 16; o > 0; o >>= 1) {
        s  += __shfl_xor_sync(0xffffffffu, s, o);
        s2 += __shfl_xor_sync(0xffffffffu, s2, o);
    }
    float mean = s * (1.f / D);
    float var = s2 * (1.f / D) - mean * mean;
    float rstd = rsqrtf(var + 1e-5f);

    const float4* gp = (const float4*)g;
    const float4* bp = (const float4*)b;
    float4 g0 = gp[lane], g1 = gp[32 + lane];
    float4 b0 = bp[lane], b1 = bp[32 + lane];
    float4 y0, y1;
    y0.x = (v0.x - mean) * rstd * g0.x + b0.x;
    y0.y = (v0.y - mean) * rstd * g0.y + b0.y;
    y0.z = (v0.z - mean) * rstd * g0.z + b0.z;
    y0.w = (v0.w - mean) * rstd * g0.w + b0.w;
    y1.x = (v1.x - mean) * rstd * g1.x + b1.x;
    y1.y = (v1.y - mean) * rstd * g1.y + b1.y;
    y1.z = (v1.z - mean) * rstd * g1.z + b1.z;
    y1.w = (v1.w - mean) * rstd * g1.w + b1.w;
    float4* yp = (float4*)yout;
    yp[lane] = y0;
    yp[32 + lane] = y1;
}

__global__ __launch_bounds__(256)
void ln_kernel(LnArgs a) {
    int z = blockIdx.y;
    int w = threadIdx.x >> 5, lane = threadIdx.x & 31;
    int row = blockIdx.x * 8 + w;
    size_t base = (size_t)row * D;

    const float4* xp = (const float4*)(a.x[z] + base);
    float4 v0 = xp[lane];
    float4 v1 = xp[32 + lane];
    if (a.r[z]) {
        const float4* rp = (const float4*)(a.r[z] + base);
        float4 r0 = rp[lane], r1 = rp[32 + lane];
        v0.x += r0.x; v0.y += r0.y; v0.z += r0.z; v0.w += r0.w;
        v1.x += r1.x; v1.y += r1.y; v1.z += r1.z; v1.w += r1.w;
    }
    ln_row(v0, v1, a.g[z], a.b[z], lane, a.y[z] + base);
}

// ---------------- fused cross residual + norm1 LNs ----------------
// r = tgt2_T + t2_RGB -> LN(g0,b0) -> x0 ; t = r + t2_T -> LN(g1,b1) -> x1
__global__ __launch_bounds__(256)
void crossln_kernel(const float* __restrict__ tgt2T, const float* __restrict__ t2R,
                    const float* __restrict__ t2T,
                    const float* __restrict__ g0, const float* __restrict__ b0,
                    const float* __restrict__ g1, const float* __restrict__ b1,
                    float* __restrict__ x0, float* __restrict__ x1) {
    int w = threadIdx.x >> 5, lane = threadIdx.x & 31;
    int row = blockIdx.x * 8 + w;
    size_t base = (size_t)row * D;

    const float4* ap = (const float4*)(tgt2T + base);
    const float4* bp = (const float4*)(t2R + base);
    const float4* cp = (const float4*)(t2T + base);
    float4 r0 = ap[lane], r1 = ap[32 + lane];
    float4 q0 = bp[lane], q1 = bp[32 + lane];
    r0.x += q0.x; r0.y += q0.y; r0.z += q0.z; r0.w += q0.w;
    r1.x += q1.x; r1.y += q1.y; r1.z += q1.z; r1.w += q1.w;
    float4 t0 = cp[lane], t1 = cp[32 + lane];
    t0.x += r0.x; t0.y += r0.y; t0.z += r0.z; t0.w += r0.w;
    t1.x += r1.x; t1.y += r1.y; t1.z += r1.z; t1.w += r1.w;

    ln_row(r0, r1, g0, b0, lane, x0 + base);
    ln_row(t0, t1, g1, b1, lane, x1 + base);
}

// ---------------- deformable sampling + fused softmax + fused head projection ----------------
__global__ __launch_bounds__(256)
void msdeform_kernel(MsdArgs ar) {
    const int Hs[4]  = {100, 50, 25, 13};
    const int Wls[4] = {134, 67, 34, 17};
    const int S0[4]  = {0, 13400, 16750, 17600};

    int z = blockIdx.y;
    const float* __restrict__ src = ar.src[z];
    const float* __restrict__ off = ar.off[z];
    const float* __restrict__ aw  = ar.aw[z];
    const float* __restrict__ ref = ar.ref[z];
    const float* __restrict__ valwT = ar.wT[z];
    const float* __restrict__ valb  = ar.vb[z];
    float* __restrict__ samp = ar.samp[z];

    __shared__ float sh_s[QB][NH][256];
    __shared__ float sh_ws[QB][NH];

    int h = threadIdx.x >> 5, lane = threadIdx.x & 31;
    int bq0 = blockIdx.x * QB;
    int b = bq0 / NQ;

    for (int qq = 0; qq < QB; qq++) {
        int bq = bq0 + qq;

        // ---- coalesced parameter prefetch (3 loads) + in-register softmax
        float offv = off[(size_t)bq * 256 + h * 32 + lane];               // 32 offsets
        float awv  = (lane < 16) ? aw[(size_t)bq * 128 + h * 16 + lane] : -3.0e38f;
        float refv = (lane < 8) ? ref[(size_t)bq * 8 + lane] : 0.f;

        float m = awv;
        #pragma unroll
        for (int o = 8; o > 0; o >>= 1)
            m = fmaxf(m, __shfl_xor_sync(0xffffffffu, m, o));
        float e = (lane < 16) ? expf(awv - m) : 0.f;
        float es = e;
        #pragma unroll
        for (int o = 8; o > 0; o >>= 1)
            es += __shfl_xor_sync(0xffffffffu, es, o);
        float aws = e / es;    // lanes 0..15 hold softmaxed weights

        float acc[8] = {};
        float wsum = 0.f;

        #pragma unroll
        for (int l = 0; l < 4; l++) {
            float rx = __shfl_sync(0xffffffffu, refv, 2 * l);
            float ry = __shfl_sync(0xffffffffu, refv, 2 * l + 1);
            int Wl = Wls[l], Hl = Hs[l];
            float Wf = (float)Wl, Hf = (float)Hl;
            int rowbase = b * LTOT + S0[l];
            #pragma unroll
            for (int p = 0; p < 4; p++) {
                float ox = __shfl_sync(0xffffffffu, offv, (l * 4 + p) * 2);
                float oy = __shfl_sync(0xffffffffu, offv, (l * 4 + p) * 2 + 1);
                float a  = __shfl_sync(0xffffffffu, aws, l * 4 + p);
                float x = fmaf(rx, Wf, ox) - 0.5f;
                float y = fmaf(ry, Hf, oy) - 0.5f;
                float x0f = floorf(x), y0f = floorf(y);
                int x0 = (int)x0f, y0 = (int)y0f;
                float wx = x - x0f, wy = y - y0f;
                float tw[4] = {(1.f - wx) * (1.f - wy) * a, wx * (1.f - wy) * a,
                               (1.f - wx) * wy * a,          wx * wy * a};
                int xs[4] = {x0, x0 + 1, x0,     x0 + 1};
                int ys[4] = {y0, y0,     y0 + 1, y0 + 1};
                #pragma unroll
                for (int t = 0; t < 4; t++) {
                    int xi = xs[t], yi = ys[t];
                    if (xi < 0 || xi >= Wl || yi < 0 || yi >= Hl) continue;
                    const float4* pr = (const float4*)(src + ((size_t)rowbase + (size_t)yi * Wl + xi) * 256);
                    float w = tw[t];
                    float4 v0 = __ldg(pr + lane);
                    float4 v1 = __ldg(pr + 32 + lane);
                    acc[0] = fmaf(w, v0.x, acc[0]);
                    acc[1] = fmaf(w, v0.y, acc[1]);
                    acc[2] = fmaf(w, v0.z, acc[2]);
                    acc[3] = fmaf(w, v0.w, acc[3]);
                    acc[4] = fmaf(w, v1.x, acc[4]);
                    acc[5] = fmaf(w, v1.y, acc[5]);
                    acc[6] = fmaf(w, v1.z, acc[6]);
                    acc[7] = fmaf(w, v1.w, acc[7]);
                    wsum += w;
                }
            }
        }
        float4* sp = (float4*)&sh_s[qq][h][0];
        sp[lane]      = make_float4(acc[0], acc[1], acc[2], acc[3]);
        sp[32 + lane] = make_float4(acc[4], acc[5], acc[6], acc[7]);
        if (lane == 0) sh_ws[qq][h] = wsum;
    }
    __syncthreads();

    int n = threadIdx.x;
    int h2 = n >> 5;
    float t0 = 0.f, t1 = 0.f, t2 = 0.f, t3 = 0.f;
    #pragma unroll 4
    for (int c = 0; c < 256; c++) {
        float w = __ldg(valwT + (size_t)c * 256 + n);
        t0 = fmaf(sh_s[0][h2][c], w, t0);
        t1 = fmaf(sh_s[1][h2][c], w, t1);
        t2 = fmaf(sh_s[2][h2][c], w, t2);
        t3 = fmaf(sh_s[3][h2][c], w, t3);
    }
    float vb = valb[n];
    samp[(size_t)(bq0 + 0) * 256 + n] = t0 + sh_ws[0][h2] * vb;
    samp[(size_t)(bq0 + 1) * 256 + n] = t1 + sh_ws[1][h2] * vb;
    samp[(size_t)(bq0 + 2) * 256 + n] = t2 + sh_ws[2][h2] * vb;
    samp[(size_t)(bq0 + 3) * 256 + n] = t3 + sh_ws[3][h2] * vb;
}

// ---------------- host side ----------------
static void gemm2(GPtrs& g, int M, int K, int relu) {
    static bool attr_done = false;
    if (!attr_done) {
        cudaFuncSetAttribute(tgemm_kernel, cudaFuncAttributeMaxDynamicSharedMemorySize,
                             SMEM_BYTES);
        attr_done = true;
    }
    int Ntot = g.N1 + g.N2;
    dim3 grid(Ntot / BNt, (M + BMt - 1) / BMt, 2);
    tgemm_kernel<<<grid, 256, SMEM_BYTES>>>(g, M, K, relu);
}

extern "C" void kernel_launch(void* const* d_in, const int* in_sizes, int n_in,
                              void* d_out_v, int out_size) {
    const float* tgt[2] = {(const float*)d_in[0], (const float*)d_in[1]};
    const float* pos[2] = {(const float*)d_in[2], (const float*)d_in[3]};
    const float* refp[2] = {(const float*)d_in[4], (const float*)d_in[5]};
    const float* src[2] = {(const float*)d_in[6], (const float*)d_in[7]};
    const float* sa_in_w  = (const float*)d_in[8];
    const float* sa_in_b  = (const float*)d_in[9];
    const float* sa_out_w = (const float*)d_in[10];
    const float* sa_out_b = (const float*)d_in[11];
    const float* ln_w     = (const float*)d_in[12];
    const float* ln_b     = (const float*)d_in[13];
    const float* ffn_w1   = (const float*)d_in[14];
    const float* ffn_b1   = (const float*)d_in[15];
    const float* ffn_w2   = (const float*)d_in[16];
    const float* ffn_b2   = (const float*)d_in[17];
    const float* val_w    = (const float*)d_in[18];
    const float* val_b    = (const float*)d_in[19];
    const float* off_w    = (const float*)d_in[20];
    const float* off_b    = (const float*)d_in[21];
    const float* aw_w     = (const float*)d_in[22];
    const float* aw_b     = (const float*)d_in[23];
    const float* cout_w   = (const float*)d_in[24];
    const float* cout_b   = (const float*)d_in[25];
    float* out = (float*)d_out_v;

    float *p_qkv, *p_attn, *p_sa, *p_tgt2, *p_off, *p_aw,
          *p_samp, *p_ffn, *p_y, *p_x, *p_wT;
    cudaGetSymbolAddress((void**)&p_qkv,  g_qkv);
    cudaGetSymbolAddress((void**)&p_attn, g_attn);
    cudaGetSymbolAddress((void**)&p_sa,   g_sa);
    cudaGetSymbolAddress((void**)&p_tgt2, g_tgt2);
    cudaGetSymbolAddress((void**)&p_off,  g_off);
    cudaGetSymbolAddress((void**)&p_aw,   g_aw);
    cudaGetSymbolAddress((void**)&p_samp, g_samp);
    cudaGetSymbolAddress((void**)&p_ffn,  g_ffn);
    cudaGetSymbolAddress((void**)&p_y,    g_y);
    cudaGetSymbolAddress((void**)&p_x,    g_x);
    cudaGetSymbolAddress((void**)&p_wT,   g_wT);

    // ---- val_w transpose (depends only on input weights; issue first)
    transpose256_kernel<<<dim3(8, 8, 2), dim3(32, 8)>>>(val_w, p_wT);

    // ---- fused qkv projection: q,k use tgt+pos (cols <512), v uses tgt
    {
        GPtrs g = {};
        g.A[0] = tgt[0]; g.A[1] = tgt[1];
        g.A2[0] = pos[0]; g.A2[1] = pos[1];
        g.W[0] = sa_in_w; g.W[1] = sa_in_w + (size_t)3 * D * D;
        g.Bi[0] = sa_in_b; g.Bi[1] = sa_in_b + 3 * D;
        g.C[0] = p_qkv; g.C[1] = p_qkv + (size_t)BNQ * 768;
        g.N1 = 768; g.N2 = 0; g.a2lim = 512;
        gemm2(g, BNQ, D, 0);
    }
    // ---- attention (5 q-chunks)
    {
        AttnArgs a = {{p_qkv, p_qkv + (size_t)BNQ * 768}, {p_attn, p_attn + NE}};
        attn_kernel<<<dim3(BS * NH, 2, 5), 192>>>(a);
    }
    // ---- out projection
    {
        GPtrs g = {};
        g.A[0] = p_attn; g.A[1] = p_attn + NE;
        g.W[0] = sa_out_w; g.W[1] = sa_out_w + (size_t)D * D;
        g.Bi[0] = sa_out_b; g.Bi[1] = sa_out_b + D;
        g.C[0] = p_sa; g.C[1] = p_sa + NE;
        g.N1 = 256; g.N2 = 0; g.a2lim = 0;
        gemm2(g, BNQ, D, 0);
    }
    // ---- tgt2 = LN(tgt + sa)  (norm2)
    {
        LnArgs a = {{tgt[0], tgt[1]}, {p_sa, p_sa + NE},
                    {ln_w + 1 * D, ln_w + 4 * D}, {ln_b + 1 * D, ln_b + 4 * D},
                    {p_tgt2, p_tgt2 + NE}};
        ln_kernel<<<dim3(BNQ / 8, 2), 256>>>(a);
    }
    // ---- fused offsets|aw projection from (tgt2 + pos)
    {
        GPtrs g = {};
        g.A[0] = p_tgt2; g.A[1] = p_tgt2 + NE;
        g.A2[0] = pos[0]; g.A2[1] = pos[1];
        g.W[0] = off_w; g.W[1] = off_w + (size_t)256 * D;
        g.W2[0] = aw_w; g.W2[1] = aw_w + (size_t)128 * D;
        g.Bi[0] = off_b; g.Bi[1] = off_b + 256;
        g.Bi2[0] = aw_b; g.Bi2[1] = aw_b + 128;
        g.C[0] = p_off; g.C[1] = p_off + NE;
        g.C2[0] = p_aw; g.C2[1] = p_aw + (size_t)BNQ * 128;
        g.N1 = 256; g.N2 = 128; g.a2lim = 384;
        gemm2(g, BNQ, D, 0);
    }

    // ---- sampling: z-batched, softmax fused in-kernel (p_aw holds raw logits)
    {
        MsdArgs a = {{src[1], src[0]},
                     {p_off, p_off + NE},
                     {p_aw, p_aw + (size_t)BNQ * 128},
                     {refp[0], refp[1]},
                     {p_wT, p_wT + (size_t)D * D},
                     {val_b, val_b + D},
                     {p_samp, p_samp + NE}};
        msdeform_kernel<<<dim3(BNQ / QB, 2), 256>>>(a);
    }
    // ---- cout projection -> output regions F_RGB / F_T
    {
        GPtrs g = {};
        g.A[0] = p_samp; g.A[1] = p_samp + NE;
        g.W[0] = cout_w; g.W[1] = cout_w + (size_t)D * D;
        g.Bi[0] = cout_b; g.Bi[1] = cout_b + D;
        g.C[0] = out + (size_t)2 * NE; g.C[1] = out + (size_t)3 * NE;
        g.N1 = 256; g.N2 = 0; g.a2lim = 0;
        gemm2(g, BNQ, D, 0);
    }

    // ---- fused cross residuals + norm1 LNs
    crossln_kernel<<<BNQ / 8, 256>>>(p_tgt2 + NE, out + (size_t)2 * NE, out + (size_t)3 * NE,
                                     ln_w + 0 * D, ln_b + 0 * D, ln_w + 3 * D, ln_b + 3 * D,
                                     p_x, p_x + NE);

    // ---- FFNs
    {
        GPtrs g = {};
        g.A[0] = p_x; g.A[1] = p_x + NE;
        g.W[0] = ffn_w1; g.W[1] = ffn_w1 + (size_t)DFF * D;
        g.Bi[0] = ffn_b1; g.Bi[1] = ffn_b1 + DFF;
        g.C[0] = p_ffn; g.C[1] = p_ffn + (size_t)BNQ * DFF;
        g.N1 = 1024; g.N2 = 0; g.a2lim = 0;
        gemm2(g, BNQ, D, 1);
    }
    {
        GPtrs g = {};
        g.A[0] = p_ffn; g.A[1] = p_ffn + (size_t)BNQ * DFF;
        g.W[0] = ffn_w2; g.W[1] = ffn_w2 + (size_t)D * DFF;
        g.Bi[0] = ffn_b2; g.Bi[1] = ffn_b2 + D;
        g.C[0] = p_y; g.C[1] = p_y + NE;
        g.N1 = 256; g.N2 = 0; g.a2lim = 0;
        gemm2(g, BNQ, DFF, 0);
    }
    {
        LnArgs a = {{p_x, p_x + NE}, {p_y, p_y + NE},
                    {ln_w + 2 * D, ln_w + 5 * D}, {ln_b + 2 * D, ln_b + 5 * D},
                    {out, out + NE}};
        ln_kernel<<<dim3(BNQ / 8, 2), 256>>>(a);
    }
}

// round 9
// speedup vs baseline: 4.0269x; 1.3559x over previous
#include <cuda_runtime.h>
#include <cuda_bf16.h>
#include <math.h>
#include <stdint.h>

// ---------------- problem constants ----------------
#define BS   4
#define NQ   300
#define D    256
#define NH   8
#define DH   32
#define NL   4
#define NP   4
#define DFF  1024
#define LTOT 17821
#define BNQ  (BS*NQ)          // 1200
#define QB   4                // queries per msdeform block
#define NE   (BNQ*D)          // 307200

// ---------------- scratch (device globals; no allocation allowed) ----------------
__device__ float g_qkv [2][BNQ*768];
__device__ float g_attn[2][BNQ*D];
__device__ float g_sa  [2][BNQ*D];
__device__ float g_tgt2[2][BNQ*D];
__device__ float g_off [2][BNQ*D];
__device__ float g_aw  [2*BNQ*(NH*NL*NP)];
__device__ float g_samp[2][BNQ*D];
__device__ float g_ffn [2][BNQ*DFF];
__device__ float g_y   [2][BNQ*D];
__device__ float g_x   [2][BNQ*D];
__device__ float g_wT  [2][D*D];

// ---------------- pointer-pack structs (passed by value) ----------------
struct GPtrs {
    const float* A[2];
    const float* A2[2];
    const float* W[2];
    const float* W2[2];
    const float* Bi[2];
    const float* Bi2[2];
    float*       C[2];
    float*       C2[2];
    int N1, N2, a2lim;
};
struct LnArgs {
    const float* x[2];
    const float* r[2];
    const float* g[2];
    const float* b[2];
    float*       y[2];
};
struct AttnArgs {
    const float* qkv[2];
    float*       out[2];
};
struct MsdArgs {
    const float* src[2];
    const float* off[2];
    const float* aw[2];
    const float* ref[2];
    const float* wT[2];
    const float* vb[2];
    float*       samp[2];
};

// ---------------- weight transpose 256x256, z-batched ----------------
__global__ void transpose256_kernel(const float* __restrict__ w, float* __restrict__ wT) {
    __shared__ float tile[32][33];
    int z = blockIdx.z;
    const float* ws = w + (size_t)z * D * D;
    float* wd = wT + (size_t)z * D * D;
    int bx = blockIdx.x * 32, by = blockIdx.y * 32;
    int tx = threadIdx.x, ty = threadIdx.y;
    #pragma unroll
    for (int i = 0; i < 32; i += 8)
        tile[ty + i][tx] = ws[(size_t)(by + ty + i) * D + bx + tx];
    __syncthreads();
    #pragma unroll
    for (int i = 0; i < 32; i += 8)
        wd[(size_t)(bx + ty + i) * D + by + tx] = tile[tx][ty + i];
}

// ---------------- bf16x3 tensor-core GEMM, z-batched, column-split capable ----------------
// C[M,N] = (A (+A2))[M,K] @ [W|W2][N,K]^T + bias (+relu).
// fp32-grade accuracy via bf16 hi/lo split: acc = aH*bH + aH*bL + aL*bH.
#define BMt 32
#define BNt 64
#define BKt 32
#define RSW 20   // row stride in 32-bit words (= 40 bf16, conflict-free fragment loads)

#define ASZW (BMt * RSW)    // 640 words per A buffer
#define WSZW (BNt * RSW)    // 1280 words per W buffer

__device__ __forceinline__ void bf16_split2(float x, float y, uint32_t& hw, uint32_t& lw) {
    uint32_t h;
    asm("cvt.rn.bf16x2.f32 %0, %1, %2;" : "=r"(h) : "f"(y), "f"(x));  // hi=y, lo=x
    float hx = __uint_as_float(h << 16);
    float hy = __uint_as_float(h & 0xFFFF0000u);
    float lx = x - hx, ly = y - hy;
    asm("cvt.rn.bf16x2.f32 %0, %1, %2;" : "=r"(lw) : "f"(ly), "f"(lx));
    hw = h;
}

__device__ __forceinline__ void mma_bf16(float4& d, uint32_t a0, uint32_t a1,
                                         uint32_t a2, uint32_t a3,
                                         uint32_t b0, uint32_t b1) {
    asm volatile(
        "mma.sync.aligned.m16n8k16.row.col.f32.bf16.bf16.f32 "
        "{%0,%1,%2,%3}, {%4,%5,%6,%7}, {%8,%9}, {%0,%1,%2,%3};\n"
        : "+f"(d.x), "+f"(d.y), "+f"(d.z), "+f"(d.w)
        : "r"(a0), "r"(a1), "r"(a2), "r"(a3), "r"(b0), "r"(b1));
}

__global__ __launch_bounds__(256)
void tgemm_kernel(GPtrs g, int M, int K, int relu) {
    __shared__ uint32_t AsH[2][ASZW];
    __shared__ uint32_t AsL[2][ASZW];
    __shared__ uint32_t WsH[2][WSZW];
    __shared__ uint32_t WsL[2][WSZW];

    int z = blockIdx.z;
    int bm = blockIdx.y * BMt, bn = blockIdx.x * BNt;

    const float* __restrict__ A  = g.A[z];
    const float* __restrict__ A2 = (bn < g.a2lim) ? g.A2[z] : nullptr;
    const float* __restrict__ W;
    const float* __restrict__ bias;
    float* __restrict__ C;
    int colbase, cstride;
    if (bn < g.N1) {
        W = g.W[z];  bias = g.Bi[z];  C = g.C[z];
        colbase = bn; cstride = g.N1;
    } else {
        W = g.W2[z]; bias = g.Bi2[z]; C = g.C2[z];
        colbase = bn - g.N1; cstride = g.N2;
    }

    int tid = threadIdx.x;
    int lane = tid & 31, warp = tid >> 5;
    int wm = (warp & 1) << 4;        // 0,16
    int wn = (warp >> 1) << 4;       // 0..48
    int g8 = lane >> 2, tig = lane & 3;

    // loader roles: q selects which 8 k-values (float4 pair) this thread loads
    int q = tid & 3;
    int lrowB = tid >> 2;                 // 0..63 (W rows)
    int lrowA = tid >> 2;                 // 0..31 valid when tid < 128
    bool aLoader = tid < 128;
    int gmr = bm + lrowA;
    bool am_ok = aLoader && gmr < M;
    const float* Ap  = A + (size_t)(am_ok ? gmr : 0) * K;
    const float* A2p = A2 ? A2 + (size_t)(am_ok ? gmr : 0) * K : nullptr;
    const float* Wp  = W + (size_t)(colbase + lrowB) * K;

    float4 a0r, a1r, w0r, w1r;

    auto gload = [&](int k0) {
        a0r = make_float4(0.f, 0.f, 0.f, 0.f);
        a1r = a0r;
        if (am_ok) {
            a0r = *(const float4*)(Ap + k0 + 4 * q);
            a1r = *(const float4*)(Ap + k0 + 16 + 4 * q);
            if (A2p) {
                float4 t0 = *(const float4*)(A2p + k0 + 4 * q);
                float4 t1 = *(const float4*)(A2p + k0 + 16 + 4 * q);
                a0r.x += t0.x; a0r.y += t0.y; a0r.z += t0.z; a0r.w += t0.w;
                a1r.x += t1.x; a1r.y += t1.y; a1r.z += t1.z; a1r.w += t1.w;
            }
        }
        w0r = *(const float4*)(Wp + k0 + 4 * q);
        w1r = *(const float4*)(Wp + k0 + 16 + 4 * q);
    };
    // store float4 (k = base..base+3) as 2 packed bf16x2 words at word offset base/2
    auto sstore = [&](int buf) {
        uint32_t h0, l0, h1, l1;
        if (aLoader) {
            uint32_t* ah = &AsH[buf][lrowA * RSW];
            uint32_t* al = &AsL[buf][lrowA * RSW];
            bf16_split2(a0r.x, a0r.y, h0, l0);
            bf16_split2(a0r.z, a0r.w, h1, l1);
            ah[2 * q]     = h0; al[2 * q]     = l0;
            ah[2 * q + 1] = h1; al[2 * q + 1] = l1;
            bf16_split2(a1r.x, a1r.y, h0, l0);
            bf16_split2(a1r.z, a1r.w, h1, l1);
            ah[8 + 2 * q]     = h0; al[8 + 2 * q]     = l0;
            ah[8 + 2 * q + 1] = h1; al[8 + 2 * q + 1] = l1;
        }
        uint32_t* wh = &WsH[buf][lrowB * RSW];
        uint32_t* wl = &WsL[buf][lrowB * RSW];
        bf16_split2(w0r.x, w0r.y, h0, l0);
        bf16_split2(w0r.z, w0r.w, h1, l1);
        wh[2 * q]     = h0; wl[2 * q]     = l0;
        wh[2 * q + 1] = h1; wl[2 * q + 1] = l1;
        bf16_split2(w1r.x, w1r.y, h0, l0);
        bf16_split2(w1r.z, w1r.w, h1, l1);
        wh[8 + 2 * q]     = h0; wl[8 + 2 * q]     = l0;
        wh[8 + 2 * q + 1] = h1; wl[8 + 2 * q + 1] = l1;
    };

    gload(0);
    sstore(0);
    __syncthreads();

    float4 accA[2], accB[2], accC[2];
    #pragma unroll
    for (int j = 0; j < 2; j++) {
        accA[j] = make_float4(0.f, 0.f, 0.f, 0.f);
        accB[j] = accA[j]; accC[j] = accA[j];
    }

    int T = K / BKt;
    for (int t = 0; t < T; t++) {
        int buf = t & 1;
        if (t + 1 < T) gload((t + 1) * BKt);

        const uint32_t* ah = AsH[buf];
        const uint32_t* al = AsL[buf];
        const uint32_t* wh = WsH[buf];
        const uint32_t* wl = WsL[buf];
        #pragma unroll
        for (int ks = 0; ks < 2; ks++) {          // two k16 steps per 32-k tile
            int ka = ks * 8 + tig;
            int ra0 = (wm + g8) * RSW + ka;
            int ra1 = (wm + g8 + 8) * RSW + ka;
            uint32_t ah0 = ah[ra0],     ah1 = ah[ra1];
            uint32_t ah2 = ah[ra0 + 4], ah3 = ah[ra1 + 4];
            uint32_t al0 = al[ra0],     al1 = al[ra1];
            uint32_t al2 = al[ra0 + 4], al3 = al[ra1 + 4];
            #pragma unroll
            for (int j = 0; j < 2; j++) {
                int rb = (wn + 8 * j + g8) * RSW + ka;
                uint32_t bh0 = wh[rb], bh1 = wh[rb + 4];
                uint32_t bl0 = wl[rb], bl1 = wl[rb + 4];
                mma_bf16(accA[j], ah0, ah1, ah2, ah3, bh0, bh1);
                mma_bf16(accB[j], ah0, ah1, ah2, ah3, bl0, bl1);
                mma_bf16(accC[j], al0, al1, al2, al3, bh0, bh1);
            }
        }

        if (t + 1 < T) {
            sstore(buf ^ 1);
            __syncthreads();
        }
    }

    int r0 = bm + wm + g8;
    int r1 = r0 + 8;
    #pragma unroll
    for (int j = 0; j < 2; j++) {
        int cl = colbase + wn + 8 * j + 2 * tig;
        float b0 = bias[cl], b1 = bias[cl + 1];
        float v00 = accA[j].x + accB[j].x + accC[j].x + b0;
        float v01 = accA[j].y + accB[j].y + accC[j].y + b1;
        float v10 = accA[j].z + accB[j].z + accC[j].z + b0;
        float v11 = accA[j].w + accB[j].w + accC[j].w + b1;
        if (relu) {
            v00 = fmaxf(v00, 0.f); v01 = fmaxf(v01, 0.f);
            v10 = fmaxf(v10, 0.f); v11 = fmaxf(v11, 0.f);
        }
        if (r0 < M) *(float2*)&C[(size_t)r0 * cstride + cl] = make_float2(v00, v01);
        if (r1 < M) *(float2*)&C[(size_t)r1 * cstride + cl] = make_float2(v10, v11);
    }
}

// ---------------- self-attention: per (b,h,z,qchunk), N=300, DH=32 ----------------
__global__ void attn_kernel(AttnArgs a) {
    const float scale = 0.17677669529663687f;
    int z = blockIdx.y;
    const float* __restrict__ qkv = a.qkv[z];
    float* __restrict__ out = a.out[z];

    int bh = blockIdx.x;
    int b = bh >> 3, h = bh & 7;
    int qbase = blockIdx.z * 60;
    __shared__ float Ks[NQ * 33];
    __shared__ float Ps[6][304];

    int tid = threadIdx.x;
    int w = tid >> 5, lane = tid & 31;

    for (int i = tid; i < NQ * 32; i += 192) {
        int k = i >> 5, c = i & 31;
        Ks[k * 33 + c] = qkv[(size_t)(b * NQ + k) * 768 + 256 + h * 32 + c];
    }
    __syncthreads();

    for (int q = qbase + w; q < qbase + 60; q += 6) {
        float qreg = qkv[(size_t)(b * NQ + q) * 768 + h * 32 + lane];
        float sj[10];
        float mx = -3.0e38f;
        #pragma unroll
        for (int j = 0; j < 10; j++) {
            int k = lane + 32 * j;
            int kk = (k < NQ) ? k : (NQ - 1);
            float acc = 0.f;
            #pragma unroll
            for (int c = 0; c < 32; c++)
                acc = fmaf(__shfl_sync(0xffffffffu, qreg, c), Ks[kk * 33 + c], acc);
            acc *= scale;
            sj[j] = (k < NQ) ? acc : -3.0e38f;
            mx = fmaxf(mx, sj[j]);
        }
        #pragma unroll
        for (int o = 16; o > 0; o >>= 1)
            mx = fmaxf(mx, __shfl_xor_sync(0xffffffffu, mx, o));
        float lsum = 0.f;
        float pj[10];
        #pragma unroll
        for (int j = 0; j < 10; j++) {
            int k = lane + 32 * j;
            pj[j] = (k < NQ) ? expf(sj[j] - mx) : 0.f;
            lsum += pj[j];
        }
        #pragma unroll
        for (int o = 16; o > 0; o >>= 1)
            lsum += __shfl_xor_sync(0xffffffffu, lsum, o);
        float inv = 1.f / lsum;
        #pragma unroll
        for (int j = 0; j < 10; j++) {
            int k = lane + 32 * j;
            if (k < NQ) Ps[w][k] = pj[j] * inv;
        }
        __syncwarp();
        float acc = 0.f;
        for (int k = 0; k < NQ; k++)
            acc = fmaf(Ps[w][k], qkv[(size_t)(b * NQ + k) * 768 + 512 + h * 32 + lane], acc);
        out[(size_t)(b * NQ + q) * D + h * 32 + lane] = acc;
        __syncwarp();
    }
}

// ---------------- layernorm: warp-per-row, barrier-free ----------------
__device__ __forceinline__ void ln_row(float4 v0, float4 v1,
                                       const float* __restrict__ g,
                                       const float* __restrict__ b,
                                       int lane, float* __restrict__ yout) {
    float s  = v0.x + v0.y + v0.z + v0.w + v1.x + v1.y + v1.z + v1.w;
    float s2 = v0.x*v0.x + v0.y*v0.y + v0.z*v0.z + v0.w*v0.w
             + v1.x*v1.x + v1.y*v1.y + v1.z*v1.z + v1.w*v1.w;
    #pragma unroll
    for (int o = 16; o > 0; o >>= 1) {
        s  += __shfl_xor_sync(0xffffffffu, s, o);
        s2 += __shfl_xor_sync(0xffffffffu, s2, o);
    }
    float mean = s * (1.f / D);
    float var = s2 * (1.f / D) - mean * mean;
    float rstd = rsqrtf(var + 1e-5f);

    const float4* gp = (const float4*)g;
    const float4* bp = (const float4*)b;
    float4 g0 = gp[lane], g1 = gp[32 + lane];
    float4 b0 = bp[lane], b1 = bp[32 + lane];
    float4 y0, y1;
    y0.x = (v0.x - mean) * rstd * g0.x + b0.x;
    y0.y = (v0.y - mean) * rstd * g0.y + b0.y;
    y0.z = (v0.z - mean) * rstd * g0.z + b0.z;
    y0.w = (v0.w - mean) * rstd * g0.w + b0.w;
    y1.x = (v1.x - mean) * rstd * g1.x + b1.x;
    y1.y = (v1.y - mean) * rstd * g1.y + b1.y;
    y1.z = (v1.z - mean) * rstd * g1.z + b1.z;
    y1.w = (v1.w - mean) * rstd * g1.w + b1.w;
    float4* yp = (float4*)yout;
    yp[lane] = y0;
    yp[32 + lane] = y1;
}

__global__ __launch_bounds__(256)
void ln_kernel(LnArgs a) {
    int z = blockIdx.y;
    int w = threadIdx.x >> 5, lane = threadIdx.x & 31;
    int row = blockIdx.x * 8 + w;
    size_t base = (size_t)row * D;

    const float4* xp = (const float4*)(a.x[z] + base);
    float4 v0 = xp[lane];
    float4 v1 = xp[32 + lane];
    if (a.r[z]) {
        const float4* rp = (const float4*)(a.r[z] + base);
        float4 r0 = rp[lane], r1 = rp[32 + lane];
        v0.x += r0.x; v0.y += r0.y; v0.z += r0.z; v0.w += r0.w;
        v1.x += r1.x; v1.y += r1.y; v1.z += r1.z; v1.w += r1.w;
    }
    ln_row(v0, v1, a.g[z], a.b[z], lane, a.y[z] + base);
}

// ---------------- fused cross residual + norm1 LNs ----------------
__global__ __launch_bounds__(256)
void crossln_kernel(const float* __restrict__ tgt2T, const float* __restrict__ t2R,
                    const float* __restrict__ t2T,
                    const float* __restrict__ g0, const float* __restrict__ b0,
                    const float* __restrict__ g1, const float* __restrict__ b1,
                    float* __restrict__ x0, float* __restrict__ x1) {
    int w = threadIdx.x >> 5, lane = threadIdx.x & 31;
    int row = blockIdx.x * 8 + w;
    size_t base = (size_t)row * D;

    const float4* ap = (const float4*)(tgt2T + base);
    const float4* bp = (const float4*)(t2R + base);
    const float4* cp = (const float4*)(t2T + base);
    float4 r0 = ap[lane], r1 = ap[32 + lane];
    float4 q0 = bp[lane], q1 = bp[32 + lane];
    r0.x += q0.x; r0.y += q0.y; r0.z += q0.z; r0.w += q0.w;
    r1.x += q1.x; r1.y += q1.y; r1.z += q1.z; r1.w += q1.w;
    float4 t0 = cp[lane], t1 = cp[32 + lane];
    t0.x += r0.x; t0.y += r0.y; t0.z += r0.z; t0.w += r0.w;
    t1.x += r1.x; t1.y += r1.y; t1.z += r1.z; t1.w += r1.w;

    ln_row(r0, r1, g0, b0, lane, x0 + base);
    ln_row(t0, t1, g1, b1, lane, x1 + base);
}

// ---------------- deformable sampling + fused softmax + fused head projection ----------------
__global__ __launch_bounds__(256)
void msdeform_kernel(MsdArgs ar) {
    const int Hs[4]  = {100, 50, 25, 13};
    const int Wls[4] = {134, 67, 34, 17};
    const int S0[4]  = {0, 13400, 16750, 17600};

    int z = blockIdx.y;
    const float* __restrict__ src = ar.src[z];
    const float* __restrict__ off = ar.off[z];
    const float* __restrict__ aw  = ar.aw[z];
    const float* __restrict__ ref = ar.ref[z];
    const float* __restrict__ valwT = ar.wT[z];
    const float* __restrict__ valb  = ar.vb[z];
    float* __restrict__ samp = ar.samp[z];

    __shared__ float sh_s[QB][NH][256];
    __shared__ float sh_ws[QB][NH];

    int h = threadIdx.x >> 5, lane = threadIdx.x & 31;
    int bq0 = blockIdx.x * QB;
    int b = bq0 / NQ;

    for (int qq = 0; qq < QB; qq++) {
        int bq = bq0 + qq;

        float offv = off[(size_t)bq * 256 + h * 32 + lane];
        float awv  = (lane < 16) ? aw[(size_t)bq * 128 + h * 16 + lane] : -3.0e38f;
        float refv = (lane < 8) ? ref[(size_t)bq * 8 + lane] : 0.f;

        float m = awv;
        #pragma unroll
        for (int o = 8; o > 0; o >>= 1)
            m = fmaxf(m, __shfl_xor_sync(0xffffffffu, m, o));
        float e = (lane < 16) ? expf(awv - m) : 0.f;
        float es = e;
        #pragma unroll
        for (int o = 8; o > 0; o >>= 1)
            es += __shfl_xor_sync(0xffffffffu, es, o);
        float aws = e / es;

        float acc[8] = {};
        float wsum = 0.f;

        #pragma unroll
        for (int l = 0; l < 4; l++) {
            float rx = __shfl_sync(0xffffffffu, refv, 2 * l);
            float ry = __shfl_sync(0xffffffffu, refv, 2 * l + 1);
            int Wl = Wls[l], Hl = Hs[l];
            float Wf = (float)Wl, Hf = (float)Hl;
            int rowbase = b * LTOT + S0[l];
            #pragma unroll
            for (int p = 0; p < 4; p++) {
                float ox = __shfl_sync(0xffffffffu, offv, (l * 4 + p) * 2);
                float oy = __shfl_sync(0xffffffffu, offv, (l * 4 + p) * 2 + 1);
                float a  = __shfl_sync(0xffffffffu, aws, l * 4 + p);
                float x = fmaf(rx, Wf, ox) - 0.5f;
                float y = fmaf(ry, Hf, oy) - 0.5f;
                float x0f = floorf(x), y0f = floorf(y);
                int x0 = (int)x0f, y0 = (int)y0f;
                float wx = x - x0f, wy = y - y0f;
                float tw[4] = {(1.f - wx) * (1.f - wy) * a, wx * (1.f - wy) * a,
                               (1.f - wx) * wy * a,          wx * wy * a};
                int xs[4] = {x0, x0 + 1, x0,     x0 + 1};
                int ys[4] = {y0, y0,     y0 + 1, y0 + 1};
                #pragma unroll
                for (int t = 0; t < 4; t++) {
                    int xi = xs[t], yi = ys[t];
                    if (xi < 0 || xi >= Wl || yi < 0 || yi >= Hl) continue;
                    const float4* pr = (const float4*)(src + ((size_t)rowbase + (size_t)yi * Wl + xi) * 256);
                    float w = tw[t];
                    float4 v0 = __ldg(pr + lane);
                    float4 v1 = __ldg(pr + 32 + lane);
                    acc[0] = fmaf(w, v0.x, acc[0]);
                    acc[1] = fmaf(w, v0.y, acc[1]);
                    acc[2] = fmaf(w, v0.z, acc[2]);
                    acc[3] = fmaf(w, v0.w, acc[3]);
                    acc[4] = fmaf(w, v1.x, acc[4]);
                    acc[5] = fmaf(w, v1.y, acc[5]);
                    acc[6] = fmaf(w, v1.z, acc[6]);
                    acc[7] = fmaf(w, v1.w, acc[7]);
                    wsum += w;
                }
            }
        }
        float4* sp = (float4*)&sh_s[qq][h][0];
        sp[lane]      = make_float4(acc[0], acc[1], acc[2], acc[3]);
        sp[32 + lane] = make_float4(acc[4], acc[5], acc[6], acc[7]);
        if (lane == 0) sh_ws[qq][h] = wsum;
    }
    __syncthreads();

    int n = threadIdx.x;
    int h2 = n >> 5;
    float t0 = 0.f, t1 = 0.f, t2 = 0.f, t3 = 0.f;
    #pragma unroll 4
    for (int c = 0; c < 256; c++) {
        float w = __ldg(valwT + (size_t)c * 256 + n);
        t0 = fmaf(sh_s[0][h2][c], w, t0);
        t1 = fmaf(sh_s[1][h2][c], w, t1);
        t2 = fmaf(sh_s[2][h2][c], w, t2);
        t3 = fmaf(sh_s[3][h2][c], w, t3);
    }
    float vb = valb[n];
    samp[(size_t)(bq0 + 0) * 256 + n] = t0 + sh_ws[0][h2] * vb;
    samp[(size_t)(bq0 + 1) * 256 + n] = t1 + sh_ws[1][h2] * vb;
    samp[(size_t)(bq0 + 2) * 256 + n] = t2 + sh_ws[2][h2] * vb;
    samp[(size_t)(bq0 + 3) * 256 + n] = t3 + sh_ws[3][h2] * vb;
}

// ---------------- host side ----------------
static void gemm2(GPtrs& g, int M, int K, int relu) {
    int Ntot = g.N1 + g.N2;
    dim3 grid(Ntot / BNt, (M + BMt - 1) / BMt, 2);
    tgemm_kernel<<<grid, 256>>>(g, M, K, relu);
}

extern "C" void kernel_launch(void* const* d_in, const int* in_sizes, int n_in,
                              void* d_out_v, int out_size) {
    const float* tgt[2] = {(const float*)d_in[0], (const float*)d_in[1]};
    const float* pos[2] = {(const float*)d_in[2], (const float*)d_in[3]};
    const float* refp[2] = {(const float*)d_in[4], (const float*)d_in[5]};
    const float* src[2] = {(const float*)d_in[6], (const float*)d_in[7]};
    const float* sa_in_w  = (const float*)d_in[8];
    const float* sa_in_b  = (const float*)d_in[9];
    const float* sa_out_w = (const float*)d_in[10];
    const float* sa_out_b = (const float*)d_in[11];
    const float* ln_w     = (const float*)d_in[12];
    const float* ln_b     = (const float*)d_in[13];
    const float* ffn_w1   = (const float*)d_in[14];
    const float* ffn_b1   = (const float*)d_in[15];
    const float* ffn_w2   = (const float*)d_in[16];
    const float* ffn_b2   = (const float*)d_in[17];
    const float* val_w    = (const float*)d_in[18];
    const float* val_b    = (const float*)d_in[19];
    const float* off_w    = (const float*)d_in[20];
    const float* off_b    = (const float*)d_in[21];
    const float* aw_w     = (const float*)d_in[22];
    const float* aw_b     = (const float*)d_in[23];
    const float* cout_w   = (const float*)d_in[24];
    const float* cout_b   = (const float*)d_in[25];
    float* out = (float*)d_out_v;

    float *p_qkv, *p_attn, *p_sa, *p_tgt2, *p_off, *p_aw,
          *p_samp, *p_ffn, *p_y, *p_x, *p_wT;
    cudaGetSymbolAddress((void**)&p_qkv,  g_qkv);
    cudaGetSymbolAddress((void**)&p_attn, g_attn);
    cudaGetSymbolAddress((void**)&p_sa,   g_sa);
    cudaGetSymbolAddress((void**)&p_tgt2, g_tgt2);
    cudaGetSymbolAddress((void**)&p_off,  g_off);
    cudaGetSymbolAddress((void**)&p_aw,   g_aw);
    cudaGetSymbolAddress((void**)&p_samp, g_samp);
    cudaGetSymbolAddress((void**)&p_ffn,  g_ffn);
    cudaGetSymbolAddress((void**)&p_y,    g_y);
    cudaGetSymbolAddress((void**)&p_x,    g_x);
    cudaGetSymbolAddress((void**)&p_wT,   g_wT);

    // ---- val_w transpose (independent; issue first)
    transpose256_kernel<<<dim3(8, 8, 2), dim3(32, 8)>>>(val_w, p_wT);

    // ---- fused qkv projection: q,k use tgt+pos (cols <512), v uses tgt
    {
        GPtrs g = {};
        g.A[0] = tgt[0]; g.A[1] = tgt[1];
        g.A2[0] = pos[0]; g.A2[1] = pos[1];
        g.W[0] = sa_in_w; g.W[1] = sa_in_w + (size_t)3 * D * D;
        g.Bi[0] = sa_in_b; g.Bi[1] = sa_in_b + 3 * D;
        g.C[0] = p_qkv; g.C[1] = p_qkv + (size_t)BNQ * 768;
        g.N1 = 768; g.N2 = 0; g.a2lim = 512;
        gemm2(g, BNQ, D, 0);
    }
    // ---- attention (5 q-chunks)
    {
        AttnArgs a = {{p_qkv, p_qkv + (size_t)BNQ * 768}, {p_attn, p_attn + NE}};
        attn_kernel<<<dim3(BS * NH, 2, 5), 192>>>(a);
    }
    // ---- out projection
    {
        GPtrs g = {};
        g.A[0] = p_attn; g.A[1] = p_attn + NE;
        g.W[0] = sa_out_w; g.W[1] = sa_out_w + (size_t)D * D;
        g.Bi[0] = sa_out_b; g.Bi[1] = sa_out_b + D;
        g.C[0] = p_sa; g.C[1] = p_sa + NE;
        g.N1 = 256; g.N2 = 0; g.a2lim = 0;
        gemm2(g, BNQ, D, 0);
    }
    // ---- tgt2 = LN(tgt + sa)  (norm2)
    {
        LnArgs a = {{tgt[0], tgt[1]}, {p_sa, p_sa + NE},
                    {ln_w + 1 * D, ln_w + 4 * D}, {ln_b + 1 * D, ln_b + 4 * D},
                    {p_tgt2, p_tgt2 + NE}};
        ln_kernel<<<dim3(BNQ / 8, 2), 256>>>(a);
    }
    // ---- fused offsets|aw projection from (tgt2 + pos)
    {
        GPtrs g = {};
        g.A[0] = p_tgt2; g.A[1] = p_tgt2 + NE;
        g.A2[0] = pos[0]; g.A2[1] = pos[1];
        g.W[0] = off_w; g.W[1] = off_w + (size_t)256 * D;
        g.W2[0] = aw_w; g.W2[1] = aw_w + (size_t)128 * D;
        g.Bi[0] = off_b; g.Bi[1] = off_b + 256;
        g.Bi2[0] = aw_b; g.Bi2[1] = aw_b + 128;
        g.C[0] = p_off; g.C[1] = p_off + NE;
        g.C2[0] = p_aw; g.C2[1] = p_aw + (size_t)BNQ * 128;
        g.N1 = 256; g.N2 = 128; g.a2lim = 384;
        gemm2(g, BNQ, D, 0);
    }

    // ---- sampling: z-batched, softmax fused in-kernel
    {
        MsdArgs a = {{src[1], src[0]},
                     {p_off, p_off + NE},
                     {p_aw, p_aw + (size_t)BNQ * 128},
                     {refp[0], refp[1]},
                     {p_wT, p_wT + (size_t)D * D},
                     {val_b, val_b + D},
                     {p_samp, p_samp + NE}};
        msdeform_kernel<<<dim3(BNQ / QB, 2), 256>>>(a);
    }
    // ---- cout projection -> output regions F_RGB / F_T
    {
        GPtrs g = {};
        g.A[0] = p_samp; g.A[1] = p_samp + NE;
        g.W[0] = cout_w; g.W[1] = cout_w + (size_t)D * D;
        g.Bi[0] = cout_b; g.Bi[1] = cout_b + D;
        g.C[0] = out + (size_t)2 * NE; g.C[1] = out + (size_t)3 * NE;
        g.N1 = 256; g.N2 = 0; g.a2lim = 0;
        gemm2(g, BNQ, D, 0);
    }

    // ---- fused cross residuals + norm1 LNs
    crossln_kernel<<<BNQ / 8, 256>>>(p_tgt2 + NE, out + (size_t)2 * NE, out + (size_t)3 * NE,
                                     ln_w + 0 * D, ln_b + 0 * D, ln_w + 3 * D, ln_b + 3 * D,
                                     p_x, p_x + NE);

    // ---- FFNs
    {
        GPtrs g = {};
        g.A[0] = p_x; g.A[1] = p_x + NE;
        g.W[0] = ffn_w1; g.W[1] = ffn_w1 + (size_t)DFF * D;
        g.Bi[0] = ffn_b1; g.Bi[1] = ffn_b1 + DFF;
        g.C[0] = p_ffn; g.C[1] = p_ffn + (size_t)BNQ * DFF;
        g.N1 = 1024; g.N2 = 0; g.a2lim = 0;
        gemm2(g, BNQ, D, 1);
    }
    {
        GPtrs g = {};
        g.A[0] = p_ffn; g.A[1] = p_ffn + (size_t)BNQ * DFF;
        g.W[0] = ffn_w2; g.W[1] = ffn_w2 + (size_t)D * DFF;
        g.Bi[0] = ffn_b2; g.Bi[1] = ffn_b2 + D;
        g.C[0] = p_y; g.C[1] = p_y + NE;
        g.N1 = 256; g.N2 = 0; g.a2lim = 0;
        gemm2(g, BNQ, DFF, 0);
    }
    {
        LnArgs a = {{p_x, p_x + NE}, {p_y, p_y + NE},
                    {ln_w + 2 * D, ln_w + 5 * D}, {ln_b + 2 * D, ln_b + 5 * D},
                    {out, out + NE}};
        ln_kernel<<<dim3(BNQ / 8, 2), 256>>>(a);
    }
}

// round 10
// speedup vs baseline: 4.0287x; 1.0004x over previous
#include <cuda_runtime.h>
#include <cuda_bf16.h>
#include <math.h>
#include <stdint.h>

// ---------------- problem constants ----------------
#define BS   4
#define NQ   300
#define D    256
#define NH   8
#define DH   32
#define NL   4
#define NP   4
#define DFF  1024
#define LTOT 17821
#define BNQ  (BS*NQ)          // 1200
#define QB   4                // queries per msdeform block
#define NE   (BNQ*D)          // 307200

// ---------------- scratch (device globals; no allocation allowed) ----------------
__device__ float g_qkv [2][BNQ*768];
__device__ float g_attn[2][BNQ*D];
__device__ float g_sa  [2][BNQ*D];
__device__ float g_tgt2[2][BNQ*D];
__device__ float g_off [2][BNQ*D];
__device__ float g_aw  [2*BNQ*(NH*NL*NP)];
__device__ float g_samp[2][BNQ*D];
__device__ float g_ffn [2][BNQ*DFF];
__device__ float g_y   [2][BNQ*D];
__device__ float g_x   [2][BNQ*D];
__device__ float g_wT  [2][D*D];

// ---------------- pointer-pack structs (passed by value) ----------------
struct GPtrs {
    const float* A[2];
    const float* A2[2];
    const float* W[2];
    const float* W2[2];
    const float* Bi[2];
    const float* Bi2[2];
    float*       C[2];
    float*       C2[2];
    int N1, N2, a2lim;
};
struct LnArgs {
    const float* x[2];
    const float* r[2];
    const float* g[2];
    const float* b[2];
    float*       y[2];
};
struct AttnArgs {
    const float* qkv[2];
    float*       out[2];
};
struct MsdArgs {
    const float* src[2];
    const float* off[2];
    const float* aw[2];
    const float* ref[2];
    const float* wT[2];
    const float* vb[2];
    float*       samp[2];
};

// ---------------- weight transpose 256x256, z-batched ----------------
__global__ void transpose256_kernel(const float* __restrict__ w, float* __restrict__ wT) {
    __shared__ float tile[32][33];
    int z = blockIdx.z;
    const float* ws = w + (size_t)z * D * D;
    float* wd = wT + (size_t)z * D * D;
    int bx = blockIdx.x * 32, by = blockIdx.y * 32;
    int tx = threadIdx.x, ty = threadIdx.y;
    #pragma unroll
    for (int i = 0; i < 32; i += 8)
        tile[ty + i][tx] = ws[(size_t)(by + ty + i) * D + bx + tx];
    __syncthreads();
    #pragma unroll
    for (int i = 0; i < 32; i += 8)
        wd[(size_t)(bx + ty + i) * D + by + tx] = tile[tx][ty + i];
}

// ---------------- bf16x3 tensor-core GEMM: 128 threads, 32x32 tile ----------------
// C[M,N] = (A (+A2))[M,K] @ [W|W2][N,K]^T + bias (+relu).
// fp32-grade accuracy via bf16 hi/lo split: acc = aH*bH + aH*bL + aL*bH.
#define BMt 32
#define BNt 32
#define BKt 32
#define RSW 20   // row stride in 32-bit words (conflict-free fragment loads)

#define ASZW (BMt * RSW)    // 640 words per buffer (A and W identical size now)

__device__ __forceinline__ void bf16_split2(float x, float y, uint32_t& hw, uint32_t& lw) {
    uint32_t h;
    asm("cvt.rn.bf16x2.f32 %0, %1, %2;" : "=r"(h) : "f"(y), "f"(x));  // hi=y, lo=x
    float hx = __uint_as_float(h << 16);
    float hy = __uint_as_float(h & 0xFFFF0000u);
    float lx = x - hx, ly = y - hy;
    asm("cvt.rn.bf16x2.f32 %0, %1, %2;" : "=r"(lw) : "f"(ly), "f"(lx));
    hw = h;
}

__device__ __forceinline__ void mma_bf16(float4& d, uint32_t a0, uint32_t a1,
                                         uint32_t a2, uint32_t a3,
                                         uint32_t b0, uint32_t b1) {
    asm volatile(
        "mma.sync.aligned.m16n8k16.row.col.f32.bf16.bf16.f32 "
        "{%0,%1,%2,%3}, {%4,%5,%6,%7}, {%8,%9}, {%0,%1,%2,%3};\n"
        : "+f"(d.x), "+f"(d.y), "+f"(d.z), "+f"(d.w)
        : "r"(a0), "r"(a1), "r"(a2), "r"(a3), "r"(b0), "r"(b1));
}

__global__ __launch_bounds__(128)
void tgemm_kernel(GPtrs g, int M, int K, int relu) {
    __shared__ uint32_t AsH[2][ASZW];
    __shared__ uint32_t AsL[2][ASZW];
    __shared__ uint32_t WsH[2][ASZW];
    __shared__ uint32_t WsL[2][ASZW];

    int z = blockIdx.z;
    int bm = blockIdx.y * BMt, bn = blockIdx.x * BNt;

    const float* __restrict__ A  = g.A[z];
    const float* __restrict__ A2 = (bn < g.a2lim) ? g.A2[z] : nullptr;
    const float* __restrict__ W;
    const float* __restrict__ bias;
    float* __restrict__ C;
    int colbase, cstride;
    if (bn < g.N1) {
        W = g.W[z];  bias = g.Bi[z];  C = g.C[z];
        colbase = bn; cstride = g.N1;
    } else {
        W = g.W2[z]; bias = g.Bi2[z]; C = g.C2[z];
        colbase = bn - g.N1; cstride = g.N2;
    }

    int tid = threadIdx.x;
    int lane = tid & 31, warp = tid >> 5;     // 4 warps
    int wm = (warp & 1) << 4;                 // 0,16
    int wn = (warp >> 1) << 4;                // 0,16
    int g8 = lane >> 2, tig = lane & 3;

    // loader roles: all 128 threads load one A row + one W row (32 rows each)
    int q = tid & 3;
    int lrow = tid >> 2;                      // 0..31
    int gmr = bm + lrow;
    bool am_ok = gmr < M;
    const float* Ap  = A + (size_t)(am_ok ? gmr : 0) * K;
    const float* A2p = A2 ? A2 + (size_t)(am_ok ? gmr : 0) * K : nullptr;
    const float* Wp  = W + (size_t)(colbase + lrow) * K;

    float4 a0r, a1r, w0r, w1r;

    auto gload = [&](int k0) {
        a0r = make_float4(0.f, 0.f, 0.f, 0.f);
        a1r = a0r;
        if (am_ok) {
            a0r = *(const float4*)(Ap + k0 + 4 * q);
            a1r = *(const float4*)(Ap + k0 + 16 + 4 * q);
            if (A2p) {
                float4 t0 = *(const float4*)(A2p + k0 + 4 * q);
                float4 t1 = *(const float4*)(A2p + k0 + 16 + 4 * q);
                a0r.x += t0.x; a0r.y += t0.y; a0r.z += t0.z; a0r.w += t0.w;
                a1r.x += t1.x; a1r.y += t1.y; a1r.z += t1.z; a1r.w += t1.w;
            }
        }
        w0r = *(const float4*)(Wp + k0 + 4 * q);
        w1r = *(const float4*)(Wp + k0 + 16 + 4 * q);
    };
    auto sstore = [&](int buf) {
        uint32_t h0, l0, h1, l1;
        uint32_t* ah = &AsH[buf][lrow * RSW];
        uint32_t* al = &AsL[buf][lrow * RSW];
        bf16_split2(a0r.x, a0r.y, h0, l0);
        bf16_split2(a0r.z, a0r.w, h1, l1);
        ah[2 * q]     = h0; al[2 * q]     = l0;
        ah[2 * q + 1] = h1; al[2 * q + 1] = l1;
        bf16_split2(a1r.x, a1r.y, h0, l0);
        bf16_split2(a1r.z, a1r.w, h1, l1);
        ah[8 + 2 * q]     = h0; al[8 + 2 * q]     = l0;
        ah[8 + 2 * q + 1] = h1; al[8 + 2 * q + 1] = l1;

        uint32_t* wh = &WsH[buf][lrow * RSW];
        uint32_t* wl = &WsL[buf][lrow * RSW];
        bf16_split2(w0r.x, w0r.y, h0, l0);
        bf16_split2(w0r.z, w0r.w, h1, l1);
        wh[2 * q]     = h0; wl[2 * q]     = l0;
        wh[2 * q + 1] = h1; wl[2 * q + 1] = l1;
        bf16_split2(w1r.x, w1r.y, h0, l0);
        bf16_split2(w1r.z, w1r.w, h1, l1);
        wh[8 + 2 * q]     = h0; wl[8 + 2 * q]     = l0;
        wh[8 + 2 * q + 1] = h1; wl[8 + 2 * q + 1] = l1;
    };

    gload(0);
    sstore(0);
    __syncthreads();

    float4 accA[2], accB[2], accC[2];
    #pragma unroll
    for (int j = 0; j < 2; j++) {
        accA[j] = make_float4(0.f, 0.f, 0.f, 0.f);
        accB[j] = accA[j]; accC[j] = accA[j];
    }

    int T = K / BKt;
    for (int t = 0; t < T; t++) {
        int buf = t & 1;
        if (t + 1 < T) gload((t + 1) * BKt);

        const uint32_t* ah = AsH[buf];
        const uint32_t* al = AsL[buf];
        const uint32_t* wh = WsH[buf];
        const uint32_t* wl = WsL[buf];
        #pragma unroll
        for (int ks = 0; ks < 2; ks++) {
            int ka = ks * 8 + tig;
            int ra0 = (wm + g8) * RSW + ka;
            int ra1 = (wm + g8 + 8) * RSW + ka;
            uint32_t ah0 = ah[ra0],     ah1 = ah[ra1];
            uint32_t ah2 = ah[ra0 + 4], ah3 = ah[ra1 + 4];
            uint32_t al0 = al[ra0],     al1 = al[ra1];
            uint32_t al2 = al[ra0 + 4], al3 = al[ra1 + 4];
            #pragma unroll
            for (int j = 0; j < 2; j++) {
                int rb = (wn + 8 * j + g8) * RSW + ka;
                uint32_t bh0 = wh[rb], bh1 = wh[rb + 4];
                uint32_t bl0 = wl[rb], bl1 = wl[rb + 4];
                mma_bf16(accA[j], ah0, ah1, ah2, ah3, bh0, bh1);
                mma_bf16(accB[j], ah0, ah1, ah2, ah3, bl0, bl1);
                mma_bf16(accC[j], al0, al1, al2, al3, bh0, bh1);
            }
        }

        if (t + 1 < T) {
            sstore(buf ^ 1);
            __syncthreads();
        }
    }

    int r0 = bm + wm + g8;
    int r1 = r0 + 8;
    #pragma unroll
    for (int j = 0; j < 2; j++) {
        int cl = colbase + wn + 8 * j + 2 * tig;
        float b0 = bias[cl], b1 = bias[cl + 1];
        float v00 = accA[j].x + accB[j].x + accC[j].x + b0;
        float v01 = accA[j].y + accB[j].y + accC[j].y + b1;
        float v10 = accA[j].z + accB[j].z + accC[j].z + b0;
        float v11 = accA[j].w + accB[j].w + accC[j].w + b1;
        if (relu) {
            v00 = fmaxf(v00, 0.f); v01 = fmaxf(v01, 0.f);
            v10 = fmaxf(v10, 0.f); v11 = fmaxf(v11, 0.f);
        }
        if (r0 < M) *(float2*)&C[(size_t)r0 * cstride + cl] = make_float2(v00, v01);
        if (r1 < M) *(float2*)&C[(size_t)r1 * cstride + cl] = make_float2(v10, v11);
    }
}

// ---------------- self-attention: per (b,h,z,qchunk), N=300, DH=32 ----------------
__global__ void attn_kernel(AttnArgs a) {
    const float scale = 0.17677669529663687f;
    int z = blockIdx.y;
    const float* __restrict__ qkv = a.qkv[z];
    float* __restrict__ out = a.out[z];

    int bh = blockIdx.x;
    int b = bh >> 3, h = bh & 7;
    int qbase = blockIdx.z * 60;
    __shared__ float Ks[NQ * 33];
    __shared__ float Ps[6][304];

    int tid = threadIdx.x;
    int w = tid >> 5, lane = tid & 31;

    for (int i = tid; i < NQ * 32; i += 192) {
        int k = i >> 5, c = i & 31;
        Ks[k * 33 + c] = qkv[(size_t)(b * NQ + k) * 768 + 256 + h * 32 + c];
    }
    __syncthreads();

    for (int q = qbase + w; q < qbase + 60; q += 6) {
        float qreg = qkv[(size_t)(b * NQ + q) * 768 + h * 32 + lane];
        float sj[10];
        float mx = -3.0e38f;
        #pragma unroll
        for (int j = 0; j < 10; j++) {
            int k = lane + 32 * j;
            int kk = (k < NQ) ? k : (NQ - 1);
            float acc = 0.f;
            #pragma unroll
            for (int c = 0; c < 32; c++)
                acc = fmaf(__shfl_sync(0xffffffffu, qreg, c), Ks[kk * 33 + c], acc);
            acc *= scale;
            sj[j] = (k < NQ) ? acc : -3.0e38f;
            mx = fmaxf(mx, sj[j]);
        }
        #pragma unroll
        for (int o = 16; o > 0; o >>= 1)
            mx = fmaxf(mx, __shfl_xor_sync(0xffffffffu, mx, o));
        float lsum = 0.f;
        float pj[10];
        #pragma unroll
        for (int j = 0; j < 10; j++) {
            int k = lane + 32 * j;
            pj[j] = (k < NQ) ? expf(sj[j] - mx) : 0.f;
            lsum += pj[j];
        }
        #pragma unroll
        for (int o = 16; o > 0; o >>= 1)
            lsum += __shfl_xor_sync(0xffffffffu, lsum, o);
        float inv = 1.f / lsum;
        #pragma unroll
        for (int j = 0; j < 10; j++) {
            int k = lane + 32 * j;
            if (k < NQ) Ps[w][k] = pj[j] * inv;
        }
        __syncwarp();
        float acc = 0.f;
        for (int k = 0; k < NQ; k++)
            acc = fmaf(Ps[w][k], qkv[(size_t)(b * NQ + k) * 768 + 512 + h * 32 + lane], acc);
        out[(size_t)(b * NQ + q) * D + h * 32 + lane] = acc;
        __syncwarp();
    }
}

// ---------------- layernorm helpers ----------------
__device__ __forceinline__ void ln_row(float4 v0, float4 v1,
                                       const float* __restrict__ g,
                                       const float* __restrict__ b,
                                       int lane, float* __restrict__ yout) {
    float s  = v0.x + v0.y + v0.z + v0.w + v1.x + v1.y + v1.z + v1.w;
    float s2 = v0.x*v0.x + v0.y*v0.y + v0.z*v0.z + v0.w*v0.w
             + v1.x*v1.x + v1.y*v1.y + v1.z*v1.z + v1.w*v1.w;
    #pragma unroll
    for (int o = 16; o > 0; o >>= 1) {
        s  += __shfl_xor_sync(0xffffffffu, s, o);
        s2 += __shfl_xor_sync(0xffffffffu, s2, o);
    }
    float mean = s * (1.f / D);
    float var = s2 * (1.f / D) - mean * mean;
    float rstd = rsqrtf(var + 1e-5f);

    const float4* gp = (const float4*)g;
    const float4* bp = (const float4*)b;
    float4 g0 = gp[lane], g1 = gp[32 + lane];
    float4 b0 = bp[lane], b1 = bp[32 + lane];
    float4 y0, y1;
    y0.x = (v0.x - mean) * rstd * g0.x + b0.x;
    y0.y = (v0.y - mean) * rstd * g0.y + b0.y;
    y0.z = (v0.z - mean) * rstd * g0.z + b0.z;
    y0.w = (v0.w - mean) * rstd * g0.w + b0.w;
    y1.x = (v1.x - mean) * rstd * g1.x + b1.x;
    y1.y = (v1.y - mean) * rstd * g1.y + b1.y;
    y1.z = (v1.z - mean) * rstd * g1.z + b1.z;
    y1.w = (v1.w - mean) * rstd * g1.w + b1.w;
    float4* yp = (float4*)yout;
    yp[lane] = y0;
    yp[32 + lane] = y1;
}

__global__ __launch_bounds__(256)
void ln_kernel(LnArgs a) {
    int z = blockIdx.y;
    int w = threadIdx.x >> 5, lane = threadIdx.x & 31;
    int row = blockIdx.x * 8 + w;
    size_t base = (size_t)row * D;

    const float4* xp = (const float4*)(a.x[z] + base);
    float4 v0 = xp[lane];
    float4 v1 = xp[32 + lane];
    if (a.r[z]) {
        const float4* rp = (const float4*)(a.r[z] + base);
        float4 r0 = rp[lane], r1 = rp[32 + lane];
        v0.x += r0.x; v0.y += r0.y; v0.z += r0.z; v0.w += r0.w;
        v1.x += r1.x; v1.y += r1.y; v1.z += r1.z; v1.w += r1.w;
    }
    ln_row(v0, v1, a.g[z], a.b[z], lane, a.y[z] + base);
}

// ---------------- fused cross residual + norm1 LNs ----------------
__global__ __launch_bounds__(256)
void crossln_kernel(const float* __restrict__ tgt2T, const float* __restrict__ t2R,
                    const float* __restrict__ t2T,
                    const float* __restrict__ g0, const float* __restrict__ b0,
                    const float* __restrict__ g1, const float* __restrict__ b1,
                    float* __restrict__ x0, float* __restrict__ x1) {
    int w = threadIdx.x >> 5, lane = threadIdx.x & 31;
    int row = blockIdx.x * 8 + w;
    size_t base = (size_t)row * D;

    const float4* ap = (const float4*)(tgt2T + base);
    const float4* bp = (const float4*)(t2R + base);
    const float4* cp = (const float4*)(t2T + base);
    float4 r0 = ap[lane], r1 = ap[32 + lane];
    float4 q0 = bp[lane], q1 = bp[32 + lane];
    r0.x += q0.x; r0.y += q0.y; r0.z += q0.z; r0.w += q0.w;
    r1.x += q1.x; r1.y += q1.y; r1.z += q1.z; r1.w += q1.w;
    float4 t0 = cp[lane], t1 = cp[32 + lane];
    t0.x += r0.x; t0.y += r0.y; t0.z += r0.z; t0.w += r0.w;
    t1.x += r1.x; t1.y += r1.y; t1.z += r1.z; t1.w += r1.w;

    ln_row(r0, r1, g0, b0, lane, x0 + base);
    ln_row(t0, t1, g1, b1, lane, x1 + base);
}

// ---------------- deformable sampling + fused softmax + fused head projection ----------------
__global__ __launch_bounds__(256)
void msdeform_kernel(MsdArgs ar) {
    const int Hs[4]  = {100, 50, 25, 13};
    const int Wls[4] = {134, 67, 34, 17};
    const int S0[4]  = {0, 13400, 16750, 17600};

    int z = blockIdx.y;
    const float* __restrict__ src = ar.src[z];
    const float* __restrict__ off = ar.off[z];
    const float* __restrict__ aw  = ar.aw[z];
    const float* __restrict__ ref = ar.ref[z];
    const float* __restrict__ valwT = ar.wT[z];
    const float* __restrict__ valb  = ar.vb[z];
    float* __restrict__ samp = ar.samp[z];

    __shared__ float sh_s[QB][NH][256];
    __shared__ float sh_ws[QB][NH];

    int h = threadIdx.x >> 5, lane = threadIdx.x & 31;
    int bq0 = blockIdx.x * QB;
    int b = bq0 / NQ;

    for (int qq = 0; qq < QB; qq++) {
        int bq = bq0 + qq;

        float offv = off[(size_t)bq * 256 + h * 32 + lane];
        float awv  = (lane < 16) ? aw[(size_t)bq * 128 + h * 16 + lane] : -3.0e38f;
        float refv = (lane < 8) ? ref[(size_t)bq * 8 + lane] : 0.f;

        float m = awv;
        #pragma unroll
        for (int o = 8; o > 0; o >>= 1)
            m = fmaxf(m, __shfl_xor_sync(0xffffffffu, m, o));
        float e = (lane < 16) ? expf(awv - m) : 0.f;
        float es = e;
        #pragma unroll
        for (int o = 8; o > 0; o >>= 1)
            es += __shfl_xor_sync(0xffffffffu, es, o);
        float aws = e / es;

        float acc[8] = {};
        float wsum = 0.f;

        #pragma unroll
        for (int l = 0; l < 4; l++) {
            float rx = __shfl_sync(0xffffffffu, refv, 2 * l);
            float ry = __shfl_sync(0xffffffffu, refv, 2 * l + 1);
            int Wl = Wls[l], Hl = Hs[l];
            float Wf = (float)Wl, Hf = (float)Hl;
            int rowbase = b * LTOT + S0[l];
            #pragma unroll
            for (int p = 0; p < 4; p++) {
                float ox = __shfl_sync(0xffffffffu, offv, (l * 4 + p) * 2);
                float oy = __shfl_sync(0xffffffffu, offv, (l * 4 + p) * 2 + 1);
                float a  = __shfl_sync(0xffffffffu, aws, l * 4 + p);
                float x = fmaf(rx, Wf, ox) - 0.5f;
                float y = fmaf(ry, Hf, oy) - 0.5f;
                float x0f = floorf(x), y0f = floorf(y);
                int x0 = (int)x0f, y0 = (int)y0f;
                float wx = x - x0f, wy = y - y0f;
                float tw[4] = {(1.f - wx) * (1.f - wy) * a, wx * (1.f - wy) * a,
                               (1.f - wx) * wy * a,          wx * wy * a};
                int xs[4] = {x0, x0 + 1, x0,     x0 + 1};
                int ys[4] = {y0, y0,     y0 + 1, y0 + 1};
                #pragma unroll
                for (int t = 0; t < 4; t++) {
                    int xi = xs[t], yi = ys[t];
                    if (xi < 0 || xi >= Wl || yi < 0 || yi >= Hl) continue;
                    const float4* pr = (const float4*)(src + ((size_t)rowbase + (size_t)yi * Wl + xi) * 256);
                    float w = tw[t];
                    float4 v0 = __ldg(pr + lane);
                    float4 v1 = __ldg(pr + 32 + lane);
                    acc[0] = fmaf(w, v0.x, acc[0]);
                    acc[1] = fmaf(w, v0.y, acc[1]);
                    acc[2] = fmaf(w, v0.z, acc[2]);
                    acc[3] = fmaf(w, v0.w, acc[3]);
                    acc[4] = fmaf(w, v1.x, acc[4]);
                    acc[5] = fmaf(w, v1.y, acc[5]);
                    acc[6] = fmaf(w, v1.z, acc[6]);
                    acc[7] = fmaf(w, v1.w, acc[7]);
                    wsum += w;
                }
            }
        }
        float4* sp = (float4*)&sh_s[qq][h][0];
        sp[lane]      = make_float4(acc[0], acc[1], acc[2], acc[3]);
        sp[32 + lane] = make_float4(acc[4], acc[5], acc[6], acc[7]);
        if (lane == 0) sh_ws[qq][h] = wsum;
    }
    __syncthreads();

    int n = threadIdx.x;
    int h2 = n >> 5;
    float t0 = 0.f, t1 = 0.f, t2 = 0.f, t3 = 0.f;
    #pragma unroll 4
    for (int c = 0; c < 256; c++) {
        float w = __ldg(valwT + (size_t)c * 256 + n);
        t0 = fmaf(sh_s[0][h2][c], w, t0);
        t1 = fmaf(sh_s[1][h2][c], w, t1);
        t2 = fmaf(sh_s[2][h2][c], w, t2);
        t3 = fmaf(sh_s[3][h2][c], w, t3);
    }
    float vb = valb[n];
    samp[(size_t)(bq0 + 0) * 256 + n] = t0 + sh_ws[0][h2] * vb;
    samp[(size_t)(bq0 + 1) * 256 + n] = t1 + sh_ws[1][h2] * vb;
    samp[(size_t)(bq0 + 2) * 256 + n] = t2 + sh_ws[2][h2] * vb;
    samp[(size_t)(bq0 + 3) * 256 + n] = t3 + sh_ws[3][h2] * vb;
}

// ---------------- host side ----------------
static void gemm2(GPtrs& g, int M, int K, int relu) {
    int Ntot = g.N1 + g.N2;
    dim3 grid(Ntot / BNt, (M + BMt - 1) / BMt, 2);
    tgemm_kernel<<<grid, 128>>>(g, M, K, relu);
}

extern "C" void kernel_launch(void* const* d_in, const int* in_sizes, int n_in,
                              void* d_out_v, int out_size) {
    const float* tgt[2] = {(const float*)d_in[0], (const float*)d_in[1]};
    const float* pos[2] = {(const float*)d_in[2], (const float*)d_in[3]};
    const float* refp[2] = {(const float*)d_in[4], (const float*)d_in[5]};
    const float* src[2] = {(const float*)d_in[6], (const float*)d_in[7]};
    const float* sa_in_w  = (const float*)d_in[8];
    const float* sa_in_b  = (const float*)d_in[9];
    const float* sa_out_w = (const float*)d_in[10];
    const float* sa_out_b = (const float*)d_in[11];
    const float* ln_w     = (const float*)d_in[12];
    const float* ln_b     = (const float*)d_in[13];
    const float* ffn_w1   = (const float*)d_in[14];
    const float* ffn_b1   = (const float*)d_in[15];
    const float* ffn_w2   = (const float*)d_in[16];
    const float* ffn_b2   = (const float*)d_in[17];
    const float* val_w    = (const float*)d_in[18];
    const float* val_b    = (const float*)d_in[19];
    const float* off_w    = (const float*)d_in[20];
    const float* off_b    = (const float*)d_in[21];
    const float* aw_w     = (const float*)d_in[22];
    const float* aw_b     = (const float*)d_in[23];
    const float* cout_w   = (const float*)d_in[24];
    const float* cout_b   = (const float*)d_in[25];
    float* out = (float*)d_out_v;

    float *p_qkv, *p_attn, *p_sa, *p_tgt2, *p_off, *p_aw,
          *p_samp, *p_ffn, *p_y, *p_x, *p_wT;
    cudaGetSymbolAddress((void**)&p_qkv,  g_qkv);
    cudaGetSymbolAddress((void**)&p_attn, g_attn);
    cudaGetSymbolAddress((void**)&p_sa,   g_sa);
    cudaGetSymbolAddress((void**)&p_tgt2, g_tgt2);
    cudaGetSymbolAddress((void**)&p_off,  g_off);
    cudaGetSymbolAddress((void**)&p_aw,   g_aw);
    cudaGetSymbolAddress((void**)&p_samp, g_samp);
    cudaGetSymbolAddress((void**)&p_ffn,  g_ffn);
    cudaGetSymbolAddress((void**)&p_y,    g_y);
    cudaGetSymbolAddress((void**)&p_x,    g_x);
    cudaGetSymbolAddress((void**)&p_wT,   g_wT);

    // ---- val_w transpose (independent; issue first)
    transpose256_kernel<<<dim3(8, 8, 2), dim3(32, 8)>>>(val_w, p_wT);

    // ---- fused qkv projection: q,k use tgt+pos (cols <512), v uses tgt
    {
        GPtrs g = {};
        g.A[0] = tgt[0]; g.A[1] = tgt[1];
        g.A2[0] = pos[0]; g.A2[1] = pos[1];
        g.W[0] = sa_in_w; g.W[1] = sa_in_w + (size_t)3 * D * D;
        g.Bi[0] = sa_in_b; g.Bi[1] = sa_in_b + 3 * D;
        g.C[0] = p_qkv; g.C[1] = p_qkv + (size_t)BNQ * 768;
        g.N1 = 768; g.N2 = 0; g.a2lim = 512;
        gemm2(g, BNQ, D, 0);
    }
    // ---- attention (5 q-chunks)
    {
        AttnArgs a = {{p_qkv, p_qkv + (size_t)BNQ * 768}, {p_attn, p_attn + NE}};
        attn_kernel<<<dim3(BS * NH, 2, 5), 192>>>(a);
    }
    // ---- out projection
    {
        GPtrs g = {};
        g.A[0] = p_attn; g.A[1] = p_attn + NE;
        g.W[0] = sa_out_w; g.W[1] = sa_out_w + (size_t)D * D;
        g.Bi[0] = sa_out_b; g.Bi[1] = sa_out_b + D;
        g.C[0] = p_sa; g.C[1] = p_sa + NE;
        g.N1 = 256; g.N2 = 0; g.a2lim = 0;
        gemm2(g, BNQ, D, 0);
    }
    // ---- tgt2 = LN(tgt + sa)  (norm2)
    {
        LnArgs a = {{tgt[0], tgt[1]}, {p_sa, p_sa + NE},
                    {ln_w + 1 * D, ln_w + 4 * D}, {ln_b + 1 * D, ln_b + 4 * D},
                    {p_tgt2, p_tgt2 + NE}};
        ln_kernel<<<dim3(BNQ / 8, 2), 256>>>(a);
    }
    // ---- fused offsets|aw projection from (tgt2 + pos)
    {
        GPtrs g = {};
        g.A[0] = p_tgt2; g.A[1] = p_tgt2 + NE;
        g.A2[0] = pos[0]; g.A2[1] = pos[1];
        g.W[0] = off_w; g.W[1] = off_w + (size_t)256 * D;
        g.W2[0] = aw_w; g.W2[1] = aw_w + (size_t)128 * D;
        g.Bi[0] = off_b; g.Bi[1] = off_b + 256;
        g.Bi2[0] = aw_b; g.Bi2[1] = aw_b + 128;
        g.C[0] = p_off; g.C[1] = p_off + NE;
        g.C2[0] = p_aw; g.C2[1] = p_aw + (size_t)BNQ * 128;
        g.N1 = 256; g.N2 = 128; g.a2lim = 384;
        gemm2(g, BNQ, D, 0);
    }

    // ---- sampling: z-batched, softmax fused in-kernel
    {
        MsdArgs a = {{src[1], src[0]},
                     {p_off, p_off + NE},
                     {p_aw, p_aw + (size_t)BNQ * 128},
                     {refp[0], refp[1]},
                     {p_wT, p_wT + (size_t)D * D},
                     {val_b, val_b + D},
                     {p_samp, p_samp + NE}};
        msdeform_kernel<<<dim3(BNQ / QB, 2), 256>>>(a);
    }
    // ---- cout projection -> output regions F_RGB / F_T
    {
        GPtrs g = {};
        g.A[0] = p_samp; g.A[1] = p_samp + NE;
        g.W[0] = cout_w; g.W[1] = cout_w + (size_t)D * D;
        g.Bi[0] = cout_b; g.Bi[1] = cout_b + D;
        g.C[0] = out + (size_t)2 * NE; g.C[1] = out + (size_t)3 * NE;
        g.N1 = 256; g.N2 = 0; g.a2lim = 0;
        gemm2(g, BNQ, D, 0);
    }

    // ---- fused cross residuals + norm1 LNs
    crossln_kernel<<<BNQ / 8, 256>>>(p_tgt2 + NE, out + (size_t)2 * NE, out + (size_t)3 * NE,
                                     ln_w + 0 * D, ln_b + 0 * D, ln_w + 3 * D, ln_b + 3 * D,
                                     p_x, p_x + NE);

    // ---- FFNs
    {
        GPtrs g = {};
        g.A[0] = p_x; g.A[1] = p_x + NE;
        g.W[0] = ffn_w1; g.W[1] = ffn_w1 + (size_t)DFF * D;
        g.Bi[0] = ffn_b1; g.Bi[1] = ffn_b1 + DFF;
        g.C[0] = p_ffn; g.C[1] = p_ffn + (size_t)BNQ * DFF;
        g.N1 = 1024; g.N2 = 0; g.a2lim = 0;
        gemm2(g, BNQ, D, 1);
    }
    {
        GPtrs g = {};
        g.A[0] = p_ffn; g.A[1] = p_ffn + (size_t)BNQ * DFF;
        g.W[0] = ffn_w2; g.W[1] = ffn_w2 + (size_t)D * DFF;
        g.Bi[0] = ffn_b2; g.Bi[1] = ffn_b2 + D;
        g.C[0] = p_y; g.C[1] = p_y + NE;
        g.N1 = 256; g.N2 = 0; g.a2lim = 0;
        gemm2(g, BNQ, DFF, 0);
    }
    {
        LnArgs a = {{p_x, p_x + NE}, {p_y, p_y + NE},
                    {ln_w + 2 * D, ln_w + 5 * D}, {ln_b + 2 * D, ln_b + 5 * D},
                    {out, out + NE}};
        ln_kernel<<<dim3(BNQ / 8, 2), 256>>>(a);
    }
}